// round 8
// baseline (speedup 1.0000x reference)
#include <cuda_runtime.h>
#include <cuda_bf16.h>
#include <cstdint>

#define NB 4
#define NS 1024
#define NH 16
#define NDH 64
#define C2A 0.18033688f   // ATT_SCALE * log2(e)
typedef __nv_bfloat16 bf16;

// ---------------- scratch ----------------
__device__ bf16 g_Qh[NB * NH * NS * NDH];
__device__ bf16 g_Ql[NB * NH * NS * NDH];
__device__ bf16 g_Kh[NB * NH * NS * NDH];
__device__ bf16 g_Kl[NB * NH * NS * NDH];
__device__ bf16 g_Vh[NB * NH * NS * NDH];
__device__ bf16 g_Vl[NB * NH * NS * NDH];
__device__ bf16 g_Oh[4096 * 1024];
__device__ bf16 g_Ol[4096 * 1024];
__device__ bf16 g_Wh[3 * 1024 * 1024];
__device__ bf16 g_Wl[3 * 1024 * 1024];
__device__ bf16 g_Bh[1024 * 1024];
__device__ bf16 g_Bl[1024 * 1024];

// ---------------- helpers ----------------
__device__ __forceinline__ uint32_t smem_u32(const void* p) {
    uint32_t a;
    asm("{ .reg .u64 t; cvta.to.shared.u64 t, %1; cvt.u32.u64 %0, t; }"
        : "=r"(a) : "l"(p));
    return a;
}
#define CP_ASYNC16(sp, gp) \
    asm volatile("cp.async.cg.shared.global [%0], [%1], 16;" :: "r"(sp), "l"(gp) : "memory")
#define CP_COMMIT() asm volatile("cp.async.commit_group;" ::: "memory")
#define CP_WAIT(n)  asm volatile("cp.async.wait_group %0;" :: "n"(n) : "memory")
#define LDSM4(r, a) \
    asm volatile("ldmatrix.sync.aligned.m8n8.x4.shared.b16 {%0,%1,%2,%3}, [%4];" \
                 : "=r"((r)[0]), "=r"((r)[1]), "=r"((r)[2]), "=r"((r)[3]) : "r"(a))
#define LDSM4T(r, a) \
    asm volatile("ldmatrix.sync.aligned.m8n8.x4.trans.shared.b16 {%0,%1,%2,%3}, [%4];" \
                 : "=r"((r)[0]), "=r"((r)[1]), "=r"((r)[2]), "=r"((r)[3]) : "r"(a))

__device__ __forceinline__ void mma_bf16(float* d, const uint32_t* a, const uint32_t* b) {
    asm volatile(
        "mma.sync.aligned.m16n8k16.row.col.f32.bf16.bf16.f32 "
        "{%0,%1,%2,%3},{%4,%5,%6,%7},{%8,%9},{%0,%1,%2,%3};"
        : "+f"(d[0]), "+f"(d[1]), "+f"(d[2]), "+f"(d[3])
        : "r"(a[0]), "r"(a[1]), "r"(a[2]), "r"(a[3]), "r"(b[0]), "r"(b[1]));
}
__device__ __forceinline__ void split2(float v, bf16& h, bf16& l) {
    h = __float2bfloat16_rn(v);
    l = __float2bfloat16_rn(v - __bfloat162float(h));
}
__device__ __forceinline__ uint32_t pack_hi(float a, float b) {
    __nv_bfloat162 t(__float2bfloat16_rn(a), __float2bfloat16_rn(b));
    return *(uint32_t*)&t;
}
__device__ __forceinline__ uint32_t pack_lo(float a, float b) {
    bf16 ha = __float2bfloat16_rn(a), hb = __float2bfloat16_rn(b);
    __nv_bfloat162 t(__float2bfloat16_rn(a - __bfloat162float(ha)),
                     __float2bfloat16_rn(b - __bfloat162float(hb)));
    return *(uint32_t*)&t;
}

// ---------------- prep kernels ----------------
__global__ __launch_bounds__(256) void split_f32(
    const float* __restrict__ A, bf16* __restrict__ H, bf16* __restrict__ L, int n)
{
    int i = (blockIdx.x * 256 + threadIdx.x) * 4;
    if (i >= n) return;
    float4 v = *(const float4*)&A[i];
    bf16 h[4], l[4];
    split2(v.x, h[0], l[0]); split2(v.y, h[1], l[1]);
    split2(v.z, h[2], l[2]); split2(v.w, h[3], l[3]);
    *(uint2*)&H[i] = *(uint2*)h;
    *(uint2*)&L[i] = *(uint2*)l;
}

__global__ __launch_bounds__(256) void splitW3(
    const float* __restrict__ Wq, const float* __restrict__ Wk,
    const float* __restrict__ Wv, bf16* __restrict__ Ht, bf16* __restrict__ Lt)
{
    const float* W = blockIdx.z == 0 ? Wq : (blockIdx.z == 1 ? Wk : Wv);
    bf16* H = Ht + (size_t)blockIdx.z * 1048576;
    bf16* L = Lt + (size_t)blockIdx.z * 1048576;
    __shared__ float t[32][33];
    const int k0 = blockIdx.x * 32, n0 = blockIdx.y * 32;
    const int h = n0 >> 6, e0 = n0 & 63;
    const int x = threadIdx.x & 31, y = threadIdx.x >> 5;
#pragma unroll
    for (int j = 0; j < 32; j += 8)
        t[y + j][x] = W[h * 65536 + (k0 + y + j) * 64 + e0 + x];
    __syncthreads();
#pragma unroll
    for (int j = 0; j < 32; j += 8) {
        bf16 hi, lo;
        split2(t[x][y + j], hi, lo);
        size_t o = (size_t)(n0 + y + j) * 1024 + k0 + x;
        H[o] = hi; L[o] = lo;
    }
}

// =================================================================
// HMMA GEMM body (unchanged)
// =================================================================
#define BK 32
#define TILE_B (128 * 80)
#define GH_SMEM (8 * TILE_B)

template <int ASPLIT, int MODE>
__device__ __forceinline__ void gemm_body(
    char* dynsm,
    const float* __restrict__ A32,
    const bf16* __restrict__ Abh, const bf16* __restrict__ Abl,
    const bf16* __restrict__ Bh, const bf16* __restrict__ Bl,
    const float* __restrict__ bias, float* __restrict__ C,
    bf16* __restrict__ Ch, bf16* __restrict__ Cl)
{
    const uint32_t sb = smem_u32(dynsm);
    const int tid = threadIdx.x;
    const int m0 = blockIdx.y * 128, n0 = blockIdx.x * 128;
    const int lane = tid & 31, w = tid >> 5;
    const int wm = w >> 2, wn = w & 3;
    const int lr = lane & 15, lcb = (lane >> 4) * 16;

    float acc[4][4][4];
#pragma unroll
    for (int i = 0; i < 4; i++)
#pragma unroll
        for (int j = 0; j < 4; j++)
#pragma unroll
            for (int r = 0; r < 4; r++) acc[i][j][r] = 0.f;

    uint32_t aoff[4], boff[2];
#pragma unroll
    for (int i = 0; i < 4; i++)
        aoff[i] = (uint32_t)((wm * 64 + i * 16 + lr) * 80) + lcb;
#pragma unroll
    for (int hlf = 0; hlf < 2; hlf++)
        boff[hlf] = (uint32_t)((wn * 32 + hlf * 16 + lr) * 80) + lcb;

    const int a_row = tid >> 1, a_chb = (tid & 1) * 4;
    float4 areg[4];
    auto ldgA = [&](int s) {
#pragma unroll
        for (int i = 0; i < 4; i++)
            areg[i] = *(const float4*)&A32[(size_t)(m0 + a_row) * 1024 + s * BK + (a_chb + i) * 4];
    };
    auto cvtA = [&](int buf) {
        char* ph = dynsm + (size_t)(buf * 4 + 0) * TILE_B;
        char* pl = dynsm + (size_t)(buf * 4 + 1) * TILE_B;
#pragma unroll
        for (int i = 0; i < 4; i++) {
            float4 v = areg[i];
            uint32_t off = (uint32_t)(a_row * 80 + (a_chb + i) * 8);
            *(uint2*)(ph + off) = make_uint2(pack_hi(v.x, v.y), pack_hi(v.z, v.w));
            *(uint2*)(pl + off) = make_uint2(pack_lo(v.x, v.y), pack_lo(v.z, v.w));
        }
    };
    auto cpStage = [&](int s) {
        const int buf = s & 1, k0 = s * BK;
        if (ASPLIT == 0) {
#pragma unroll
            for (int mat = 0; mat < 2; mat++) {
                const bf16* g = mat ? Abl : Abh;
                uint32_t sbase = sb + (uint32_t)(buf * 4 + mat) * TILE_B;
#pragma unroll
                for (int i = 0; i < 2; i++) {
                    int idx = tid + 256 * i, row = idx >> 2, ch = idx & 3;
                    CP_ASYNC16(sbase + (uint32_t)(row * 80 + ch * 16),
                               g + (size_t)(m0 + row) * 1024 + k0 + ch * 8);
                }
            }
        }
#pragma unroll
        for (int mat = 0; mat < 2; mat++) {
            const bf16* g = mat ? Bl : Bh;
            uint32_t sbase = sb + (uint32_t)(buf * 4 + 2 + mat) * TILE_B;
#pragma unroll
            for (int i = 0; i < 2; i++) {
                int idx = tid + 256 * i, row = idx >> 2, ch = idx & 3;
                CP_ASYNC16(sbase + (uint32_t)(row * 80 + ch * 16),
                           g + (size_t)(n0 + row) * 1024 + k0 + ch * 8);
            }
        }
        CP_COMMIT();
    };

    if (ASPLIT) ldgA(0);
    cpStage(0);
    if (ASPLIT) cvtA(0);

    for (int s = 0; s < 32; s++) {
        if (s < 31) {
            if (ASPLIT) ldgA(s + 1);
            cpStage(s + 1);
            CP_WAIT(1);
        } else CP_WAIT(0);
        __syncthreads();

        const uint32_t base = sb + (uint32_t)(s & 1) * 4 * TILE_B;
#pragma unroll
        for (int kk = 0; kk < 2; kk++) {
            const uint32_t kb = kk * 32;
            uint32_t ah[4][4], al[4][4];
#pragma unroll
            for (int i = 0; i < 4; i++) {
                LDSM4(ah[i], base + aoff[i] + kb);
                LDSM4(al[i], base + TILE_B + aoff[i] + kb);
            }
            uint32_t bh[4][2], bl[4][2];
#pragma unroll
            for (int hlf = 0; hlf < 2; hlf++) {
                uint32_t r[4];
                LDSM4(r, base + 2 * TILE_B + boff[hlf] + kb);
                bh[2*hlf][0] = r[0]; bh[2*hlf+1][0] = r[1];
                bh[2*hlf][1] = r[2]; bh[2*hlf+1][1] = r[3];
                LDSM4(r, base + 3 * TILE_B + boff[hlf] + kb);
                bl[2*hlf][0] = r[0]; bl[2*hlf+1][0] = r[1];
                bl[2*hlf][1] = r[2]; bl[2*hlf+1][1] = r[3];
            }
#pragma unroll
            for (int i = 0; i < 4; i++)
#pragma unroll
                for (int j = 0; j < 4; j++) {
                    mma_bf16(acc[i][j], ah[i], bh[j]);
                    mma_bf16(acc[i][j], ah[i], bl[j]);
                    mma_bf16(acc[i][j], al[i], bh[j]);
                }
        }
        __syncthreads();
        if (ASPLIT && s < 31) cvtA((s + 1) & 1);
    }

#pragma unroll
    for (int i = 0; i < 4; i++)
#pragma unroll
        for (int j = 0; j < 4; j++) {
            int row = m0 + wm * 64 + i * 16 + (lane >> 2);
            int col = n0 + wn * 32 + j * 8 + (lane & 3) * 2;
            float b0 = bias[col], b1 = bias[col + 1];
            float v00 = acc[i][j][0] + b0, v01 = acc[i][j][1] + b1;
            float v10 = acc[i][j][2] + b0, v11 = acc[i][j][3] + b1;
            if (MODE == 0) {
                *(float2*)&C[(size_t)row * 1024 + col] = make_float2(v00, v01);
                *(float2*)&C[(size_t)(row + 8) * 1024 + col] = make_float2(v10, v11);
            } else {
                int h = col >> 6, e = col & 63;
                int b = row >> 10, sI = row & 1023;
                size_t o0 = (((size_t)(b * 16 + h) * 1024 + sI) << 6) + e;
                size_t o1 = o0 + (8 << 6);
                *(uint32_t*)&Ch[o0] = pack_hi(v00, v01);
                *(uint32_t*)&Cl[o0] = pack_lo(v00, v01);
                *(uint32_t*)&Ch[o1] = pack_hi(v10, v11);
                *(uint32_t*)&Cl[o1] = pack_lo(v10, v11);
            }
        }
}

__global__ __launch_bounds__(256) void gemm_proj(
    const float* q, const float* k, const float* v,
    const bf16* Wh, const bf16* Wl,
    const float* bq, const float* bk, const float* bv,
    bf16* Qh, bf16* Ql, bf16* Kh, bf16* Kl, bf16* Vh, bf16* Vl)
{
    extern __shared__ __align__(128) char dynsm[];
    int z = blockIdx.z;
    const float* A = z == 0 ? q : (z == 1 ? k : v);
    const float* bias = z == 0 ? bq : (z == 1 ? bk : bv);
    bf16* Ch = z == 0 ? Qh : (z == 1 ? Kh : Vh);
    bf16* Cl = z == 0 ? Ql : (z == 1 ? Kl : Vl);
    gemm_body<1, 1>(dynsm, A, nullptr, nullptr,
                    Wh + (size_t)z * 1048576, Wl + (size_t)z * 1048576,
                    bias, nullptr, Ch, Cl);
}

__global__ __launch_bounds__(256) void gemm_fc(
    const bf16* Abh, const bf16* Abl, const bf16* Bh, const bf16* Bl,
    const float* bias, float* C)
{
    extern __shared__ __align__(128) char dynsm[];
    gemm_body<0, 0>(dynsm, nullptr, Abh, Abl, Bh, Bl, bias, C, nullptr, nullptr);
}

// =================================================================
// HMMA fused attention — 256 threads, register-resident P.
// =================================================================
#define AQH 0
#define AQL 18432
#define AKH 36864
#define AKL 55296
#define AVH 73728
#define AVL 92160
#define AOS 110592
#define ARB 143360
#define AW  151808
#define ARK 168704
#define ARV 177152
#define ALP 185600
#define AWP 186624
#define AL_ 187648
#define ATT_SMEM 188160

__global__ __launch_bounds__(256) void attn_hmma(
    const bf16* __restrict__ Qh, const bf16* __restrict__ Ql,
    const bf16* __restrict__ Kh, const bf16* __restrict__ Kl,
    const bf16* __restrict__ Vh, const bf16* __restrict__ Vl,
    const float* __restrict__ relk, const float* __restrict__ relv,
    bf16* __restrict__ Oh, bf16* __restrict__ Ol)
{
    extern __shared__ __align__(128) char sm[];
    const uint32_t sb = smem_u32(sm);
    const int tid = threadIdx.x;
    const int lane = tid & 31, w = tid >> 5;
    const int q0 = blockIdx.x * 128;
    const size_t base = (size_t)(blockIdx.z * NH + blockIdx.y) * (NS * NDH);
    const int lr = lane & 15, hc = (lane >> 4) * 16;
    float* sOst = (float*)(sm + AOS);
    float* sW = (float*)(sm + AW);
    float* sRK = (float*)(sm + ARK);
    float* sRV = (float*)(sm + ARV);
    float* sLp = (float*)(sm + ALP);
    float* sWp = (float*)(sm + AWP);
    float* sL = (float*)(sm + AL_);

    auto ldTile = [&](uint32_t dh, uint32_t dl, const bf16* gh, const bf16* gl, int t) {
#pragma unroll
        for (int i = 0; i < 4; i++) {
            int idx = tid + 256 * i, row = idx >> 3, ch = idx & 7;
            size_t go = base + (size_t)(t * 128 + row) * 64 + ch * 8;
            uint32_t so = (uint32_t)(row * 144 + ch * 16);
            CP_ASYNC16(sb + dh + so, gh + go);
            CP_ASYNC16(sb + dl + so, gl + go);
        }
        CP_COMMIT();
    };

    {
#pragma unroll
        for (int i = 0; i < 4; i++) {
            int idx = tid + 256 * i, row = idx >> 3, ch = idx & 7;
            size_t go = base + (size_t)(q0 + row) * 64 + ch * 8;
            uint32_t so = (uint32_t)(row * 144 + ch * 16);
            CP_ASYNC16(sb + AQH + so, Qh + go);
            CP_ASYNC16(sb + AQL + so, Ql + go);
        }
        CP_COMMIT();
    }
    ldTile(AKH, AKL, Kh, Kl, 0);
    ldTile(AVH, AVL, Vh, Vl, 0);

    for (int i = tid; i < 33 * 64; i += 256) { sRK[i] = relk[i]; sRV[i] = relv[i]; }
    for (int i = tid; i < 128 * 33; i += 256) sW[i] = 0.f;

    CP_WAIT(2);
    __syncthreads();

    // r[q][d] = (q . relk[d]) * C2A  (bf16, pre-scaled for exp2)
    {
        int q = tid >> 1;
        int d0 = (tid & 1) * 17, nd = (tid & 1) ? 16 : 17;
        float qv[64];
#pragma unroll
        for (int e2 = 0; e2 < 32; e2++) {
            uint32_t hv = *(uint32_t*)(sm + AQH + q * 144 + e2 * 4);
            uint32_t lv = *(uint32_t*)(sm + AQL + q * 144 + e2 * 4);
            float2 fh = __bfloat1622float2(*(__nv_bfloat162*)&hv);
            float2 fl = __bfloat1622float2(*(__nv_bfloat162*)&lv);
            qv[2 * e2] = fh.x + fl.x;
            qv[2 * e2 + 1] = fh.y + fl.y;
        }
        for (int d = d0; d < d0 + nd; d++) {
            float s = 0.f;
#pragma unroll
            for (int e = 0; e < 64; e++) s += qv[e] * sRK[d * 64 + e];
            *(bf16*)(sm + ARB + (q * 33 + d) * 2) = __float2bfloat16_rn(s * C2A);
        }
    }
    __syncthreads();

    const int wm = w >> 1, wn = w & 1;   // 32 q rows x 64 k cols per warp
    float acc2[2][8][4];                 // partial O: 32 rows x 64 e cols
#pragma unroll
    for (int i = 0; i < 2; i++)
#pragma unroll
        for (int j = 0; j < 8; j++)
#pragma unroll
            for (int r = 0; r < 4; r++) acc2[i][j][r] = 0.f;
    float lsum[4] = {0.f, 0.f, 0.f, 0.f};
    float wsuf[4] = {0.f, 0.f, 0.f, 0.f};

    for (int t = 0; t < 8; t++) {
        CP_WAIT(1);
        __syncthreads();

        // ---- QK phase: acc = scores for 32 rows x 64 cols ----
        float acc[2][8][4];
#pragma unroll
        for (int i = 0; i < 2; i++)
#pragma unroll
            for (int j = 0; j < 8; j++)
#pragma unroll
                for (int r = 0; r < 4; r++) acc[i][j][r] = 0.f;
#pragma unroll
        for (int es = 0; es < 4; es++) {
            uint32_t ah[2][4], al[2][4];
#pragma unroll
            for (int i = 0; i < 2; i++) {
                uint32_t ao = (uint32_t)((wm * 32 + i * 16 + lr) * 144) + hc + es * 32;
                LDSM4(ah[i], sb + AQH + ao);
                LDSM4(al[i], sb + AQL + ao);
            }
            uint32_t bh[8][2], bl[8][2];
#pragma unroll
            for (int c = 0; c < 4; c++) {
                uint32_t bo = (uint32_t)((wn * 64 + c * 16 + lr) * 144) + hc + es * 32;
                uint32_t r[4];
                LDSM4(r, sb + AKH + bo);
                bh[2*c][0] = r[0]; bh[2*c+1][0] = r[1];
                bh[2*c][1] = r[2]; bh[2*c+1][1] = r[3];
                LDSM4(r, sb + AKL + bo);
                bl[2*c][0] = r[0]; bl[2*c+1][0] = r[1];
                bl[2*c][1] = r[2]; bl[2*c+1][1] = r[3];
            }
#pragma unroll
            for (int i = 0; i < 2; i++)
#pragma unroll
                for (int j = 0; j < 8; j++) {
                    mma_bf16(acc[i][j], ah[i], bh[j]);
                    mma_bf16(acc[i][j], ah[i], bl[j]);
                    mma_bf16(acc[i][j], al[i], bh[j]);
                }
        }
        __syncthreads();
        if (t < 7) ldTile(AKH, AKL, Kh, Kl, t + 1);

        // ---- softmax in registers: acc <- p ----
        const int k0 = t * 128;
        const int X = blockIdx.x;
        const int cls = (t + 2 <= X) ? 0 : ((t >= X + 2) ? 2 : 1);
        if (cls != 1) {
            float rbv[2][2];
#pragma unroll
            for (int i = 0; i < 2; i++)
#pragma unroll
                for (int rh = 0; rh < 2; rh++) {
                    int rr = wm * 32 + i * 16 + (lane >> 2) + rh * 8;
                    rbv[i][rh] = __bfloat162float(
                        *(bf16*)(sm + ARB + (rr * 33 + (cls == 2 ? 32 : 0)) * 2));
                }
#pragma unroll
            for (int i = 0; i < 2; i++)
#pragma unroll
                for (int j = 0; j < 8; j++)
#pragma unroll
                    for (int rh = 0; rh < 2; rh++) {
                        float p0 = exp2f(fmaf(acc[i][j][rh * 2 + 0], C2A, rbv[i][rh]));
                        float p1 = exp2f(fmaf(acc[i][j][rh * 2 + 1], C2A, rbv[i][rh]));
                        acc[i][j][rh * 2 + 0] = p0;
                        acc[i][j][rh * 2 + 1] = p1;
                        lsum[i * 2 + rh] += p0 + p1;
                        if (cls == 2) wsuf[i * 2 + rh] += p0 + p1;
                    }
        } else {
#pragma unroll
            for (int i = 0; i < 2; i++)
#pragma unroll
                for (int j = 0; j < 8; j++) {
                    int col = wn * 64 + j * 8 + (lane & 3) * 2;
#pragma unroll
                    for (int rh = 0; rh < 2; rh++) {
                        int rr = wm * 32 + i * 16 + (lane >> 2) + rh * 8;
                        int qg = q0 + rr;
#pragma unroll
                        for (int v = 0; v < 2; v++) {
                            int kg = k0 + col + v;
                            int dd = kg - qg;
                            int dc = dd < -16 ? -16 : (dd > 16 ? 16 : dd);
                            float rb = __bfloat162float(
                                *(bf16*)(sm + ARB + (rr * 33 + dc + 16) * 2));
                            float p = exp2f(fmaf(acc[i][j][rh * 2 + v], C2A, rb));
                            acc[i][j][rh * 2 + v] = p;
                            lsum[i * 2 + rh] += p;
                            if (dd >= 16) wsuf[i * 2 + rh] += p;
                            else if (dd > -16) sW[rr * 33 + dd + 16] = p;
                        }
                    }
                }
        }
        if (t < 7) { CP_WAIT(1); } else { CP_WAIT(0); }
        __syncthreads();   // V[t] ready (also covers sW middle-tile stores)

        // ---- PV phase: P from registers, V rows = warp's own k half ----
#pragma unroll
        for (int kc = 0; kc < 4; kc++) {
            uint32_t ph[2][4], pl[2][4];
#pragma unroll
            for (int i = 0; i < 2; i++) {
                ph[i][0] = pack_hi(acc[i][2*kc][0],   acc[i][2*kc][1]);
                ph[i][1] = pack_hi(acc[i][2*kc][2],   acc[i][2*kc][3]);
                ph[i][2] = pack_hi(acc[i][2*kc+1][0], acc[i][2*kc+1][1]);
                ph[i][3] = pack_hi(acc[i][2*kc+1][2], acc[i][2*kc+1][3]);
                pl[i][0] = pack_lo(acc[i][2*kc][0],   acc[i][2*kc][1]);
                pl[i][1] = pack_lo(acc[i][2*kc][2],   acc[i][2*kc][3]);
                pl[i][2] = pack_lo(acc[i][2*kc+1][0], acc[i][2*kc+1][1]);
                pl[i][3] = pack_lo(acc[i][2*kc+1][2], acc[i][2*kc+1][3]);
            }
            uint32_t vh[8][2], vl[8][2];
            const int krow = wn * 64 + kc * 16;
#pragma unroll
            for (int c = 0; c < 4; c++) {
                uint32_t vo = (uint32_t)((krow + lr) * 144) + (c * 2 + (lane >> 4)) * 16;
                uint32_t r[4];
                LDSM4T(r, sb + AVH + vo);
                vh[2*c][0] = r[0]; vh[2*c][1] = r[1];
                vh[2*c+1][0] = r[2]; vh[2*c+1][1] = r[3];
                LDSM4T(r, sb + AVL + vo);
                vl[2*c][0] = r[0]; vl[2*c][1] = r[1];
                vl[2*c+1][0] = r[2]; vl[2*c+1][1] = r[3];
            }
#pragma unroll
            for (int i = 0; i < 2; i++)
#pragma unroll
                for (int nf = 0; nf < 8; nf++) {
                    mma_bf16(acc2[i][nf], ph[i], vh[nf]);
                    mma_bf16(acc2[i][nf], ph[i], vl[nf]);
                    mma_bf16(acc2[i][nf], pl[i], vh[nf]);
                }
        }
        __syncthreads();
        if (t < 7) ldTile(AVH, AVL, Vh, Vl, t + 1);
    }

    // ---- deterministic l / w32 reduction ----
#pragma unroll
    for (int i = 0; i < 4; i++) {
        lsum[i] += __shfl_xor_sync(0xffffffffu, lsum[i], 1);
        lsum[i] += __shfl_xor_sync(0xffffffffu, lsum[i], 2);
        wsuf[i] += __shfl_xor_sync(0xffffffffu, wsuf[i], 1);
        wsuf[i] += __shfl_xor_sync(0xffffffffu, wsuf[i], 2);
    }
    if ((lane & 3) == 0) {
#pragma unroll
        for (int i = 0; i < 4; i++) {
            int row = wm * 32 + (i >> 1) * 16 + (i & 1) * 8 + (lane >> 2);
            sLp[row * 2 + wn] = lsum[i];
            sWp[row * 2 + wn] = wsuf[i];
        }
    }
    // wn=1 warps stage their partial O
    if (wn == 1) {
#pragma unroll
        for (int i = 0; i < 2; i++)
#pragma unroll
            for (int nf = 0; nf < 8; nf++) {
                int row0 = wm * 32 + i * 16 + (lane >> 2);
                int col = nf * 8 + (lane & 3) * 2;
                *(float2*)&sOst[row0 * 64 + col] =
                    make_float2(acc2[i][nf][0], acc2[i][nf][1]);
                *(float2*)&sOst[(row0 + 8) * 64 + col] =
                    make_float2(acc2[i][nf][2], acc2[i][nf][3]);
            }
    }
    __syncthreads();
    if (tid < 128) {
        int r = tid;
        float l = sLp[r * 2] + sLp[r * 2 + 1];
        float ws = sWp[r * 2] + sWp[r * 2 + 1];
        float mid = 0.f;
#pragma unroll
        for (int d = 1; d < 32; d++) mid += sW[r * 33 + d];
        sW[r * 33 + 0] = l - ws - mid;
        sW[r * 33 + 32] = ws;
        sL[r] = 1.f / l;
    }
    __syncthreads();

    // ---- wn=0 warps: combine halves, rel_v bias, normalize, store ----
    if (wn == 0) {
#pragma unroll
        for (int i = 0; i < 2; i++) {
            int row0 = wm * 32 + i * 16 + (lane >> 2), row1 = row0 + 8;
            float il0 = sL[row0], il1 = sL[row1];
#pragma unroll
            for (int nf = 0; nf < 8; nf++) {
                int col = nf * 8 + (lane & 3) * 2;
                float2 s0 = *(float2*)&sOst[row0 * 64 + col];
                float2 s1 = *(float2*)&sOst[row1 * 64 + col];
                float o00 = acc2[i][nf][0] + s0.x, o01 = acc2[i][nf][1] + s0.y;
                float o10 = acc2[i][nf][2] + s1.x, o11 = acc2[i][nf][3] + s1.y;
                float b00 = 0.f, b01 = 0.f, b10 = 0.f, b11 = 0.f;
#pragma unroll
                for (int d = 0; d < 33; d++) {
                    float w0v = sW[row0 * 33 + d], w1v = sW[row1 * 33 + d];
                    float r0 = sRV[d * 64 + col], r1 = sRV[d * 64 + col + 1];
                    b00 += w0v * r0; b01 += w0v * r1;
                    b10 += w1v * r0; b11 += w1v * r1;
                }
                o00 = (o00 + b00) * il0; o01 = (o01 + b01) * il0;
                o10 = (o10 + b10) * il1; o11 = (o11 + b11) * il1;
                size_t g0 = ((size_t)(blockIdx.z * 1024 + q0 + row0)) * 1024
                            + blockIdx.y * 64 + col;
                size_t g1 = ((size_t)(blockIdx.z * 1024 + q0 + row1)) * 1024
                            + blockIdx.y * 64 + col;
                *(uint32_t*)&Oh[g0] = pack_hi(o00, o01);
                *(uint32_t*)&Ol[g0] = pack_lo(o00, o01);
                *(uint32_t*)&Oh[g1] = pack_hi(o10, o11);
                *(uint32_t*)&Ol[g1] = pack_lo(o10, o11);
            }
        }
    }
}

// =================================================================
extern "C" void kernel_launch(void* const* d_in, const int* in_sizes, int n_in,
                              void* d_out, int out_size)
{
    const float* query = (const float*)d_in[0];
    const float* key   = (const float*)d_in[1];
    const float* value = (const float*)d_in[2];
    const float* Wq    = (const float*)d_in[3];
    const float* bq    = (const float*)d_in[4];
    const float* Wk    = (const float*)d_in[5];
    const float* bk    = (const float*)d_in[6];
    const float* Wv    = (const float*)d_in[7];
    const float* bv    = (const float*)d_in[8];
    const float* relk  = (const float*)d_in[9];
    const float* relv  = (const float*)d_in[10];
    const float* fcW   = (const float*)d_in[11];
    const float* fcb   = (const float*)d_in[12];
    float* out = (float*)d_out;

    bf16 *Qh, *Ql, *Kh, *Kl, *Vh, *Vl, *Oh, *Ol, *Wh, *Wl, *Bh, *Bl;
    cudaGetSymbolAddress((void**)&Qh, g_Qh); cudaGetSymbolAddress((void**)&Ql, g_Ql);
    cudaGetSymbolAddress((void**)&Kh, g_Kh); cudaGetSymbolAddress((void**)&Kl, g_Kl);
    cudaGetSymbolAddress((void**)&Vh, g_Vh); cudaGetSymbolAddress((void**)&Vl, g_Vl);
    cudaGetSymbolAddress((void**)&Oh, g_Oh); cudaGetSymbolAddress((void**)&Ol, g_Ol);
    cudaGetSymbolAddress((void**)&Wh, g_Wh); cudaGetSymbolAddress((void**)&Wl, g_Wl);
    cudaGetSymbolAddress((void**)&Bh, g_Bh); cudaGetSymbolAddress((void**)&Bl, g_Bl);

    cudaFuncSetAttribute(gemm_proj, cudaFuncAttributeMaxDynamicSharedMemorySize, GH_SMEM);
    cudaFuncSetAttribute(gemm_fc, cudaFuncAttributeMaxDynamicSharedMemorySize, GH_SMEM);
    cudaFuncSetAttribute(attn_hmma, cudaFuncAttributeMaxDynamicSharedMemorySize, ATT_SMEM);

    splitW3<<<dim3(32, 32, 3), 256>>>(Wq, Wk, Wv, Wh, Wl);
    split_f32<<<1024, 256>>>(fcW, Bh, Bl, 1024 * 1024);

    gemm_proj<<<dim3(8, 32, 3), 256, GH_SMEM>>>(query, key, value, Wh, Wl,
                                                bq, bk, bv,
                                                Qh, Ql, Kh, Kl, Vh, Vl);

    attn_hmma<<<dim3(8, NH, NB), 256, ATT_SMEM>>>(Qh, Ql, Kh, Kl, Vh, Vl,
                                                  relk, relv, Oh, Ol);

    gemm_fc<<<dim3(8, 32), 256, GH_SMEM>>>(Oh, Ol, Bh, Bl, fcb, out);
}

// round 9
// speedup vs baseline: 1.0425x; 1.0425x over previous
#include <cuda_runtime.h>
#include <cuda_bf16.h>
#include <cstdint>

#define NB 4
#define NS 1024
#define NH 16
#define NDH 64
#define C2A 0.18033688f   // ATT_SCALE * log2(e)
typedef __nv_bfloat16 bf16;

// ---------------- scratch ----------------
__device__ bf16 g_Qh[NB * NH * NS * NDH];
__device__ bf16 g_Ql[NB * NH * NS * NDH];
__device__ bf16 g_Kh[NB * NH * NS * NDH];
__device__ bf16 g_Kl[NB * NH * NS * NDH];
__device__ bf16 g_Vh[NB * NH * NS * NDH];
__device__ bf16 g_Vl[NB * NH * NS * NDH];
__device__ bf16 g_Oh[4096 * 1024];
__device__ bf16 g_Ol[4096 * 1024];
__device__ bf16 g_Wh[3 * 1024 * 1024];
__device__ bf16 g_Wl[3 * 1024 * 1024];
__device__ bf16 g_Bh[1024 * 1024];
__device__ bf16 g_Bl[1024 * 1024];

// ---------------- helpers ----------------
__device__ __forceinline__ uint32_t smem_u32(const void* p) {
    uint32_t a;
    asm("{ .reg .u64 t; cvta.to.shared.u64 t, %1; cvt.u32.u64 %0, t; }"
        : "=r"(a) : "l"(p));
    return a;
}
#define CP_ASYNC16(sp, gp) \
    asm volatile("cp.async.cg.shared.global [%0], [%1], 16;" :: "r"(sp), "l"(gp) : "memory")
#define CP_COMMIT() asm volatile("cp.async.commit_group;" ::: "memory")
#define CP_WAIT(n)  asm volatile("cp.async.wait_group %0;" :: "n"(n) : "memory")
#define LDSM4(r, a) \
    asm volatile("ldmatrix.sync.aligned.m8n8.x4.shared.b16 {%0,%1,%2,%3}, [%4];" \
                 : "=r"((r)[0]), "=r"((r)[1]), "=r"((r)[2]), "=r"((r)[3]) : "r"(a))
#define LDSM4T(r, a) \
    asm volatile("ldmatrix.sync.aligned.m8n8.x4.trans.shared.b16 {%0,%1,%2,%3}, [%4];" \
                 : "=r"((r)[0]), "=r"((r)[1]), "=r"((r)[2]), "=r"((r)[3]) : "r"(a))

__device__ __forceinline__ void mma_bf16(float* d, const uint32_t* a, const uint32_t* b) {
    asm volatile(
        "mma.sync.aligned.m16n8k16.row.col.f32.bf16.bf16.f32 "
        "{%0,%1,%2,%3},{%4,%5,%6,%7},{%8,%9},{%0,%1,%2,%3};"
        : "+f"(d[0]), "+f"(d[1]), "+f"(d[2]), "+f"(d[3])
        : "r"(a[0]), "r"(a[1]), "r"(a[2]), "r"(a[3]), "r"(b[0]), "r"(b[1]));
}
__device__ __forceinline__ void split2(float v, bf16& h, bf16& l) {
    h = __float2bfloat16_rn(v);
    l = __float2bfloat16_rn(v - __bfloat162float(h));
}
__device__ __forceinline__ uint32_t pack_hi(float a, float b) {
    __nv_bfloat162 t(__float2bfloat16_rn(a), __float2bfloat16_rn(b));
    return *(uint32_t*)&t;
}
__device__ __forceinline__ uint32_t pack_lo(float a, float b) {
    bf16 ha = __float2bfloat16_rn(a), hb = __float2bfloat16_rn(b);
    __nv_bfloat162 t(__float2bfloat16_rn(a - __bfloat162float(ha)),
                     __float2bfloat16_rn(b - __bfloat162float(hb)));
    return *(uint32_t*)&t;
}

// ---------------- prep kernels ----------------
__global__ __launch_bounds__(256) void split_f32(
    const float* __restrict__ A, bf16* __restrict__ H, bf16* __restrict__ L, int n)
{
    int i = (blockIdx.x * 256 + threadIdx.x) * 4;
    if (i >= n) return;
    float4 v = *(const float4*)&A[i];
    bf16 h[4], l[4];
    split2(v.x, h[0], l[0]); split2(v.y, h[1], l[1]);
    split2(v.z, h[2], l[2]); split2(v.w, h[3], l[3]);
    *(uint2*)&H[i] = *(uint2*)h;
    *(uint2*)&L[i] = *(uint2*)l;
}

__global__ __launch_bounds__(256) void splitW3(
    const float* __restrict__ Wq, const float* __restrict__ Wk,
    const float* __restrict__ Wv, bf16* __restrict__ Ht, bf16* __restrict__ Lt)
{
    const float* W = blockIdx.z == 0 ? Wq : (blockIdx.z == 1 ? Wk : Wv);
    bf16* H = Ht + (size_t)blockIdx.z * 1048576;
    bf16* L = Lt + (size_t)blockIdx.z * 1048576;
    __shared__ float t[32][33];
    const int k0 = blockIdx.x * 32, n0 = blockIdx.y * 32;
    const int h = n0 >> 6, e0 = n0 & 63;
    const int x = threadIdx.x & 31, y = threadIdx.x >> 5;
#pragma unroll
    for (int j = 0; j < 32; j += 8)
        t[y + j][x] = W[h * 65536 + (k0 + y + j) * 64 + e0 + x];
    __syncthreads();
#pragma unroll
    for (int j = 0; j < 32; j += 8) {
        bf16 hi, lo;
        split2(t[x][y + j], hi, lo);
        size_t o = (size_t)(n0 + y + j) * 1024 + k0 + x;
        H[o] = hi; L[o] = lo;
    }
}

// =================================================================
// HMMA GEMM body — split-MMA issued in 3 passes (RAW-chain break)
// =================================================================
#define BK 32
#define TILE_B (128 * 80)
#define GH_SMEM (8 * TILE_B)

template <int ASPLIT, int MODE>
__device__ __forceinline__ void gemm_body(
    char* dynsm,
    const float* __restrict__ A32,
    const bf16* __restrict__ Abh, const bf16* __restrict__ Abl,
    const bf16* __restrict__ Bh, const bf16* __restrict__ Bl,
    const float* __restrict__ bias, float* __restrict__ C,
    bf16* __restrict__ Ch, bf16* __restrict__ Cl)
{
    const uint32_t sb = smem_u32(dynsm);
    const int tid = threadIdx.x;
    const int m0 = blockIdx.y * 128, n0 = blockIdx.x * 128;
    const int lane = tid & 31, w = tid >> 5;
    const int wm = w >> 2, wn = w & 3;
    const int lr = lane & 15, lcb = (lane >> 4) * 16;

    float acc[4][4][4];
#pragma unroll
    for (int i = 0; i < 4; i++)
#pragma unroll
        for (int j = 0; j < 4; j++)
#pragma unroll
            for (int r = 0; r < 4; r++) acc[i][j][r] = 0.f;

    uint32_t aoff[4], boff[2];
#pragma unroll
    for (int i = 0; i < 4; i++)
        aoff[i] = (uint32_t)((wm * 64 + i * 16 + lr) * 80) + lcb;
#pragma unroll
    for (int hlf = 0; hlf < 2; hlf++)
        boff[hlf] = (uint32_t)((wn * 32 + hlf * 16 + lr) * 80) + lcb;

    const int a_row = tid >> 1, a_chb = (tid & 1) * 4;
    float4 areg[4];
    auto ldgA = [&](int s) {
#pragma unroll
        for (int i = 0; i < 4; i++)
            areg[i] = *(const float4*)&A32[(size_t)(m0 + a_row) * 1024 + s * BK + (a_chb + i) * 4];
    };
    auto cvtA = [&](int buf) {
        char* ph = dynsm + (size_t)(buf * 4 + 0) * TILE_B;
        char* pl = dynsm + (size_t)(buf * 4 + 1) * TILE_B;
#pragma unroll
        for (int i = 0; i < 4; i++) {
            float4 v = areg[i];
            uint32_t off = (uint32_t)(a_row * 80 + (a_chb + i) * 8);
            *(uint2*)(ph + off) = make_uint2(pack_hi(v.x, v.y), pack_hi(v.z, v.w));
            *(uint2*)(pl + off) = make_uint2(pack_lo(v.x, v.y), pack_lo(v.z, v.w));
        }
    };
    auto cpStage = [&](int s) {
        const int buf = s & 1, k0 = s * BK;
        if (ASPLIT == 0) {
#pragma unroll
            for (int mat = 0; mat < 2; mat++) {
                const bf16* g = mat ? Abl : Abh;
                uint32_t sbase = sb + (uint32_t)(buf * 4 + mat) * TILE_B;
#pragma unroll
                for (int i = 0; i < 2; i++) {
                    int idx = tid + 256 * i, row = idx >> 2, ch = idx & 3;
                    CP_ASYNC16(sbase + (uint32_t)(row * 80 + ch * 16),
                               g + (size_t)(m0 + row) * 1024 + k0 + ch * 8);
                }
            }
        }
#pragma unroll
        for (int mat = 0; mat < 2; mat++) {
            const bf16* g = mat ? Bl : Bh;
            uint32_t sbase = sb + (uint32_t)(buf * 4 + 2 + mat) * TILE_B;
#pragma unroll
            for (int i = 0; i < 2; i++) {
                int idx = tid + 256 * i, row = idx >> 2, ch = idx & 3;
                CP_ASYNC16(sbase + (uint32_t)(row * 80 + ch * 16),
                           g + (size_t)(n0 + row) * 1024 + k0 + ch * 8);
            }
        }
        CP_COMMIT();
    };

    if (ASPLIT) ldgA(0);
    cpStage(0);
    if (ASPLIT) cvtA(0);

    for (int s = 0; s < 32; s++) {
        if (s < 31) {
            if (ASPLIT) ldgA(s + 1);
            cpStage(s + 1);
            CP_WAIT(1);
        } else CP_WAIT(0);
        __syncthreads();

        const uint32_t base = sb + (uint32_t)(s & 1) * 4 * TILE_B;
#pragma unroll
        for (int kk = 0; kk < 2; kk++) {
            const uint32_t kb = kk * 32;
            uint32_t ah[4][4], al[4][4];
#pragma unroll
            for (int i = 0; i < 4; i++) {
                LDSM4(ah[i], base + aoff[i] + kb);
                LDSM4(al[i], base + TILE_B + aoff[i] + kb);
            }
            uint32_t bh[4][2], bl[4][2];
#pragma unroll
            for (int hlf = 0; hlf < 2; hlf++) {
                uint32_t r[4];
                LDSM4(r, base + 2 * TILE_B + boff[hlf] + kb);
                bh[2*hlf][0] = r[0]; bh[2*hlf+1][0] = r[1];
                bh[2*hlf][1] = r[2]; bh[2*hlf+1][1] = r[3];
                LDSM4(r, base + 3 * TILE_B + boff[hlf] + kb);
                bl[2*hlf][0] = r[0]; bl[2*hlf+1][0] = r[1];
                bl[2*hlf][1] = r[2]; bl[2*hlf+1][1] = r[3];
            }
            // 3 passes: same-acc MMAs now 16 instructions apart
#pragma unroll
            for (int i = 0; i < 4; i++)
#pragma unroll
                for (int j = 0; j < 4; j++) mma_bf16(acc[i][j], ah[i], bh[j]);
#pragma unroll
            for (int i = 0; i < 4; i++)
#pragma unroll
                for (int j = 0; j < 4; j++) mma_bf16(acc[i][j], ah[i], bl[j]);
#pragma unroll
            for (int i = 0; i < 4; i++)
#pragma unroll
                for (int j = 0; j < 4; j++) mma_bf16(acc[i][j], al[i], bh[j]);
        }
        __syncthreads();
        if (ASPLIT && s < 31) cvtA((s + 1) & 1);
    }

#pragma unroll
    for (int i = 0; i < 4; i++)
#pragma unroll
        for (int j = 0; j < 4; j++) {
            int row = m0 + wm * 64 + i * 16 + (lane >> 2);
            int col = n0 + wn * 32 + j * 8 + (lane & 3) * 2;
            float b0 = bias[col], b1 = bias[col + 1];
            float v00 = acc[i][j][0] + b0, v01 = acc[i][j][1] + b1;
            float v10 = acc[i][j][2] + b0, v11 = acc[i][j][3] + b1;
            if (MODE == 0) {
                *(float2*)&C[(size_t)row * 1024 + col] = make_float2(v00, v01);
                *(float2*)&C[(size_t)(row + 8) * 1024 + col] = make_float2(v10, v11);
            } else {
                int h = col >> 6, e = col & 63;
                int b = row >> 10, sI = row & 1023;
                size_t o0 = (((size_t)(b * 16 + h) * 1024 + sI) << 6) + e;
                size_t o1 = o0 + (8 << 6);
                *(uint32_t*)&Ch[o0] = pack_hi(v00, v01);
                *(uint32_t*)&Cl[o0] = pack_lo(v00, v01);
                *(uint32_t*)&Ch[o1] = pack_hi(v10, v11);
                *(uint32_t*)&Cl[o1] = pack_lo(v10, v11);
            }
        }
}

__global__ __launch_bounds__(256) void gemm_proj(
    const float* q, const float* k, const float* v,
    const bf16* Wh, const bf16* Wl,
    const float* bq, const float* bk, const float* bv,
    bf16* Qh, bf16* Ql, bf16* Kh, bf16* Kl, bf16* Vh, bf16* Vl)
{
    extern __shared__ __align__(128) char dynsm[];
    int z = blockIdx.z;
    const float* A = z == 0 ? q : (z == 1 ? k : v);
    const float* bias = z == 0 ? bq : (z == 1 ? bk : bv);
    bf16* Ch = z == 0 ? Qh : (z == 1 ? Kh : Vh);
    bf16* Cl = z == 0 ? Ql : (z == 1 ? Kl : Vl);
    gemm_body<1, 1>(dynsm, A, nullptr, nullptr,
                    Wh + (size_t)z * 1048576, Wl + (size_t)z * 1048576,
                    bias, nullptr, Ch, Cl);
}

__global__ __launch_bounds__(256) void gemm_fc(
    const bf16* Abh, const bf16* Abl, const bf16* Bh, const bf16* Bl,
    const float* bias, float* C)
{
    extern __shared__ __align__(128) char dynsm[];
    gemm_body<0, 0>(dynsm, nullptr, Abh, Abl, Bh, Bl, bias, C, nullptr, nullptr);
}

// =================================================================
// HMMA fused attention — 256 threads (R6 structure), 3-pass MMAs.
// =================================================================
#define AQH 0
#define AQL 18432
#define AKH 36864
#define AKL 55296
#define AVH 73728
#define AVL 92160
#define APH 110592
#define APL 145408
#define ARB 180224
#define AW  188672
#define ARK 205568
#define ARV 214016
#define ALP 222464
#define AWP 223488
#define AL_ 224512
#define ATT_SMEM 225024

__global__ __launch_bounds__(256) void attn_hmma(
    const bf16* __restrict__ Qh, const bf16* __restrict__ Ql,
    const bf16* __restrict__ Kh, const bf16* __restrict__ Kl,
    const bf16* __restrict__ Vh, const bf16* __restrict__ Vl,
    const float* __restrict__ relk, const float* __restrict__ relv,
    bf16* __restrict__ Oh, bf16* __restrict__ Ol)
{
    extern __shared__ __align__(128) char sm[];
    const uint32_t sb = smem_u32(sm);
    const int tid = threadIdx.x;
    const int lane = tid & 31, w = tid >> 5;
    const int q0 = blockIdx.x * 128;
    const size_t base = (size_t)(blockIdx.z * NH + blockIdx.y) * (NS * NDH);
    const int lr = lane & 15, hc = (lane >> 4) * 16;
    float* sW = (float*)(sm + AW);
    float* sRK = (float*)(sm + ARK);
    float* sRV = (float*)(sm + ARV);
    float* sLp = (float*)(sm + ALP);
    float* sWp = (float*)(sm + AWP);
    float* sL = (float*)(sm + AL_);

    auto ldTile = [&](uint32_t dh, uint32_t dl, const bf16* gh, const bf16* gl, int t) {
#pragma unroll
        for (int i = 0; i < 4; i++) {
            int idx = tid + 256 * i, row = idx >> 3, ch = idx & 7;
            size_t go = base + (size_t)(t * 128 + row) * 64 + ch * 8;
            uint32_t so = (uint32_t)(row * 144 + ch * 16);
            CP_ASYNC16(sb + dh + so, gh + go);
            CP_ASYNC16(sb + dl + so, gl + go);
        }
        CP_COMMIT();
    };

    {
#pragma unroll
        for (int i = 0; i < 4; i++) {
            int idx = tid + 256 * i, row = idx >> 3, ch = idx & 7;
            size_t go = base + (size_t)(q0 + row) * 64 + ch * 8;
            uint32_t so = (uint32_t)(row * 144 + ch * 16);
            CP_ASYNC16(sb + AQH + so, Qh + go);
            CP_ASYNC16(sb + AQL + so, Ql + go);
        }
        CP_COMMIT();
    }
    ldTile(AKH, AKL, Kh, Kl, 0);
    ldTile(AVH, AVL, Vh, Vl, 0);

    for (int i = tid; i < 33 * 64; i += 256) { sRK[i] = relk[i]; sRV[i] = relv[i]; }
    for (int i = tid; i < 128 * 33; i += 256) sW[i] = 0.f;

    CP_WAIT(2);
    __syncthreads();

    // r[q][d] = (q . relk[d]) * C2A  (bf16, pre-scaled for exp2)
    {
        int q = tid >> 1;
        int d0 = (tid & 1) * 17, nd = (tid & 1) ? 16 : 17;
        float qv[64];
#pragma unroll
        for (int e2 = 0; e2 < 32; e2++) {
            uint32_t hv = *(uint32_t*)(sm + AQH + q * 144 + e2 * 4);
            uint32_t lv = *(uint32_t*)(sm + AQL + q * 144 + e2 * 4);
            float2 fh = __bfloat1622float2(*(__nv_bfloat162*)&hv);
            float2 fl = __bfloat1622float2(*(__nv_bfloat162*)&lv);
            qv[2 * e2] = fh.x + fl.x;
            qv[2 * e2 + 1] = fh.y + fl.y;
        }
        for (int d = d0; d < d0 + nd; d++) {
            float s = 0.f;
#pragma unroll
            for (int e = 0; e < 64; e++) s += qv[e] * sRK[d * 64 + e];
            *(bf16*)(sm + ARB + (q * 33 + d) * 2) = __float2bfloat16_rn(s * C2A);
        }
    }
    __syncthreads();

    const int wm = w >> 1, wn = w & 1;
    float acc2[8][4];
#pragma unroll
    for (int j = 0; j < 8; j++)
#pragma unroll
        for (int r = 0; r < 4; r++) acc2[j][r] = 0.f;
    float lsum[4] = {0.f, 0.f, 0.f, 0.f};
    float wsuf[4] = {0.f, 0.f, 0.f, 0.f};

    for (int t = 0; t < 8; t++) {
        CP_WAIT(1);
        __syncthreads();

        // ---- QK phase (3-pass MMA issue) ----
        float acc[2][8][4];
#pragma unroll
        for (int i = 0; i < 2; i++)
#pragma unroll
            for (int j = 0; j < 8; j++)
#pragma unroll
                for (int r = 0; r < 4; r++) acc[i][j][r] = 0.f;
#pragma unroll
        for (int es = 0; es < 4; es++) {
            uint32_t ah[2][4], al[2][4];
#pragma unroll
            for (int i = 0; i < 2; i++) {
                uint32_t ao = (uint32_t)((wm * 32 + i * 16 + lr) * 144) + hc + es * 32;
                LDSM4(ah[i], sb + AQH + ao);
                LDSM4(al[i], sb + AQL + ao);
            }
            uint32_t bh[8][2], bl[8][2];
#pragma unroll
            for (int c = 0; c < 4; c++) {
                uint32_t bo = (uint32_t)((wn * 64 + c * 16 + lr) * 144) + hc + es * 32;
                uint32_t r[4];
                LDSM4(r, sb + AKH + bo);
                bh[2*c][0] = r[0]; bh[2*c+1][0] = r[1];
                bh[2*c][1] = r[2]; bh[2*c+1][1] = r[3];
                LDSM4(r, sb + AKL + bo);
                bl[2*c][0] = r[0]; bl[2*c+1][0] = r[1];
                bl[2*c][1] = r[2]; bl[2*c+1][1] = r[3];
            }
#pragma unroll
            for (int i = 0; i < 2; i++)
#pragma unroll
                for (int j = 0; j < 8; j++) mma_bf16(acc[i][j], ah[i], bh[j]);
#pragma unroll
            for (int i = 0; i < 2; i++)
#pragma unroll
                for (int j = 0; j < 8; j++) mma_bf16(acc[i][j], ah[i], bl[j]);
#pragma unroll
            for (int i = 0; i < 2; i++)
#pragma unroll
                for (int j = 0; j < 8; j++) mma_bf16(acc[i][j], al[i], bh[j]);
        }
        __syncthreads();
        if (t < 7) ldTile(AKH, AKL, Kh, Kl, t + 1);

        // ---- softmax epilogue -> P (bf16 hi/lo) ----
        const int k0 = t * 128;
        const int X = blockIdx.x;
        const int cls = (t + 2 <= X) ? 0 : ((t >= X + 2) ? 2 : 1);
        if (cls != 1) {
            float rbv[2][2];
#pragma unroll
            for (int i = 0; i < 2; i++)
#pragma unroll
                for (int rh = 0; rh < 2; rh++) {
                    int rr = wm * 32 + i * 16 + (lane >> 2) + rh * 8;
                    rbv[i][rh] = __bfloat162float(
                        *(bf16*)(sm + ARB + (rr * 33 + (cls == 2 ? 32 : 0)) * 2));
                }
#pragma unroll
            for (int i = 0; i < 2; i++)
#pragma unroll
                for (int j = 0; j < 8; j++) {
                    int col = wn * 64 + j * 8 + (lane & 3) * 2;
#pragma unroll
                    for (int rh = 0; rh < 2; rh++) {
                        int rr = wm * 32 + i * 16 + (lane >> 2) + rh * 8;
                        float p0 = exp2f(fmaf(acc[i][j][rh * 2 + 0], C2A, rbv[i][rh]));
                        float p1 = exp2f(fmaf(acc[i][j][rh * 2 + 1], C2A, rbv[i][rh]));
                        lsum[i * 2 + rh] += p0 + p1;
                        if (cls == 2) wsuf[i * 2 + rh] += p0 + p1;
                        uint32_t po = (uint32_t)(rr * 272 + col * 2);
                        *(uint32_t*)(sm + APH + po) = pack_hi(p0, p1);
                        *(uint32_t*)(sm + APL + po) = pack_lo(p0, p1);
                    }
                }
        } else {
#pragma unroll
            for (int i = 0; i < 2; i++)
#pragma unroll
                for (int j = 0; j < 8; j++) {
                    int col = wn * 64 + j * 8 + (lane & 3) * 2;
#pragma unroll
                    for (int rh = 0; rh < 2; rh++) {
                        int rr = wm * 32 + i * 16 + (lane >> 2) + rh * 8;
                        int qg = q0 + rr;
                        float p01[2];
#pragma unroll
                        for (int v = 0; v < 2; v++) {
                            int kg = k0 + col + v;
                            int dd = kg - qg;
                            int dc = dd < -16 ? -16 : (dd > 16 ? 16 : dd);
                            float rb = __bfloat162float(
                                *(bf16*)(sm + ARB + (rr * 33 + dc + 16) * 2));
                            float p = exp2f(fmaf(acc[i][j][rh * 2 + v], C2A, rb));
                            p01[v] = p;
                            lsum[i * 2 + rh] += p;
                            if (dd >= 16) wsuf[i * 2 + rh] += p;
                            else if (dd > -16) sW[rr * 33 + dd + 16] = p;
                        }
                        uint32_t po = (uint32_t)(rr * 272 + col * 2);
                        *(uint32_t*)(sm + APH + po) = pack_hi(p01[0], p01[1]);
                        *(uint32_t*)(sm + APL + po) = pack_lo(p01[0], p01[1]);
                    }
                }
        }
        if (t < 7) { CP_WAIT(1); } else { CP_WAIT(0); }
        __syncthreads();   // P visible + V[t] ready

        // ---- PV phase (3-pass MMA issue) ----
#pragma unroll
        for (int ks = 0; ks < 8; ks++) {
            uint32_t ph[4], pl[4];
            uint32_t po = (uint32_t)((w * 16 + lr) * 272) + ks * 32 + hc;
            LDSM4(ph, sb + APH + po);
            LDSM4(pl, sb + APL + po);
            uint32_t vh[8][2], vl[8][2];
#pragma unroll
            for (int c = 0; c < 4; c++) {
                uint32_t vo = (uint32_t)((ks * 16 + lr) * 144) + (c * 2 + (lane >> 4)) * 16;
                uint32_t r[4];
                LDSM4T(r, sb + AVH + vo);
                vh[2*c][0] = r[0]; vh[2*c][1] = r[1];
                vh[2*c+1][0] = r[2]; vh[2*c+1][1] = r[3];
                LDSM4T(r, sb + AVL + vo);
                vl[2*c][0] = r[0]; vl[2*c][1] = r[1];
                vl[2*c+1][0] = r[2]; vl[2*c+1][1] = r[3];
            }
#pragma unroll
            for (int j = 0; j < 8; j++) mma_bf16(acc2[j], ph, vh[j]);
#pragma unroll
            for (int j = 0; j < 8; j++) mma_bf16(acc2[j], ph, vl[j]);
#pragma unroll
            for (int j = 0; j < 8; j++) mma_bf16(acc2[j], pl, vh[j]);
        }
        __syncthreads();
        if (t < 7) ldTile(AVH, AVL, Vh, Vl, t + 1);
    }

    // ---- deterministic l / w32 reduction ----
#pragma unroll
    for (int i = 0; i < 4; i++) {
        lsum[i] += __shfl_xor_sync(0xffffffffu, lsum[i], 1);
        lsum[i] += __shfl_xor_sync(0xffffffffu, lsum[i], 2);
        wsuf[i] += __shfl_xor_sync(0xffffffffu, wsuf[i], 1);
        wsuf[i] += __shfl_xor_sync(0xffffffffu, wsuf[i], 2);
    }
    if ((lane & 3) == 0) {
#pragma unroll
        for (int i = 0; i < 4; i++) {
            int row = wm * 32 + (i >> 1) * 16 + (i & 1) * 8 + (lane >> 2);
            sLp[row * 2 + wn] = lsum[i];
            sWp[row * 2 + wn] = wsuf[i];
        }
    }
    __syncthreads();
    if (tid < 128) {
        int r = tid;
        float l = sLp[r * 2] + sLp[r * 2 + 1];
        float ws = sWp[r * 2] + sWp[r * 2 + 1];
        float mid = 0.f;
#pragma unroll
        for (int d = 1; d < 32; d++) mid += sW[r * 33 + d];
        sW[r * 33 + 0] = l - ws - mid;
        sW[r * 33 + 32] = ws;
        sL[r] = 1.f / l;
    }
    __syncthreads();

    // ---- rel_v bias + normalize + store O (bf16 hi/lo, [B,S,HID]) ----
#pragma unroll
    for (int j = 0; j < 8; j++) {
        int row0 = w * 16 + (lane >> 2), row1 = row0 + 8;
        int col = j * 8 + (lane & 3) * 2;
        float b00 = 0.f, b01 = 0.f, b10 = 0.f, b11 = 0.f;
#pragma unroll
        for (int d = 0; d < 33; d++) {
            float w0v = sW[row0 * 33 + d], w1v = sW[row1 * 33 + d];
            float r0 = sRV[d * 64 + col], r1 = sRV[d * 64 + col + 1];
            b00 += w0v * r0; b01 += w0v * r1;
            b10 += w1v * r0; b11 += w1v * r1;
        }
        float il0 = sL[row0], il1 = sL[row1];
        float o00 = (acc2[j][0] + b00) * il0, o01 = (acc2[j][1] + b01) * il0;
        float o10 = (acc2[j][2] + b10) * il1, o11 = (acc2[j][3] + b11) * il1;
        size_t g0 = ((size_t)(blockIdx.z * 1024 + q0 + row0)) * 1024 + blockIdx.y * 64 + col;
        size_t g1 = ((size_t)(blockIdx.z * 1024 + q0 + row1)) * 1024 + blockIdx.y * 64 + col;
        *(uint32_t*)&Oh[g0] = pack_hi(o00, o01);
        *(uint32_t*)&Ol[g0] = pack_lo(o00, o01);
        *(uint32_t*)&Oh[g1] = pack_hi(o10, o11);
        *(uint32_t*)&Ol[g1] = pack_lo(o10, o11);
    }
}

// =================================================================
extern "C" void kernel_launch(void* const* d_in, const int* in_sizes, int n_in,
                              void* d_out, int out_size)
{
    const float* query = (const float*)d_in[0];
    const float* key   = (const float*)d_in[1];
    const float* value = (const float*)d_in[2];
    const float* Wq    = (const float*)d_in[3];
    const float* bq    = (const float*)d_in[4];
    const float* Wk    = (const float*)d_in[5];
    const float* bk    = (const float*)d_in[6];
    const float* Wv    = (const float*)d_in[7];
    const float* bv    = (const float*)d_in[8];
    const float* relk  = (const float*)d_in[9];
    const float* relv  = (const float*)d_in[10];
    const float* fcW   = (const float*)d_in[11];
    const float* fcb   = (const float*)d_in[12];
    float* out = (float*)d_out;

    bf16 *Qh, *Ql, *Kh, *Kl, *Vh, *Vl, *Oh, *Ol, *Wh, *Wl, *Bh, *Bl;
    cudaGetSymbolAddress((void**)&Qh, g_Qh); cudaGetSymbolAddress((void**)&Ql, g_Ql);
    cudaGetSymbolAddress((void**)&Kh, g_Kh); cudaGetSymbolAddress((void**)&Kl, g_Kl);
    cudaGetSymbolAddress((void**)&Vh, g_Vh); cudaGetSymbolAddress((void**)&Vl, g_Vl);
    cudaGetSymbolAddress((void**)&Oh, g_Oh); cudaGetSymbolAddress((void**)&Ol, g_Ol);
    cudaGetSymbolAddress((void**)&Wh, g_Wh); cudaGetSymbolAddress((void**)&Wl, g_Wl);
    cudaGetSymbolAddress((void**)&Bh, g_Bh); cudaGetSymbolAddress((void**)&Bl, g_Bl);

    cudaFuncSetAttribute(gemm_proj, cudaFuncAttributeMaxDynamicSharedMemorySize, GH_SMEM);
    cudaFuncSetAttribute(gemm_fc, cudaFuncAttributeMaxDynamicSharedMemorySize, GH_SMEM);
    cudaFuncSetAttribute(attn_hmma, cudaFuncAttributeMaxDynamicSharedMemorySize, ATT_SMEM);

    splitW3<<<dim3(32, 32, 3), 256>>>(Wq, Wk, Wv, Wh, Wl);
    split_f32<<<1024, 256>>>(fcW, Bh, Bl, 1024 * 1024);

    gemm_proj<<<dim3(8, 32, 3), 256, GH_SMEM>>>(query, key, value, Wh, Wl,
                                                bq, bk, bv,
                                                Qh, Ql, Kh, Kl, Vh, Vl);

    attn_hmma<<<dim3(8, NH, NB), 256, ATT_SMEM>>>(Qh, Ql, Kh, Kl, Vh, Vl,
                                                  relk, relv, Oh, Ol);

    gemm_fc<<<dim3(8, 32), 256, GH_SMEM>>>(Oh, Ol, Bh, Bl, fcb, out);
}

// round 10
// speedup vs baseline: 1.0663x; 1.0228x over previous
#include <cuda_runtime.h>
#include <cuda_bf16.h>
#include <cstdint>

#define NB 4
#define NS 1024
#define NH 16
#define NDH 64
#define C2A 0.18033688f   // ATT_SCALE * log2(e)
typedef __nv_bfloat16 bf16;

// ---------------- scratch ----------------
__device__ bf16 g_Qh[NB * NH * NS * NDH];
__device__ bf16 g_Ql[NB * NH * NS * NDH];
__device__ bf16 g_Kh[NB * NH * NS * NDH];
__device__ bf16 g_Kl[NB * NH * NS * NDH];
__device__ bf16 g_Vh[NB * NH * NS * NDH];
__device__ bf16 g_Vl[NB * NH * NS * NDH];
__device__ bf16 g_Oh[4096 * 1024];
__device__ bf16 g_Ol[4096 * 1024];
__device__ bf16 g_Wh[3 * 1024 * 1024];
__device__ bf16 g_Wl[3 * 1024 * 1024];
__device__ bf16 g_Bh[1024 * 1024];
__device__ bf16 g_Bl[1024 * 1024];

// ---------------- helpers ----------------
__device__ __forceinline__ uint32_t smem_u32(const void* p) {
    uint32_t a;
    asm("{ .reg .u64 t; cvta.to.shared.u64 t, %1; cvt.u32.u64 %0, t; }"
        : "=r"(a) : "l"(p));
    return a;
}
#define CP_ASYNC16(sp, gp) \
    asm volatile("cp.async.cg.shared.global [%0], [%1], 16;" :: "r"(sp), "l"(gp) : "memory")
#define CP_COMMIT() asm volatile("cp.async.commit_group;" ::: "memory")
#define CP_WAIT(n)  asm volatile("cp.async.wait_group %0;" :: "n"(n) : "memory")
#define LDSM4(r, a) \
    asm volatile("ldmatrix.sync.aligned.m8n8.x4.shared.b16 {%0,%1,%2,%3}, [%4];" \
                 : "=r"((r)[0]), "=r"((r)[1]), "=r"((r)[2]), "=r"((r)[3]) : "r"(a))
#define LDSM4T(r, a) \
    asm volatile("ldmatrix.sync.aligned.m8n8.x4.trans.shared.b16 {%0,%1,%2,%3}, [%4];" \
                 : "=r"((r)[0]), "=r"((r)[1]), "=r"((r)[2]), "=r"((r)[3]) : "r"(a))

__device__ __forceinline__ void mma_bf16(float* d, const uint32_t* a, const uint32_t* b) {
    asm volatile(
        "mma.sync.aligned.m16n8k16.row.col.f32.bf16.bf16.f32 "
        "{%0,%1,%2,%3},{%4,%5,%6,%7},{%8,%9},{%0,%1,%2,%3};"
        : "+f"(d[0]), "+f"(d[1]), "+f"(d[2]), "+f"(d[3])
        : "r"(a[0]), "r"(a[1]), "r"(a[2]), "r"(a[3]), "r"(b[0]), "r"(b[1]));
}
__device__ __forceinline__ void split2(float v, bf16& h, bf16& l) {
    h = __float2bfloat16_rn(v);
    l = __float2bfloat16_rn(v - __bfloat162float(h));
}
__device__ __forceinline__ uint32_t pack_hi(float a, float b) {
    __nv_bfloat162 t(__float2bfloat16_rn(a), __float2bfloat16_rn(b));
    return *(uint32_t*)&t;
}
__device__ __forceinline__ uint32_t pack_lo(float a, float b) {
    bf16 ha = __float2bfloat16_rn(a), hb = __float2bfloat16_rn(b);
    __nv_bfloat162 t(__float2bfloat16_rn(a - __bfloat162float(ha)),
                     __float2bfloat16_rn(b - __bfloat162float(hb)));
    return *(uint32_t*)&t;
}

// ---------------- prep kernels ----------------
__global__ __launch_bounds__(256) void split_f32(
    const float* __restrict__ A, bf16* __restrict__ H, bf16* __restrict__ L, int n)
{
    int i = (blockIdx.x * 256 + threadIdx.x) * 4;
    if (i >= n) return;
    float4 v = *(const float4*)&A[i];
    bf16 h[4], l[4];
    split2(v.x, h[0], l[0]); split2(v.y, h[1], l[1]);
    split2(v.z, h[2], l[2]); split2(v.w, h[3], l[3]);
    *(uint2*)&H[i] = *(uint2*)h;
    *(uint2*)&L[i] = *(uint2*)l;
}

__global__ __launch_bounds__(256) void splitW3(
    const float* __restrict__ Wq, const float* __restrict__ Wk,
    const float* __restrict__ Wv, bf16* __restrict__ Ht, bf16* __restrict__ Lt)
{
    const float* W = blockIdx.z == 0 ? Wq : (blockIdx.z == 1 ? Wk : Wv);
    bf16* H = Ht + (size_t)blockIdx.z * 1048576;
    bf16* L = Lt + (size_t)blockIdx.z * 1048576;
    __shared__ float t[32][33];
    const int k0 = blockIdx.x * 32, n0 = blockIdx.y * 32;
    const int h = n0 >> 6, e0 = n0 & 63;
    const int x = threadIdx.x & 31, y = threadIdx.x >> 5;
#pragma unroll
    for (int j = 0; j < 32; j += 8)
        t[y + j][x] = W[h * 65536 + (k0 + y + j) * 64 + e0 + x];
    __syncthreads();
#pragma unroll
    for (int j = 0; j < 32; j += 8) {
        bf16 hi, lo;
        split2(t[x][y + j], hi, lo);
        size_t o = (size_t)(n0 + y + j) * 1024 + k0 + x;
        H[o] = hi; L[o] = lo;
    }
}

// =================================================================
// HMMA GEMM body (unchanged from round 9)
// =================================================================
#define BK 32
#define TILE_B (128 * 80)
#define GH_SMEM (8 * TILE_B)

template <int ASPLIT, int MODE>
__device__ __forceinline__ void gemm_body(
    char* dynsm,
    const float* __restrict__ A32,
    const bf16* __restrict__ Abh, const bf16* __restrict__ Abl,
    const bf16* __restrict__ Bh, const bf16* __restrict__ Bl,
    const float* __restrict__ bias, float* __restrict__ C,
    bf16* __restrict__ Ch, bf16* __restrict__ Cl)
{
    const uint32_t sb = smem_u32(dynsm);
    const int tid = threadIdx.x;
    const int m0 = blockIdx.y * 128, n0 = blockIdx.x * 128;
    const int lane = tid & 31, w = tid >> 5;
    const int wm = w >> 2, wn = w & 3;
    const int lr = lane & 15, lcb = (lane >> 4) * 16;

    float acc[4][4][4];
#pragma unroll
    for (int i = 0; i < 4; i++)
#pragma unroll
        for (int j = 0; j < 4; j++)
#pragma unroll
            for (int r = 0; r < 4; r++) acc[i][j][r] = 0.f;

    uint32_t aoff[4], boff[2];
#pragma unroll
    for (int i = 0; i < 4; i++)
        aoff[i] = (uint32_t)((wm * 64 + i * 16 + lr) * 80) + lcb;
#pragma unroll
    for (int hlf = 0; hlf < 2; hlf++)
        boff[hlf] = (uint32_t)((wn * 32 + hlf * 16 + lr) * 80) + lcb;

    const int a_row = tid >> 1, a_chb = (tid & 1) * 4;
    float4 areg[4];
    auto ldgA = [&](int s) {
#pragma unroll
        for (int i = 0; i < 4; i++)
            areg[i] = *(const float4*)&A32[(size_t)(m0 + a_row) * 1024 + s * BK + (a_chb + i) * 4];
    };
    auto cvtA = [&](int buf) {
        char* ph = dynsm + (size_t)(buf * 4 + 0) * TILE_B;
        char* pl = dynsm + (size_t)(buf * 4 + 1) * TILE_B;
#pragma unroll
        for (int i = 0; i < 4; i++) {
            float4 v = areg[i];
            uint32_t off = (uint32_t)(a_row * 80 + (a_chb + i) * 8);
            *(uint2*)(ph + off) = make_uint2(pack_hi(v.x, v.y), pack_hi(v.z, v.w));
            *(uint2*)(pl + off) = make_uint2(pack_lo(v.x, v.y), pack_lo(v.z, v.w));
        }
    };
    auto cpStage = [&](int s) {
        const int buf = s & 1, k0 = s * BK;
        if (ASPLIT == 0) {
#pragma unroll
            for (int mat = 0; mat < 2; mat++) {
                const bf16* g = mat ? Abl : Abh;
                uint32_t sbase = sb + (uint32_t)(buf * 4 + mat) * TILE_B;
#pragma unroll
                for (int i = 0; i < 2; i++) {
                    int idx = tid + 256 * i, row = idx >> 2, ch = idx & 3;
                    CP_ASYNC16(sbase + (uint32_t)(row * 80 + ch * 16),
                               g + (size_t)(m0 + row) * 1024 + k0 + ch * 8);
                }
            }
        }
#pragma unroll
        for (int mat = 0; mat < 2; mat++) {
            const bf16* g = mat ? Bl : Bh;
            uint32_t sbase = sb + (uint32_t)(buf * 4 + 2 + mat) * TILE_B;
#pragma unroll
            for (int i = 0; i < 2; i++) {
                int idx = tid + 256 * i, row = idx >> 2, ch = idx & 3;
                CP_ASYNC16(sbase + (uint32_t)(row * 80 + ch * 16),
                           g + (size_t)(n0 + row) * 1024 + k0 + ch * 8);
            }
        }
        CP_COMMIT();
    };

    if (ASPLIT) ldgA(0);
    cpStage(0);
    if (ASPLIT) cvtA(0);

    for (int s = 0; s < 32; s++) {
        if (s < 31) {
            if (ASPLIT) ldgA(s + 1);
            cpStage(s + 1);
            CP_WAIT(1);
        } else CP_WAIT(0);
        __syncthreads();

        const uint32_t base = sb + (uint32_t)(s & 1) * 4 * TILE_B;
#pragma unroll
        for (int kk = 0; kk < 2; kk++) {
            const uint32_t kb = kk * 32;
            uint32_t ah[4][4], al[4][4];
#pragma unroll
            for (int i = 0; i < 4; i++) {
                LDSM4(ah[i], base + aoff[i] + kb);
                LDSM4(al[i], base + TILE_B + aoff[i] + kb);
            }
            uint32_t bh[4][2], bl[4][2];
#pragma unroll
            for (int hlf = 0; hlf < 2; hlf++) {
                uint32_t r[4];
                LDSM4(r, base + 2 * TILE_B + boff[hlf] + kb);
                bh[2*hlf][0] = r[0]; bh[2*hlf+1][0] = r[1];
                bh[2*hlf][1] = r[2]; bh[2*hlf+1][1] = r[3];
                LDSM4(r, base + 3 * TILE_B + boff[hlf] + kb);
                bl[2*hlf][0] = r[0]; bl[2*hlf+1][0] = r[1];
                bl[2*hlf][1] = r[2]; bl[2*hlf+1][1] = r[3];
            }
#pragma unroll
            for (int i = 0; i < 4; i++)
#pragma unroll
                for (int j = 0; j < 4; j++) mma_bf16(acc[i][j], ah[i], bh[j]);
#pragma unroll
            for (int i = 0; i < 4; i++)
#pragma unroll
                for (int j = 0; j < 4; j++) mma_bf16(acc[i][j], ah[i], bl[j]);
#pragma unroll
            for (int i = 0; i < 4; i++)
#pragma unroll
                for (int j = 0; j < 4; j++) mma_bf16(acc[i][j], al[i], bh[j]);
        }
        __syncthreads();
        if (ASPLIT && s < 31) cvtA((s + 1) & 1);
    }

#pragma unroll
    for (int i = 0; i < 4; i++)
#pragma unroll
        for (int j = 0; j < 4; j++) {
            int row = m0 + wm * 64 + i * 16 + (lane >> 2);
            int col = n0 + wn * 32 + j * 8 + (lane & 3) * 2;
            float b0 = bias[col], b1 = bias[col + 1];
            float v00 = acc[i][j][0] + b0, v01 = acc[i][j][1] + b1;
            float v10 = acc[i][j][2] + b0, v11 = acc[i][j][3] + b1;
            if (MODE == 0) {
                *(float2*)&C[(size_t)row * 1024 + col] = make_float2(v00, v01);
                *(float2*)&C[(size_t)(row + 8) * 1024 + col] = make_float2(v10, v11);
            } else {
                int h = col >> 6, e = col & 63;
                int b = row >> 10, sI = row & 1023;
                size_t o0 = (((size_t)(b * 16 + h) * 1024 + sI) << 6) + e;
                size_t o1 = o0 + (8 << 6);
                *(uint32_t*)&Ch[o0] = pack_hi(v00, v01);
                *(uint32_t*)&Cl[o0] = pack_lo(v00, v01);
                *(uint32_t*)&Ch[o1] = pack_hi(v10, v11);
                *(uint32_t*)&Cl[o1] = pack_lo(v10, v11);
            }
        }
}

__global__ __launch_bounds__(256) void gemm_proj(
    const float* q, const float* k, const float* v,
    const bf16* Wh, const bf16* Wl,
    const float* bq, const float* bk, const float* bv,
    bf16* Qh, bf16* Ql, bf16* Kh, bf16* Kl, bf16* Vh, bf16* Vl)
{
    extern __shared__ __align__(128) char dynsm[];
    int z = blockIdx.z;
    const float* A = z == 0 ? q : (z == 1 ? k : v);
    const float* bias = z == 0 ? bq : (z == 1 ? bk : bv);
    bf16* Ch = z == 0 ? Qh : (z == 1 ? Kh : Vh);
    bf16* Cl = z == 0 ? Ql : (z == 1 ? Kl : Vl);
    gemm_body<1, 1>(dynsm, A, nullptr, nullptr,
                    Wh + (size_t)z * 1048576, Wl + (size_t)z * 1048576,
                    bias, nullptr, Ch, Cl);
}

__global__ __launch_bounds__(256) void gemm_fc(
    const bf16* Abh, const bf16* Abl, const bf16* Bh, const bf16* Bl,
    const float* bias, float* C)
{
    extern __shared__ __align__(128) char dynsm[];
    gemm_body<0, 0>(dynsm, nullptr, Abh, Abl, Bh, Bl, bias, C, nullptr, nullptr);
}

// =================================================================
// HMMA fused attention — 64 q-rows x 64 k-tile, 2 CTAs/SM.
// =================================================================
#define AQH 0
#define AQL 9216
#define AKH 18432
#define AKL 27648
#define AVH 36864
#define AVL 46080
#define APH 55296
#define APL 64512
#define ARB 73728
#define AW  77952
#define ARK 86400
#define ARV 94848
#define ALP 103296
#define AWP 103808
#define AL_ 104320
#define ATT_SMEM 104576

__global__ __launch_bounds__(256, 2) void attn_hmma(
    const bf16* __restrict__ Qh, const bf16* __restrict__ Ql,
    const bf16* __restrict__ Kh, const bf16* __restrict__ Kl,
    const bf16* __restrict__ Vh, const bf16* __restrict__ Vl,
    const float* __restrict__ relk, const float* __restrict__ relv,
    bf16* __restrict__ Oh, bf16* __restrict__ Ol)
{
    extern __shared__ __align__(128) char sm[];
    const uint32_t sb = smem_u32(sm);
    const int tid = threadIdx.x;
    const int lane = tid & 31, w = tid >> 5;
    const int q0 = blockIdx.x * 64;
    const size_t base = (size_t)(blockIdx.z * NH + blockIdx.y) * (NS * NDH);
    const int lr = lane & 15, hc = (lane >> 4) * 16;
    float* sW = (float*)(sm + AW);
    float* sRK = (float*)(sm + ARK);
    float* sRV = (float*)(sm + ARV);
    float* sLp = (float*)(sm + ALP);
    float* sWp = (float*)(sm + AWP);
    float* sL = (float*)(sm + AL_);

    // tile loader: 64 rows x 64 cols bf16 (hi+lo), row stride 144 B
    auto ldTile = [&](uint32_t dh, uint32_t dl, const bf16* gh, const bf16* gl, int t) {
#pragma unroll
        for (int i = 0; i < 2; i++) {
            int idx = tid + 256 * i, row = idx >> 3, ch = idx & 7;
            size_t go = base + (size_t)(t * 64 + row) * 64 + ch * 8;
            uint32_t so = (uint32_t)(row * 144 + ch * 16);
            CP_ASYNC16(sb + dh + so, gh + go);
            CP_ASYNC16(sb + dl + so, gl + go);
        }
        CP_COMMIT();
    };

    {
#pragma unroll
        for (int i = 0; i < 2; i++) {
            int idx = tid + 256 * i, row = idx >> 3, ch = idx & 7;
            size_t go = base + (size_t)(q0 + row) * 64 + ch * 8;
            uint32_t so = (uint32_t)(row * 144 + ch * 16);
            CP_ASYNC16(sb + AQH + so, Qh + go);
            CP_ASYNC16(sb + AQL + so, Ql + go);
        }
        CP_COMMIT();
    }
    ldTile(AKH, AKL, Kh, Kl, 0);
    ldTile(AVH, AVL, Vh, Vl, 0);

    for (int i = tid; i < 33 * 64; i += 256) { sRK[i] = relk[i]; sRV[i] = relv[i]; }
    for (int i = tid; i < 64 * 33; i += 256) sW[i] = 0.f;

    CP_WAIT(2);          // Q landed
    __syncthreads();

    // r[q][d] = (q . relk[d]) * C2A  (bf16, pre-scaled for exp2)
    {
        int q = tid >> 2;
        int part = tid & 3;
        int d0 = part * 8, nd = (part == 3) ? 9 : 8;
        float qv[64];
#pragma unroll
        for (int e2 = 0; e2 < 32; e2++) {
            uint32_t hv = *(uint32_t*)(sm + AQH + q * 144 + e2 * 4);
            uint32_t lv = *(uint32_t*)(sm + AQL + q * 144 + e2 * 4);
            float2 fh = __bfloat1622float2(*(__nv_bfloat162*)&hv);
            float2 fl = __bfloat1622float2(*(__nv_bfloat162*)&lv);
            qv[2 * e2] = fh.x + fl.x;
            qv[2 * e2 + 1] = fh.y + fl.y;
        }
        for (int d = d0; d < d0 + nd; d++) {
            float s = 0.f;
#pragma unroll
            for (int e = 0; e < 64; e++) s += qv[e] * sRK[d * 64 + e];
            *(bf16*)(sm + ARB + (q * 33 + d) * 2) = __float2bfloat16_rn(s * C2A);
        }
    }
    __syncthreads();

    const int wm = w >> 1, wn = w & 1;   // 16 rows x 32 cols per warp (both phases)
    float acc2[4][4];
#pragma unroll
    for (int j = 0; j < 4; j++)
#pragma unroll
        for (int r = 0; r < 4; r++) acc2[j][r] = 0.f;
    float lsum[2] = {0.f, 0.f};
    float wsuf[2] = {0.f, 0.f};

    for (int t = 0; t < 16; t++) {
        CP_WAIT(1);
        __syncthreads();

        // ---- QK phase: 16 rows x 32 cols ----
        float acc[4][4];
#pragma unroll
        for (int j = 0; j < 4; j++)
#pragma unroll
            for (int r = 0; r < 4; r++) acc[j][r] = 0.f;
#pragma unroll
        for (int es = 0; es < 4; es++) {
            uint32_t ah[4], al[4];
            {
                uint32_t ao = (uint32_t)((wm * 16 + lr) * 144) + hc + es * 32;
                LDSM4(ah, sb + AQH + ao);
                LDSM4(al, sb + AQL + ao);
            }
            uint32_t bh[4][2], bl[4][2];
#pragma unroll
            for (int c = 0; c < 2; c++) {
                uint32_t bo = (uint32_t)((wn * 32 + c * 16 + lr) * 144) + hc + es * 32;
                uint32_t r[4];
                LDSM4(r, sb + AKH + bo);
                bh[2*c][0] = r[0]; bh[2*c+1][0] = r[1];
                bh[2*c][1] = r[2]; bh[2*c+1][1] = r[3];
                LDSM4(r, sb + AKL + bo);
                bl[2*c][0] = r[0]; bl[2*c+1][0] = r[1];
                bl[2*c][1] = r[2]; bl[2*c+1][1] = r[3];
            }
#pragma unroll
            for (int j = 0; j < 4; j++) mma_bf16(acc[j], ah, bh[j]);
#pragma unroll
            for (int j = 0; j < 4; j++) mma_bf16(acc[j], ah, bl[j]);
#pragma unroll
            for (int j = 0; j < 4; j++) mma_bf16(acc[j], al, bh[j]);
        }
        __syncthreads();
        if (t < 15) ldTile(AKH, AKL, Kh, Kl, t + 1);

        // ---- softmax epilogue -> P (bf16 hi/lo) ----
        const int k0 = t * 64;
        const int X = blockIdx.x;
        const int cls = (t + 2 <= X) ? 0 : ((t >= X + 2) ? 2 : 1);
        if (cls != 1) {
            float rbv[2];
#pragma unroll
            for (int rh = 0; rh < 2; rh++) {
                int rr = wm * 16 + (lane >> 2) + rh * 8;
                rbv[rh] = __bfloat162float(
                    *(bf16*)(sm + ARB + (rr * 33 + (cls == 2 ? 32 : 0)) * 2));
            }
#pragma unroll
            for (int j = 0; j < 4; j++) {
                int col = wn * 32 + j * 8 + (lane & 3) * 2;
#pragma unroll
                for (int rh = 0; rh < 2; rh++) {
                    int rr = wm * 16 + (lane >> 2) + rh * 8;
                    float p0 = exp2f(fmaf(acc[j][rh * 2 + 0], C2A, rbv[rh]));
                    float p1 = exp2f(fmaf(acc[j][rh * 2 + 1], C2A, rbv[rh]));
                    lsum[rh] += p0 + p1;
                    if (cls == 2) wsuf[rh] += p0 + p1;
                    uint32_t po = (uint32_t)(rr * 144 + col * 2);
                    *(uint32_t*)(sm + APH + po) = pack_hi(p0, p1);
                    *(uint32_t*)(sm + APL + po) = pack_lo(p0, p1);
                }
            }
        } else {
#pragma unroll
            for (int j = 0; j < 4; j++) {
                int col = wn * 32 + j * 8 + (lane & 3) * 2;
#pragma unroll
                for (int rh = 0; rh < 2; rh++) {
                    int rr = wm * 16 + (lane >> 2) + rh * 8;
                    int qg = q0 + rr;
                    float p01[2];
#pragma unroll
                    for (int v = 0; v < 2; v++) {
                        int kg = k0 + col + v;
                        int dd = kg - qg;
                        int dc = dd < -16 ? -16 : (dd > 16 ? 16 : dd);
                        float rb = __bfloat162float(
                            *(bf16*)(sm + ARB + (rr * 33 + dc + 16) * 2));
                        float p = exp2f(fmaf(acc[j][rh * 2 + v], C2A, rb));
                        p01[v] = p;
                        lsum[rh] += p;
                        if (dd >= 16) wsuf[rh] += p;
                        else if (dd > -16) sW[rr * 33 + dd + 16] = p;
                    }
                    uint32_t po = (uint32_t)(rr * 144 + col * 2);
                    *(uint32_t*)(sm + APH + po) = pack_hi(p01[0], p01[1]);
                    *(uint32_t*)(sm + APL + po) = pack_lo(p01[0], p01[1]);
                }
            }
        }
        if (t < 15) { CP_WAIT(1); } else { CP_WAIT(0); }
        __syncthreads();   // P visible + V[t] ready

        // ---- PV phase: 16 rows x 32 dh cols per warp ----
#pragma unroll
        for (int ks = 0; ks < 4; ks++) {
            uint32_t ph[4], pl[4];
            uint32_t po = (uint32_t)((wm * 16 + lr) * 144) + ks * 32 + hc;
            LDSM4(ph, sb + APH + po);
            LDSM4(pl, sb + APL + po);
            uint32_t vh[4][2], vl[4][2];
#pragma unroll
            for (int c = 0; c < 2; c++) {
                int cg = wn * 2 + c;   // 16-col group 0..3
                uint32_t vo = (uint32_t)((ks * 16 + lr) * 144) + (cg * 2 + (lane >> 4)) * 16;
                uint32_t r[4];
                LDSM4T(r, sb + AVH + vo);
                vh[2*c][0] = r[0]; vh[2*c][1] = r[1];
                vh[2*c+1][0] = r[2]; vh[2*c+1][1] = r[3];
                LDSM4T(r, sb + AVL + vo);
                vl[2*c][0] = r[0]; vl[2*c][1] = r[1];
                vl[2*c+1][0] = r[2]; vl[2*c+1][1] = r[3];
            }
#pragma unroll
            for (int nf = 0; nf < 4; nf++) mma_bf16(acc2[nf], ph, vh[nf]);
#pragma unroll
            for (int nf = 0; nf < 4; nf++) mma_bf16(acc2[nf], ph, vl[nf]);
#pragma unroll
            for (int nf = 0; nf < 4; nf++) mma_bf16(acc2[nf], pl, vh[nf]);
        }
        __syncthreads();
        if (t < 15) ldTile(AVH, AVL, Vh, Vl, t + 1);
    }

    // ---- deterministic l / w32 reduction ----
#pragma unroll
    for (int i = 0; i < 2; i++) {
        lsum[i] += __shfl_xor_sync(0xffffffffu, lsum[i], 1);
        lsum[i] += __shfl_xor_sync(0xffffffffu, lsum[i], 2);
        wsuf[i] += __shfl_xor_sync(0xffffffffu, wsuf[i], 1);
        wsuf[i] += __shfl_xor_sync(0xffffffffu, wsuf[i], 2);
    }
    if ((lane & 3) == 0) {
#pragma unroll
        for (int rh = 0; rh < 2; rh++) {
            int row = wm * 16 + rh * 8 + (lane >> 2);
            sLp[row * 2 + wn] = lsum[rh];
            sWp[row * 2 + wn] = wsuf[rh];
        }
    }
    __syncthreads();
    if (tid < 64) {
        int r = tid;
        float l = sLp[r * 2] + sLp[r * 2 + 1];
        float ws = sWp[r * 2] + sWp[r * 2 + 1];
        float mid = 0.f;
#pragma unroll
        for (int d = 1; d < 32; d++) mid += sW[r * 33 + d];
        sW[r * 33 + 0] = l - ws - mid;
        sW[r * 33 + 32] = ws;
        sL[r] = 1.f / l;
    }
    __syncthreads();

    // ---- rel_v bias + normalize + store O (bf16 hi/lo, [B,S,HID]) ----
#pragma unroll
    for (int nf = 0; nf < 4; nf++) {
        int row0 = wm * 16 + (lane >> 2), row1 = row0 + 8;
        int col = wn * 32 + nf * 8 + (lane & 3) * 2;
        float b00 = 0.f, b01 = 0.f, b10 = 0.f, b11 = 0.f;
#pragma unroll
        for (int d = 0; d < 33; d++) {
            float w0v = sW[row0 * 33 + d], w1v = sW[row1 * 33 + d];
            float r0 = sRV[d * 64 + col], r1 = sRV[d * 64 + col + 1];
            b00 += w0v * r0; b01 += w0v * r1;
            b10 += w1v * r0; b11 += w1v * r1;
        }
        float il0 = sL[row0], il1 = sL[row1];
        float o00 = (acc2[nf][0] + b00) * il0, o01 = (acc2[nf][1] + b01) * il0;
        float o10 = (acc2[nf][2] + b10) * il1, o11 = (acc2[nf][3] + b11) * il1;
        size_t g0 = ((size_t)(blockIdx.z * 1024 + q0 + row0)) * 1024 + blockIdx.y * 64 + col;
        size_t g1 = ((size_t)(blockIdx.z * 1024 + q0 + row1)) * 1024 + blockIdx.y * 64 + col;
        *(uint32_t*)&Oh[g0] = pack_hi(o00, o01);
        *(uint32_t*)&Ol[g0] = pack_lo(o00, o01);
        *(uint32_t*)&Oh[g1] = pack_hi(o10, o11);
        *(uint32_t*)&Ol[g1] = pack_lo(o10, o11);
    }
}

// =================================================================
extern "C" void kernel_launch(void* const* d_in, const int* in_sizes, int n_in,
                              void* d_out, int out_size)
{
    const float* query = (const float*)d_in[0];
    const float* key   = (const float*)d_in[1];
    const float* value = (const float*)d_in[2];
    const float* Wq    = (const float*)d_in[3];
    const float* bq    = (const float*)d_in[4];
    const float* Wk    = (const float*)d_in[5];
    const float* bk    = (const float*)d_in[6];
    const float* Wv    = (const float*)d_in[7];
    const float* bv    = (const float*)d_in[8];
    const float* relk  = (const float*)d_in[9];
    const float* relv  = (const float*)d_in[10];
    const float* fcW   = (const float*)d_in[11];
    const float* fcb   = (const float*)d_in[12];
    float* out = (float*)d_out;

    bf16 *Qh, *Ql, *Kh, *Kl, *Vh, *Vl, *Oh, *Ol, *Wh, *Wl, *Bh, *Bl;
    cudaGetSymbolAddress((void**)&Qh, g_Qh); cudaGetSymbolAddress((void**)&Ql, g_Ql);
    cudaGetSymbolAddress((void**)&Kh, g_Kh); cudaGetSymbolAddress((void**)&Kl, g_Kl);
    cudaGetSymbolAddress((void**)&Vh, g_Vh); cudaGetSymbolAddress((void**)&Vl, g_Vl);
    cudaGetSymbolAddress((void**)&Oh, g_Oh); cudaGetSymbolAddress((void**)&Ol, g_Ol);
    cudaGetSymbolAddress((void**)&Wh, g_Wh); cudaGetSymbolAddress((void**)&Wl, g_Wl);
    cudaGetSymbolAddress((void**)&Bh, g_Bh); cudaGetSymbolAddress((void**)&Bl, g_Bl);

    cudaFuncSetAttribute(gemm_proj, cudaFuncAttributeMaxDynamicSharedMemorySize, GH_SMEM);
    cudaFuncSetAttribute(gemm_fc, cudaFuncAttributeMaxDynamicSharedMemorySize, GH_SMEM);
    cudaFuncSetAttribute(attn_hmma, cudaFuncAttributeMaxDynamicSharedMemorySize, ATT_SMEM);

    splitW3<<<dim3(32, 32, 3), 256>>>(Wq, Wk, Wv, Wh, Wl);
    split_f32<<<1024, 256>>>(fcW, Bh, Bl, 1024 * 1024);

    gemm_proj<<<dim3(8, 32, 3), 256, GH_SMEM>>>(query, key, value, Wh, Wl,
                                                bq, bk, bv,
                                                Qh, Ql, Kh, Kl, Vh, Vl);

    attn_hmma<<<dim3(16, NH, NB), 256, ATT_SMEM>>>(Qh, Ql, Kh, Kl, Vh, Vl,
                                                   relk, relv, Oh, Ol);

    gemm_fc<<<dim3(8, 32), 256, GH_SMEM>>>(Oh, Ol, Bh, Bl, fcb, out);
}

// round 11
// speedup vs baseline: 1.3838x; 1.2977x over previous
#include <cuda_runtime.h>
#include <cuda_fp16.h>
#include <cstdint>

#define NB 4
#define NS 1024
#define NH 16
#define NDH 64
#define C2A 0.18033688f   // ATT_SCALE * log2(e)
typedef __half hf;

// ---------------- scratch ----------------
__device__ hf g_Qh[NB * NH * NS * NDH];
__device__ hf g_Ql[NB * NH * NS * NDH];   // written by proj, unused by attn
__device__ hf g_Kh[NB * NH * NS * NDH];
__device__ hf g_Kl[NB * NH * NS * NDH];
__device__ hf g_Vh[NB * NH * NS * NDH];
__device__ hf g_Vl[NB * NH * NS * NDH];
__device__ hf g_Oh[4096 * 1024];
__device__ hf g_Wh[3 * 1024 * 1024];
__device__ hf g_Wl[3 * 1024 * 1024];
__device__ hf g_Bh[1024 * 1024];
__device__ hf g_Bl[1024 * 1024];

// ---------------- helpers ----------------
__device__ __forceinline__ uint32_t smem_u32(const void* p) {
    uint32_t a;
    asm("{ .reg .u64 t; cvta.to.shared.u64 t, %1; cvt.u32.u64 %0, t; }"
        : "=r"(a) : "l"(p));
    return a;
}
#define CP_ASYNC16(sp, gp) \
    asm volatile("cp.async.cg.shared.global [%0], [%1], 16;" :: "r"(sp), "l"(gp) : "memory")
#define CP_COMMIT() asm volatile("cp.async.commit_group;" ::: "memory")
#define CP_WAIT(n)  asm volatile("cp.async.wait_group %0;" :: "n"(n) : "memory")
#define LDSM4(r, a) \
    asm volatile("ldmatrix.sync.aligned.m8n8.x4.shared.b16 {%0,%1,%2,%3}, [%4];" \
                 : "=r"((r)[0]), "=r"((r)[1]), "=r"((r)[2]), "=r"((r)[3]) : "r"(a))
#define LDSM4T(r, a) \
    asm volatile("ldmatrix.sync.aligned.m8n8.x4.trans.shared.b16 {%0,%1,%2,%3}, [%4];" \
                 : "=r"((r)[0]), "=r"((r)[1]), "=r"((r)[2]), "=r"((r)[3]) : "r"(a))

__device__ __forceinline__ void mma_f16(float* d, const uint32_t* a, const uint32_t* b) {
    asm volatile(
        "mma.sync.aligned.m16n8k16.row.col.f32.f16.f16.f32 "
        "{%0,%1,%2,%3},{%4,%5,%6,%7},{%8,%9},{%0,%1,%2,%3};"
        : "+f"(d[0]), "+f"(d[1]), "+f"(d[2]), "+f"(d[3])
        : "r"(a[0]), "r"(a[1]), "r"(a[2]), "r"(a[3]), "r"(b[0]), "r"(b[1]));
}
__device__ __forceinline__ void split2(float v, hf& h, hf& l) {
    h = __float2half_rn(v);
    l = __float2half_rn(v - __half2float(h));
}
__device__ __forceinline__ uint32_t pk_h(float a, float b) {
    __half2 t = __floats2half2_rn(a, b);
    return *(uint32_t*)&t;
}
__device__ __forceinline__ uint32_t pk_l(float a, float b) {
    float ha = __half2float(__float2half_rn(a));
    float hb = __half2float(__float2half_rn(b));
    __half2 t = __floats2half2_rn(a - ha, b - hb);
    return *(uint32_t*)&t;
}

// ---------------- prep kernels ----------------
__global__ __launch_bounds__(256) void split_f32(
    const float* __restrict__ A, hf* __restrict__ H, hf* __restrict__ L, int n)
{
    int i = (blockIdx.x * 256 + threadIdx.x) * 4;
    if (i >= n) return;
    float4 v = *(const float4*)&A[i];
    hf h[4], l[4];
    split2(v.x, h[0], l[0]); split2(v.y, h[1], l[1]);
    split2(v.z, h[2], l[2]); split2(v.w, h[3], l[3]);
    *(uint2*)&H[i] = *(uint2*)h;
    *(uint2*)&L[i] = *(uint2*)l;
}

__global__ __launch_bounds__(256) void splitW3(
    const float* __restrict__ Wq, const float* __restrict__ Wk,
    const float* __restrict__ Wv, hf* __restrict__ Ht, hf* __restrict__ Lt)
{
    const float* W = blockIdx.z == 0 ? Wq : (blockIdx.z == 1 ? Wk : Wv);
    hf* H = Ht + (size_t)blockIdx.z * 1048576;
    hf* L = Lt + (size_t)blockIdx.z * 1048576;
    __shared__ float t[32][33];
    const int k0 = blockIdx.x * 32, n0 = blockIdx.y * 32;
    const int h = n0 >> 6, e0 = n0 & 63;
    const int x = threadIdx.x & 31, y = threadIdx.x >> 5;
#pragma unroll
    for (int j = 0; j < 32; j += 8)
        t[y + j][x] = W[h * 65536 + (k0 + y + j) * 64 + e0 + x];
    __syncthreads();
#pragma unroll
    for (int j = 0; j < 32; j += 8) {
        hf hi, lo;
        split2(t[x][y + j], hi, lo);
        size_t o = (size_t)(n0 + y + j) * 1024 + k0 + x;
        H[o] = hi; L[o] = lo;
    }
}

// =================================================================
// HMMA GEMM body — fp16, A single (hi), B hi/lo: 2 MMA passes.
// smem slots per stage: 0=Ah, 1=Bh, 2=Bl.
// =================================================================
#define BK 32
#define TILE_B (128 * 80)
#define GH_SMEM (6 * TILE_B)

template <int ASPLIT, int MODE>
__device__ __forceinline__ void gemm_body(
    char* dynsm,
    const float* __restrict__ A32, const hf* __restrict__ Abh,
    const hf* __restrict__ Bh, const hf* __restrict__ Bl,
    const float* __restrict__ bias, float* __restrict__ C,
    hf* __restrict__ Ch, hf* __restrict__ Cl)
{
    const uint32_t sb = smem_u32(dynsm);
    const int tid = threadIdx.x;
    const int m0 = blockIdx.y * 128, n0 = blockIdx.x * 128;
    const int lane = tid & 31, w = tid >> 5;
    const int wm = w >> 2, wn = w & 3;
    const int lr = lane & 15, lcb = (lane >> 4) * 16;

    float acc[4][4][4];
#pragma unroll
    for (int i = 0; i < 4; i++)
#pragma unroll
        for (int j = 0; j < 4; j++)
#pragma unroll
            for (int r = 0; r < 4; r++) acc[i][j][r] = 0.f;

    uint32_t aoff[4], boff[2];
#pragma unroll
    for (int i = 0; i < 4; i++)
        aoff[i] = (uint32_t)((wm * 64 + i * 16 + lr) * 80) + lcb;
#pragma unroll
    for (int hlf = 0; hlf < 2; hlf++)
        boff[hlf] = (uint32_t)((wn * 32 + hlf * 16 + lr) * 80) + lcb;

    const int a_row = tid >> 1, a_chb = (tid & 1) * 4;
    float4 areg[4];
    auto ldgA = [&](int s) {
#pragma unroll
        for (int i = 0; i < 4; i++)
            areg[i] = *(const float4*)&A32[(size_t)(m0 + a_row) * 1024 + s * BK + (a_chb + i) * 4];
    };
    auto cvtA = [&](int buf) {
        char* ph = dynsm + (size_t)(buf * 3 + 0) * TILE_B;
#pragma unroll
        for (int i = 0; i < 4; i++) {
            float4 v = areg[i];
            uint32_t off = (uint32_t)(a_row * 80 + (a_chb + i) * 8);
            *(uint2*)(ph + off) = make_uint2(pk_h(v.x, v.y), pk_h(v.z, v.w));
        }
    };
    auto cpStage = [&](int s) {
        const int buf = s & 1, k0 = s * BK;
        if (ASPLIT == 0) {
            uint32_t sbase = sb + (uint32_t)(buf * 3 + 0) * TILE_B;
#pragma unroll
            for (int i = 0; i < 2; i++) {
                int idx = tid + 256 * i, row = idx >> 2, ch = idx & 3;
                CP_ASYNC16(sbase + (uint32_t)(row * 80 + ch * 16),
                           Abh + (size_t)(m0 + row) * 1024 + k0 + ch * 8);
            }
        }
#pragma unroll
        for (int mat = 0; mat < 2; mat++) {
            const hf* g = mat ? Bl : Bh;
            uint32_t sbase = sb + (uint32_t)(buf * 3 + 1 + mat) * TILE_B;
#pragma unroll
            for (int i = 0; i < 2; i++) {
                int idx = tid + 256 * i, row = idx >> 2, ch = idx & 3;
                CP_ASYNC16(sbase + (uint32_t)(row * 80 + ch * 16),
                           g + (size_t)(n0 + row) * 1024 + k0 + ch * 8);
            }
        }
        CP_COMMIT();
    };

    if (ASPLIT) ldgA(0);
    cpStage(0);
    if (ASPLIT) cvtA(0);

    for (int s = 0; s < 32; s++) {
        if (s < 31) {
            if (ASPLIT) ldgA(s + 1);
            cpStage(s + 1);
            CP_WAIT(1);
        } else CP_WAIT(0);
        __syncthreads();

        const uint32_t base = sb + (uint32_t)(s & 1) * 3 * TILE_B;
#pragma unroll
        for (int kk = 0; kk < 2; kk++) {
            const uint32_t kb = kk * 32;
            uint32_t ah[4][4];
#pragma unroll
            for (int i = 0; i < 4; i++)
                LDSM4(ah[i], base + aoff[i] + kb);
            uint32_t bh[4][2], bl[4][2];
#pragma unroll
            for (int hlf = 0; hlf < 2; hlf++) {
                uint32_t r[4];
                LDSM4(r, base + TILE_B + boff[hlf] + kb);
                bh[2*hlf][0] = r[0]; bh[2*hlf+1][0] = r[1];
                bh[2*hlf][1] = r[2]; bh[2*hlf+1][1] = r[3];
                LDSM4(r, base + 2 * TILE_B + boff[hlf] + kb);
                bl[2*hlf][0] = r[0]; bl[2*hlf+1][0] = r[1];
                bl[2*hlf][1] = r[2]; bl[2*hlf+1][1] = r[3];
            }
#pragma unroll
            for (int i = 0; i < 4; i++)
#pragma unroll
                for (int j = 0; j < 4; j++) mma_f16(acc[i][j], ah[i], bh[j]);
#pragma unroll
            for (int i = 0; i < 4; i++)
#pragma unroll
                for (int j = 0; j < 4; j++) mma_f16(acc[i][j], ah[i], bl[j]);
        }
        __syncthreads();
        if (ASPLIT && s < 31) cvtA((s + 1) & 1);
    }

#pragma unroll
    for (int i = 0; i < 4; i++)
#pragma unroll
        for (int j = 0; j < 4; j++) {
            int row = m0 + wm * 64 + i * 16 + (lane >> 2);
            int col = n0 + wn * 32 + j * 8 + (lane & 3) * 2;
            float b0 = bias[col], b1 = bias[col + 1];
            float v00 = acc[i][j][0] + b0, v01 = acc[i][j][1] + b1;
            float v10 = acc[i][j][2] + b0, v11 = acc[i][j][3] + b1;
            if (MODE == 0) {
                *(float2*)&C[(size_t)row * 1024 + col] = make_float2(v00, v01);
                *(float2*)&C[(size_t)(row + 8) * 1024 + col] = make_float2(v10, v11);
            } else {
                int h = col >> 6, e = col & 63;
                int b = row >> 10, sI = row & 1023;
                size_t o0 = (((size_t)(b * 16 + h) * 1024 + sI) << 6) + e;
                size_t o1 = o0 + (8 << 6);
                *(uint32_t*)&Ch[o0] = pk_h(v00, v01);
                *(uint32_t*)&Cl[o0] = pk_l(v00, v01);
                *(uint32_t*)&Ch[o1] = pk_h(v10, v11);
                *(uint32_t*)&Cl[o1] = pk_l(v10, v11);
            }
        }
}

__global__ __launch_bounds__(256) void gemm_proj(
    const float* q, const float* k, const float* v,
    const hf* Wh, const hf* Wl,
    const float* bq, const float* bk, const float* bv,
    hf* Qh, hf* Ql, hf* Kh, hf* Kl, hf* Vh, hf* Vl)
{
    extern __shared__ __align__(128) char dynsm[];
    int z = blockIdx.z;
    const float* A = z == 0 ? q : (z == 1 ? k : v);
    const float* bias = z == 0 ? bq : (z == 1 ? bk : bv);
    hf* Ch = z == 0 ? Qh : (z == 1 ? Kh : Vh);
    hf* Cl = z == 0 ? Ql : (z == 1 ? Kl : Vl);
    gemm_body<1, 1>(dynsm, A, nullptr,
                    Wh + (size_t)z * 1048576, Wl + (size_t)z * 1048576,
                    bias, nullptr, Ch, Cl);
}

__global__ __launch_bounds__(256) void gemm_fc(
    const hf* Abh, const hf* Bh, const hf* Bl,
    const float* bias, float* C)
{
    extern __shared__ __align__(128) char dynsm[];
    gemm_body<0, 0>(dynsm, nullptr, Abh, Bh, Bl, bias, C, nullptr, nullptr);
}

// =================================================================
// HMMA fused attention — fp16, Q/P single, K/V hi/lo. 2 CTAs/SM.
// =================================================================
#define AQH 0
#define AKH 9216
#define AKL 18432
#define AVH 27648
#define AVL 36864
#define APH 46080
#define ARB 55296
#define AW  59520
#define ARK 67968
#define ARV 76416
#define ALP 84864
#define AWP 85376
#define AL_ 85888
#define ATT_SMEM 86144

__global__ __launch_bounds__(256, 2) void attn_hmma(
    const hf* __restrict__ Qh,
    const hf* __restrict__ Kh, const hf* __restrict__ Kl,
    const hf* __restrict__ Vh, const hf* __restrict__ Vl,
    const float* __restrict__ relk, const float* __restrict__ relv,
    hf* __restrict__ Oh)
{
    extern __shared__ __align__(128) char sm[];
    const uint32_t sb = smem_u32(sm);
    const int tid = threadIdx.x;
    const int lane = tid & 31, w = tid >> 5;
    const int q0 = blockIdx.x * 64;
    const size_t base = (size_t)(blockIdx.z * NH + blockIdx.y) * (NS * NDH);
    const int lr = lane & 15, hc = (lane >> 4) * 16;
    float* sW = (float*)(sm + AW);
    float* sRK = (float*)(sm + ARK);
    float* sRV = (float*)(sm + ARV);
    float* sLp = (float*)(sm + ALP);
    float* sWp = (float*)(sm + AWP);
    float* sL = (float*)(sm + AL_);

    // K/V tile loader: 64x64 fp16 hi+lo, row stride 144 B
    auto ldTile = [&](uint32_t dh, uint32_t dl, const hf* gh, const hf* gl, int t) {
#pragma unroll
        for (int i = 0; i < 2; i++) {
            int idx = tid + 256 * i, row = idx >> 3, ch = idx & 7;
            size_t go = base + (size_t)(t * 64 + row) * 64 + ch * 8;
            uint32_t so = (uint32_t)(row * 144 + ch * 16);
            CP_ASYNC16(sb + dh + so, gh + go);
            CP_ASYNC16(sb + dl + so, gl + go);
        }
        CP_COMMIT();
    };

    {   // Q tile: hi only
#pragma unroll
        for (int i = 0; i < 2; i++) {
            int idx = tid + 256 * i, row = idx >> 3, ch = idx & 7;
            size_t go = base + (size_t)(q0 + row) * 64 + ch * 8;
            CP_ASYNC16(sb + AQH + (uint32_t)(row * 144 + ch * 16), Qh + go);
        }
        CP_COMMIT();
    }
    ldTile(AKH, AKL, Kh, Kl, 0);
    ldTile(AVH, AVL, Vh, Vl, 0);

    for (int i = tid; i < 33 * 64; i += 256) { sRK[i] = relk[i]; sRV[i] = relv[i]; }
    for (int i = tid; i < 64 * 33; i += 256) sW[i] = 0.f;

    CP_WAIT(2);
    __syncthreads();

    // r[q][d] = (q . relk[d]) * C2A  (fp16, pre-scaled for exp2)
    {
        int q = tid >> 2;
        int part = tid & 3;
        int d0 = part * 8, nd = (part == 3) ? 9 : 8;
        float qv[64];
#pragma unroll
        for (int e2 = 0; e2 < 32; e2++) {
            uint32_t hv = *(uint32_t*)(sm + AQH + q * 144 + e2 * 4);
            float2 fh = __half22float2(*(__half2*)&hv);
            qv[2 * e2] = fh.x;
            qv[2 * e2 + 1] = fh.y;
        }
        for (int d = d0; d < d0 + nd; d++) {
            float s = 0.f;
#pragma unroll
            for (int e = 0; e < 64; e++) s += qv[e] * sRK[d * 64 + e];
            *(hf*)(sm + ARB + (q * 33 + d) * 2) = __float2half_rn(s * C2A);
        }
    }
    __syncthreads();

    const int wm = w >> 1, wn = w & 1;   // 16 rows x 32 cols per warp
    float acc2[4][4];
#pragma unroll
    for (int j = 0; j < 4; j++)
#pragma unroll
        for (int r = 0; r < 4; r++) acc2[j][r] = 0.f;
    float lsum[2] = {0.f, 0.f};
    float wsuf[2] = {0.f, 0.f};

    for (int t = 0; t < 16; t++) {
        CP_WAIT(1);
        __syncthreads();

        // ---- QK phase ----
        float acc[4][4];
#pragma unroll
        for (int j = 0; j < 4; j++)
#pragma unroll
            for (int r = 0; r < 4; r++) acc[j][r] = 0.f;
#pragma unroll
        for (int es = 0; es < 4; es++) {
            uint32_t ah[4];
            LDSM4(ah, sb + AQH + (uint32_t)((wm * 16 + lr) * 144) + hc + es * 32);
            uint32_t bh[4][2], bl[4][2];
#pragma unroll
            for (int c = 0; c < 2; c++) {
                uint32_t bo = (uint32_t)((wn * 32 + c * 16 + lr) * 144) + hc + es * 32;
                uint32_t r[4];
                LDSM4(r, sb + AKH + bo);
                bh[2*c][0] = r[0]; bh[2*c+1][0] = r[1];
                bh[2*c][1] = r[2]; bh[2*c+1][1] = r[3];
                LDSM4(r, sb + AKL + bo);
                bl[2*c][0] = r[0]; bl[2*c+1][0] = r[1];
                bl[2*c][1] = r[2]; bl[2*c+1][1] = r[3];
            }
#pragma unroll
            for (int j = 0; j < 4; j++) mma_f16(acc[j], ah, bh[j]);
#pragma unroll
            for (int j = 0; j < 4; j++) mma_f16(acc[j], ah, bl[j]);
        }
        __syncthreads();
        if (t < 15) ldTile(AKH, AKL, Kh, Kl, t + 1);

        // ---- softmax epilogue -> P (fp16 hi only) ----
        const int k0 = t * 64;
        const int X = blockIdx.x;
        const int cls = (t + 2 <= X) ? 0 : ((t >= X + 2) ? 2 : 1);
        if (cls != 1) {
            float rbv[2];
#pragma unroll
            for (int rh = 0; rh < 2; rh++) {
                int rr = wm * 16 + (lane >> 2) + rh * 8;
                rbv[rh] = __half2float(
                    *(hf*)(sm + ARB + (rr * 33 + (cls == 2 ? 32 : 0)) * 2));
            }
#pragma unroll
            for (int j = 0; j < 4; j++) {
                int col = wn * 32 + j * 8 + (lane & 3) * 2;
#pragma unroll
                for (int rh = 0; rh < 2; rh++) {
                    int rr = wm * 16 + (lane >> 2) + rh * 8;
                    float p0 = exp2f(fmaf(acc[j][rh * 2 + 0], C2A, rbv[rh]));
                    float p1 = exp2f(fmaf(acc[j][rh * 2 + 1], C2A, rbv[rh]));
                    lsum[rh] += p0 + p1;
                    if (cls == 2) wsuf[rh] += p0 + p1;
                    *(uint32_t*)(sm + APH + (uint32_t)(rr * 144 + col * 2)) = pk_h(p0, p1);
                }
            }
        } else {
#pragma unroll
            for (int j = 0; j < 4; j++) {
                int col = wn * 32 + j * 8 + (lane & 3) * 2;
#pragma unroll
                for (int rh = 0; rh < 2; rh++) {
                    int rr = wm * 16 + (lane >> 2) + rh * 8;
                    int qg = q0 + rr;
                    float p01[2];
#pragma unroll
                    for (int v = 0; v < 2; v++) {
                        int kg = k0 + col + v;
                        int dd = kg - qg;
                        int dc = dd < -16 ? -16 : (dd > 16 ? 16 : dd);
                        float rb = __half2float(
                            *(hf*)(sm + ARB + (rr * 33 + dc + 16) * 2));
                        float p = exp2f(fmaf(acc[j][rh * 2 + v], C2A, rb));
                        p01[v] = p;
                        lsum[rh] += p;
                        if (dd >= 16) wsuf[rh] += p;
                        else if (dd > -16) sW[rr * 33 + dd + 16] = p;
                    }
                    *(uint32_t*)(sm + APH + (uint32_t)(rr * 144 + col * 2)) =
                        pk_h(p01[0], p01[1]);
                }
            }
        }
        if (t < 15) { CP_WAIT(1); } else { CP_WAIT(0); }
        __syncthreads();   // P visible + V[t] ready

        // ---- PV phase ----
#pragma unroll
        for (int ks = 0; ks < 4; ks++) {
            uint32_t ph[4];
            LDSM4(ph, sb + APH + (uint32_t)((wm * 16 + lr) * 144) + ks * 32 + hc);
            uint32_t vh[4][2], vl[4][2];
#pragma unroll
            for (int c = 0; c < 2; c++) {
                int cg = wn * 2 + c;
                uint32_t vo = (uint32_t)((ks * 16 + lr) * 144) + (cg * 2 + (lane >> 4)) * 16;
                uint32_t r[4];
                LDSM4T(r, sb + AVH + vo);
                vh[2*c][0] = r[0]; vh[2*c][1] = r[1];
                vh[2*c+1][0] = r[2]; vh[2*c+1][1] = r[3];
                LDSM4T(r, sb + AVL + vo);
                vl[2*c][0] = r[0]; vl[2*c][1] = r[1];
                vl[2*c+1][0] = r[2]; vl[2*c+1][1] = r[3];
            }
#pragma unroll
            for (int nf = 0; nf < 4; nf++) mma_f16(acc2[nf], ph, vh[nf]);
#pragma unroll
            for (int nf = 0; nf < 4; nf++) mma_f16(acc2[nf], ph, vl[nf]);
        }
        __syncthreads();
        if (t < 15) ldTile(AVH, AVL, Vh, Vl, t + 1);
    }

    // ---- deterministic l / w32 reduction ----
#pragma unroll
    for (int i = 0; i < 2; i++) {
        lsum[i] += __shfl_xor_sync(0xffffffffu, lsum[i], 1);
        lsum[i] += __shfl_xor_sync(0xffffffffu, lsum[i], 2);
        wsuf[i] += __shfl_xor_sync(0xffffffffu, wsuf[i], 1);
        wsuf[i] += __shfl_xor_sync(0xffffffffu, wsuf[i], 2);
    }
    if ((lane & 3) == 0) {
#pragma unroll
        for (int rh = 0; rh < 2; rh++) {
            int row = wm * 16 + rh * 8 + (lane >> 2);
            sLp[row * 2 + wn] = lsum[rh];
            sWp[row * 2 + wn] = wsuf[rh];
        }
    }
    __syncthreads();
    if (tid < 64) {
        int r = tid;
        float l = sLp[r * 2] + sLp[r * 2 + 1];
        float ws = sWp[r * 2] + sWp[r * 2 + 1];
        float mid = 0.f;
#pragma unroll
        for (int d = 1; d < 32; d++) mid += sW[r * 33 + d];
        sW[r * 33 + 0] = l - ws - mid;
        sW[r * 33 + 32] = ws;
        sL[r] = 1.f / l;
    }
    __syncthreads();

    // ---- rel_v bias + normalize + store O (fp16 hi, [B,S,HID]) ----
#pragma unroll
    for (int nf = 0; nf < 4; nf++) {
        int row0 = wm * 16 + (lane >> 2), row1 = row0 + 8;
        int col = wn * 32 + nf * 8 + (lane & 3) * 2;
        float b00 = 0.f, b01 = 0.f, b10 = 0.f, b11 = 0.f;
#pragma unroll
        for (int d = 0; d < 33; d++) {
            float w0v = sW[row0 * 33 + d], w1v = sW[row1 * 33 + d];
            float r0 = sRV[d * 64 + col], r1 = sRV[d * 64 + col + 1];
            b00 += w0v * r0; b01 += w0v * r1;
            b10 += w1v * r0; b11 += w1v * r1;
        }
        float il0 = sL[row0], il1 = sL[row1];
        float o00 = (acc2[nf][0] + b00) * il0, o01 = (acc2[nf][1] + b01) * il0;
        float o10 = (acc2[nf][2] + b10) * il1, o11 = (acc2[nf][3] + b11) * il1;
        size_t g0 = ((size_t)(blockIdx.z * 1024 + q0 + row0)) * 1024 + blockIdx.y * 64 + col;
        size_t g1 = ((size_t)(blockIdx.z * 1024 + q0 + row1)) * 1024 + blockIdx.y * 64 + col;
        *(uint32_t*)&Oh[g0] = pk_h(o00, o01);
        *(uint32_t*)&Oh[g1] = pk_h(o10, o11);
    }
}

// =================================================================
extern "C" void kernel_launch(void* const* d_in, const int* in_sizes, int n_in,
                              void* d_out, int out_size)
{
    const float* query = (const float*)d_in[0];
    const float* key   = (const float*)d_in[1];
    const float* value = (const float*)d_in[2];
    const float* Wq    = (const float*)d_in[3];
    const float* bq    = (const float*)d_in[4];
    const float* Wk    = (const float*)d_in[5];
    const float* bk    = (const float*)d_in[6];
    const float* Wv    = (const float*)d_in[7];
    const float* bv    = (const float*)d_in[8];
    const float* relk  = (const float*)d_in[9];
    const float* relv  = (const float*)d_in[10];
    const float* fcW   = (const float*)d_in[11];
    const float* fcb   = (const float*)d_in[12];
    float* out = (float*)d_out;

    hf *Qh, *Ql, *Kh, *Kl, *Vh, *Vl, *Oh, *Wh, *Wl, *Bh, *Bl;
    cudaGetSymbolAddress((void**)&Qh, g_Qh); cudaGetSymbolAddress((void**)&Ql, g_Ql);
    cudaGetSymbolAddress((void**)&Kh, g_Kh); cudaGetSymbolAddress((void**)&Kl, g_Kl);
    cudaGetSymbolAddress((void**)&Vh, g_Vh); cudaGetSymbolAddress((void**)&Vl, g_Vl);
    cudaGetSymbolAddress((void**)&Oh, g_Oh);
    cudaGetSymbolAddress((void**)&Wh, g_Wh); cudaGetSymbolAddress((void**)&Wl, g_Wl);
    cudaGetSymbolAddress((void**)&Bh, g_Bh); cudaGetSymbolAddress((void**)&Bl, g_Bl);

    cudaFuncSetAttribute(gemm_proj, cudaFuncAttributeMaxDynamicSharedMemorySize, GH_SMEM);
    cudaFuncSetAttribute(gemm_fc, cudaFuncAttributeMaxDynamicSharedMemorySize, GH_SMEM);
    cudaFuncSetAttribute(attn_hmma, cudaFuncAttributeMaxDynamicSharedMemorySize, ATT_SMEM);

    splitW3<<<dim3(32, 32, 3), 256>>>(Wq, Wk, Wv, Wh, Wl);
    split_f32<<<1024, 256>>>(fcW, Bh, Bl, 1024 * 1024);

    gemm_proj<<<dim3(8, 32, 3), 256, GH_SMEM>>>(query, key, value, Wh, Wl,
                                                bq, bk, bv,
                                                Qh, Ql, Kh, Kl, Vh, Vl);

    attn_hmma<<<dim3(16, NH, NB), 256, ATT_SMEM>>>(Qh, Kh, Kl, Vh, Vl,
                                                   relk, relv, Oh);

    gemm_fc<<<dim3(8, 32), 256, GH_SMEM>>>(Oh, Bh, Bl, fcb, out);
}

// round 12
// speedup vs baseline: 1.4097x; 1.0187x over previous
#include <cuda_runtime.h>
#include <cuda_fp16.h>
#include <cstdint>

#define NB 4
#define NS 1024
#define NH 16
#define NDH 64
#define C2A 0.18033688f   // ATT_SCALE * log2(e)
typedef __half hf;

// ---------------- scratch ----------------
__device__ hf g_Qh[NB * NH * NS * NDH];
__device__ hf g_Kh[NB * NH * NS * NDH];
__device__ hf g_Vh[NB * NH * NS * NDH];
__device__ hf g_Oh[4096 * 1024];
__device__ hf g_Wh[3 * 1024 * 1024];
__device__ hf g_Wl[3 * 1024 * 1024];
__device__ hf g_Bh[1024 * 1024];
__device__ hf g_Bl[1024 * 1024];

// ---------------- helpers ----------------
__device__ __forceinline__ uint32_t smem_u32(const void* p) {
    uint32_t a;
    asm("{ .reg .u64 t; cvta.to.shared.u64 t, %1; cvt.u32.u64 %0, t; }"
        : "=r"(a) : "l"(p));
    return a;
}
#define CP_ASYNC16(sp, gp) \
    asm volatile("cp.async.cg.shared.global [%0], [%1], 16;" :: "r"(sp), "l"(gp) : "memory")
#define CP_COMMIT() asm volatile("cp.async.commit_group;" ::: "memory")
#define CP_WAIT(n)  asm volatile("cp.async.wait_group %0;" :: "n"(n) : "memory")
#define LDSM4(r, a) \
    asm volatile("ldmatrix.sync.aligned.m8n8.x4.shared.b16 {%0,%1,%2,%3}, [%4];" \
                 : "=r"((r)[0]), "=r"((r)[1]), "=r"((r)[2]), "=r"((r)[3]) : "r"(a))
#define LDSM4T(r, a) \
    asm volatile("ldmatrix.sync.aligned.m8n8.x4.trans.shared.b16 {%0,%1,%2,%3}, [%4];" \
                 : "=r"((r)[0]), "=r"((r)[1]), "=r"((r)[2]), "=r"((r)[3]) : "r"(a))

__device__ __forceinline__ void mma_f16(float* d, const uint32_t* a, const uint32_t* b) {
    asm volatile(
        "mma.sync.aligned.m16n8k16.row.col.f32.f16.f16.f32 "
        "{%0,%1,%2,%3},{%4,%5,%6,%7},{%8,%9},{%0,%1,%2,%3};"
        : "+f"(d[0]), "+f"(d[1]), "+f"(d[2]), "+f"(d[3])
        : "r"(a[0]), "r"(a[1]), "r"(a[2]), "r"(a[3]), "r"(b[0]), "r"(b[1]));
}
__device__ __forceinline__ void split2(float v, hf& h, hf& l) {
    h = __float2half_rn(v);
    l = __float2half_rn(v - __half2float(h));
}
__device__ __forceinline__ uint32_t pk_h(float a, float b) {
    __half2 t = __floats2half2_rn(a, b);
    return *(uint32_t*)&t;
}

// ---------------- prep kernels ----------------
__global__ __launch_bounds__(256) void split_f32(
    const float* __restrict__ A, hf* __restrict__ H, hf* __restrict__ L, int n)
{
    int i = (blockIdx.x * 256 + threadIdx.x) * 4;
    if (i >= n) return;
    float4 v = *(const float4*)&A[i];
    hf h[4], l[4];
    split2(v.x, h[0], l[0]); split2(v.y, h[1], l[1]);
    split2(v.z, h[2], l[2]); split2(v.w, h[3], l[3]);
    *(uint2*)&H[i] = *(uint2*)h;
    *(uint2*)&L[i] = *(uint2*)l;
}

__global__ __launch_bounds__(256) void splitW3(
    const float* __restrict__ Wq, const float* __restrict__ Wk,
    const float* __restrict__ Wv, hf* __restrict__ Ht, hf* __restrict__ Lt)
{
    const float* W = blockIdx.z == 0 ? Wq : (blockIdx.z == 1 ? Wk : Wv);
    hf* H = Ht + (size_t)blockIdx.z * 1048576;
    hf* L = Lt + (size_t)blockIdx.z * 1048576;
    __shared__ float t[32][33];
    const int k0 = blockIdx.x * 32, n0 = blockIdx.y * 32;
    const int h = n0 >> 6, e0 = n0 & 63;
    const int x = threadIdx.x & 31, y = threadIdx.x >> 5;
#pragma unroll
    for (int j = 0; j < 32; j += 8)
        t[y + j][x] = W[h * 65536 + (k0 + y + j) * 64 + e0 + x];
    __syncthreads();
#pragma unroll
    for (int j = 0; j < 32; j += 8) {
        hf hi, lo;
        split2(t[x][y + j], hi, lo);
        size_t o = (size_t)(n0 + y + j) * 1024 + k0 + x;
        H[o] = hi; L[o] = lo;
    }
}

// =================================================================
// HMMA GEMM body — fp16, A single (hi), B hi/lo: 2 MMA passes.
// smem slots per stage: 0=Ah, 1=Bh, 2=Bl.
// MODE 0: fp32 C row-major.  MODE 1: fp16 hi only at [B,H,S,DH].
// =================================================================
#define BK 32
#define TILE_B (128 * 80)
#define GH_SMEM (6 * TILE_B)

template <int ASPLIT, int MODE>
__device__ __forceinline__ void gemm_body(
    char* dynsm,
    const float* __restrict__ A32, const hf* __restrict__ Abh,
    const hf* __restrict__ Bh, const hf* __restrict__ Bl,
    const float* __restrict__ bias, float* __restrict__ C,
    hf* __restrict__ Ch)
{
    const uint32_t sb = smem_u32(dynsm);
    const int tid = threadIdx.x;
    const int m0 = blockIdx.y * 128, n0 = blockIdx.x * 128;
    const int lane = tid & 31, w = tid >> 5;
    const int wm = w >> 2, wn = w & 3;
    const int lr = lane & 15, lcb = (lane >> 4) * 16;

    float acc[4][4][4];
#pragma unroll
    for (int i = 0; i < 4; i++)
#pragma unroll
        for (int j = 0; j < 4; j++)
#pragma unroll
            for (int r = 0; r < 4; r++) acc[i][j][r] = 0.f;

    uint32_t aoff[4], boff[2];
#pragma unroll
    for (int i = 0; i < 4; i++)
        aoff[i] = (uint32_t)((wm * 64 + i * 16 + lr) * 80) + lcb;
#pragma unroll
    for (int hlf = 0; hlf < 2; hlf++)
        boff[hlf] = (uint32_t)((wn * 32 + hlf * 16 + lr) * 80) + lcb;

    const int a_row = tid >> 1, a_chb = (tid & 1) * 4;
    float4 areg[4];
    auto ldgA = [&](int s) {
#pragma unroll
        for (int i = 0; i < 4; i++)
            areg[i] = *(const float4*)&A32[(size_t)(m0 + a_row) * 1024 + s * BK + (a_chb + i) * 4];
    };
    auto cvtA = [&](int buf) {
        char* ph = dynsm + (size_t)(buf * 3 + 0) * TILE_B;
#pragma unroll
        for (int i = 0; i < 4; i++) {
            float4 v = areg[i];
            uint32_t off = (uint32_t)(a_row * 80 + (a_chb + i) * 8);
            *(uint2*)(ph + off) = make_uint2(pk_h(v.x, v.y), pk_h(v.z, v.w));
        }
    };
    auto cpStage = [&](int s) {
        const int buf = s & 1, k0 = s * BK;
        if (ASPLIT == 0) {
            uint32_t sbase = sb + (uint32_t)(buf * 3 + 0) * TILE_B;
#pragma unroll
            for (int i = 0; i < 2; i++) {
                int idx = tid + 256 * i, row = idx >> 2, ch = idx & 3;
                CP_ASYNC16(sbase + (uint32_t)(row * 80 + ch * 16),
                           Abh + (size_t)(m0 + row) * 1024 + k0 + ch * 8);
            }
        }
#pragma unroll
        for (int mat = 0; mat < 2; mat++) {
            const hf* g = mat ? Bl : Bh;
            uint32_t sbase = sb + (uint32_t)(buf * 3 + 1 + mat) * TILE_B;
#pragma unroll
            for (int i = 0; i < 2; i++) {
                int idx = tid + 256 * i, row = idx >> 2, ch = idx & 3;
                CP_ASYNC16(sbase + (uint32_t)(row * 80 + ch * 16),
                           g + (size_t)(n0 + row) * 1024 + k0 + ch * 8);
            }
        }
        CP_COMMIT();
    };

    if (ASPLIT) ldgA(0);
    cpStage(0);
    if (ASPLIT) cvtA(0);

    for (int s = 0; s < 32; s++) {
        if (s < 31) {
            if (ASPLIT) ldgA(s + 1);
            cpStage(s + 1);
            CP_WAIT(1);
        } else CP_WAIT(0);
        __syncthreads();

        const uint32_t base = sb + (uint32_t)(s & 1) * 3 * TILE_B;
#pragma unroll
        for (int kk = 0; kk < 2; kk++) {
            const uint32_t kb = kk * 32;
            uint32_t ah[4][4];
#pragma unroll
            for (int i = 0; i < 4; i++)
                LDSM4(ah[i], base + aoff[i] + kb);
            uint32_t bh[4][2], bl[4][2];
#pragma unroll
            for (int hlf = 0; hlf < 2; hlf++) {
                uint32_t r[4];
                LDSM4(r, base + TILE_B + boff[hlf] + kb);
                bh[2*hlf][0] = r[0]; bh[2*hlf+1][0] = r[1];
                bh[2*hlf][1] = r[2]; bh[2*hlf+1][1] = r[3];
                LDSM4(r, base + 2 * TILE_B + boff[hlf] + kb);
                bl[2*hlf][0] = r[0]; bl[2*hlf+1][0] = r[1];
                bl[2*hlf][1] = r[2]; bl[2*hlf+1][1] = r[3];
            }
#pragma unroll
            for (int i = 0; i < 4; i++)
#pragma unroll
                for (int j = 0; j < 4; j++) mma_f16(acc[i][j], ah[i], bh[j]);
#pragma unroll
            for (int i = 0; i < 4; i++)
#pragma unroll
                for (int j = 0; j < 4; j++) mma_f16(acc[i][j], ah[i], bl[j]);
        }
        __syncthreads();
        if (ASPLIT && s < 31) cvtA((s + 1) & 1);
    }

#pragma unroll
    for (int i = 0; i < 4; i++)
#pragma unroll
        for (int j = 0; j < 4; j++) {
            int row = m0 + wm * 64 + i * 16 + (lane >> 2);
            int col = n0 + wn * 32 + j * 8 + (lane & 3) * 2;
            float b0 = bias[col], b1 = bias[col + 1];
            float v00 = acc[i][j][0] + b0, v01 = acc[i][j][1] + b1;
            float v10 = acc[i][j][2] + b0, v11 = acc[i][j][3] + b1;
            if (MODE == 0) {
                *(float2*)&C[(size_t)row * 1024 + col] = make_float2(v00, v01);
                *(float2*)&C[(size_t)(row + 8) * 1024 + col] = make_float2(v10, v11);
            } else {
                int h = col >> 6, e = col & 63;
                int b = row >> 10, sI = row & 1023;
                size_t o0 = (((size_t)(b * 16 + h) * 1024 + sI) << 6) + e;
                size_t o1 = o0 + (8 << 6);
                *(uint32_t*)&Ch[o0] = pk_h(v00, v01);
                *(uint32_t*)&Ch[o1] = pk_h(v10, v11);
            }
        }
}

__global__ __launch_bounds__(256) void gemm_proj(
    const float* q, const float* k, const float* v,
    const hf* Wh, const hf* Wl,
    const float* bq, const float* bk, const float* bv,
    hf* Qh, hf* Kh, hf* Vh)
{
    extern __shared__ __align__(128) char dynsm[];
    int z = blockIdx.z;
    const float* A = z == 0 ? q : (z == 1 ? k : v);
    const float* bias = z == 0 ? bq : (z == 1 ? bk : bv);
    hf* Ch = z == 0 ? Qh : (z == 1 ? Kh : Vh);
    gemm_body<1, 1>(dynsm, A, nullptr,
                    Wh + (size_t)z * 1048576, Wl + (size_t)z * 1048576,
                    bias, nullptr, Ch);
}

__global__ __launch_bounds__(256) void gemm_fc(
    const hf* Abh, const hf* Bh, const hf* Bl,
    const float* bias, float* C)
{
    extern __shared__ __align__(128) char dynsm[];
    gemm_body<0, 0>(dynsm, nullptr, Abh, Bh, Bl, bias, C, nullptr);
}

// =================================================================
// HMMA fused attention — all-fp16-single Q/K/V/P.  2 CTAs/SM.
// =================================================================
#define AQH 0
#define AKH 9216
#define AVH 18432
#define APH 27648
#define ARB 36864
#define AW  41088
#define ARK 49536
#define ARV 57984
#define ALP 66432
#define AWP 66944
#define AL_ 67456
#define ATT_SMEM 67712

__global__ __launch_bounds__(256, 2) void attn_hmma(
    const hf* __restrict__ Qh,
    const hf* __restrict__ Kh, const hf* __restrict__ Vh,
    const float* __restrict__ relk, const float* __restrict__ relv,
    hf* __restrict__ Oh)
{
    extern __shared__ __align__(128) char sm[];
    const uint32_t sb = smem_u32(sm);
    const int tid = threadIdx.x;
    const int lane = tid & 31, w = tid >> 5;
    const int q0 = blockIdx.x * 64;
    const size_t base = (size_t)(blockIdx.z * NH + blockIdx.y) * (NS * NDH);
    const int lr = lane & 15, hc = (lane >> 4) * 16;
    float* sW = (float*)(sm + AW);
    float* sRK = (float*)(sm + ARK);
    float* sRV = (float*)(sm + ARV);
    float* sLp = (float*)(sm + ALP);
    float* sWp = (float*)(sm + AWP);
    float* sL = (float*)(sm + AL_);

    // tile loader: 64x64 fp16, row stride 144 B
    auto ldTile = [&](uint32_t dst, const hf* g, int t) {
#pragma unroll
        for (int i = 0; i < 2; i++) {
            int idx = tid + 256 * i, row = idx >> 3, ch = idx & 7;
            size_t go = base + (size_t)(t * 64 + row) * 64 + ch * 8;
            CP_ASYNC16(sb + dst + (uint32_t)(row * 144 + ch * 16), g + go);
        }
        CP_COMMIT();
    };

    {   // Q tile
#pragma unroll
        for (int i = 0; i < 2; i++) {
            int idx = tid + 256 * i, row = idx >> 3, ch = idx & 7;
            size_t go = base + (size_t)(q0 + row) * 64 + ch * 8;
            CP_ASYNC16(sb + AQH + (uint32_t)(row * 144 + ch * 16), Qh + go);
        }
        CP_COMMIT();
    }
    ldTile(AKH, Kh, 0);
    ldTile(AVH, Vh, 0);

    for (int i = tid; i < 33 * 64; i += 256) { sRK[i] = relk[i]; sRV[i] = relv[i]; }
    for (int i = tid; i < 64 * 33; i += 256) sW[i] = 0.f;

    CP_WAIT(2);
    __syncthreads();

    // r[q][d] = (q . relk[d]) * C2A  (fp16, pre-scaled for exp2)
    {
        int q = tid >> 2;
        int part = tid & 3;
        int d0 = part * 8, nd = (part == 3) ? 9 : 8;
        float qv[64];
#pragma unroll
        for (int e2 = 0; e2 < 32; e2++) {
            uint32_t hv = *(uint32_t*)(sm + AQH + q * 144 + e2 * 4);
            float2 fh = __half22float2(*(__half2*)&hv);
            qv[2 * e2] = fh.x;
            qv[2 * e2 + 1] = fh.y;
        }
        for (int d = d0; d < d0 + nd; d++) {
            float s = 0.f;
#pragma unroll
            for (int e = 0; e < 64; e++) s += qv[e] * sRK[d * 64 + e];
            *(hf*)(sm + ARB + (q * 33 + d) * 2) = __float2half_rn(s * C2A);
        }
    }
    __syncthreads();

    const int wm = w >> 1, wn = w & 1;   // 16 rows x 32 cols per warp
    float acc2[4][4];
#pragma unroll
    for (int j = 0; j < 4; j++)
#pragma unroll
        for (int r = 0; r < 4; r++) acc2[j][r] = 0.f;
    float lsum[2] = {0.f, 0.f};
    float wsuf[2] = {0.f, 0.f};

    for (int t = 0; t < 16; t++) {
        CP_WAIT(1);
        __syncthreads();

        // ---- QK phase ----
        float acc[4][4];
#pragma unroll
        for (int j = 0; j < 4; j++)
#pragma unroll
            for (int r = 0; r < 4; r++) acc[j][r] = 0.f;
#pragma unroll
        for (int es = 0; es < 4; es++) {
            uint32_t ah[4];
            LDSM4(ah, sb + AQH + (uint32_t)((wm * 16 + lr) * 144) + hc + es * 32);
            uint32_t bh[4][2];
#pragma unroll
            for (int c = 0; c < 2; c++) {
                uint32_t bo = (uint32_t)((wn * 32 + c * 16 + lr) * 144) + hc + es * 32;
                uint32_t r[4];
                LDSM4(r, sb + AKH + bo);
                bh[2*c][0] = r[0]; bh[2*c+1][0] = r[1];
                bh[2*c][1] = r[2]; bh[2*c+1][1] = r[3];
            }
#pragma unroll
            for (int j = 0; j < 4; j++) mma_f16(acc[j], ah, bh[j]);
        }
        __syncthreads();
        if (t < 15) ldTile(AKH, Kh, t + 1);

        // ---- softmax epilogue -> P (fp16) ----
        const int k0 = t * 64;
        const int X = blockIdx.x;
        const int cls = (t + 2 <= X) ? 0 : ((t >= X + 2) ? 2 : 1);
        if (cls != 1) {
            float rbv[2];
#pragma unroll
            for (int rh = 0; rh < 2; rh++) {
                int rr = wm * 16 + (lane >> 2) + rh * 8;
                rbv[rh] = __half2float(
                    *(hf*)(sm + ARB + (rr * 33 + (cls == 2 ? 32 : 0)) * 2));
            }
#pragma unroll
            for (int j = 0; j < 4; j++) {
                int col = wn * 32 + j * 8 + (lane & 3) * 2;
#pragma unroll
                for (int rh = 0; rh < 2; rh++) {
                    int rr = wm * 16 + (lane >> 2) + rh * 8;
                    float p0 = exp2f(fmaf(acc[j][rh * 2 + 0], C2A, rbv[rh]));
                    float p1 = exp2f(fmaf(acc[j][rh * 2 + 1], C2A, rbv[rh]));
                    lsum[rh] += p0 + p1;
                    if (cls == 2) wsuf[rh] += p0 + p1;
                    *(uint32_t*)(sm + APH + (uint32_t)(rr * 144 + col * 2)) = pk_h(p0, p1);
                }
            }
        } else {
#pragma unroll
            for (int j = 0; j < 4; j++) {
                int col = wn * 32 + j * 8 + (lane & 3) * 2;
#pragma unroll
                for (int rh = 0; rh < 2; rh++) {
                    int rr = wm * 16 + (lane >> 2) + rh * 8;
                    int qg = q0 + rr;
                    float p01[2];
#pragma unroll
                    for (int v = 0; v < 2; v++) {
                        int kg = k0 + col + v;
                        int dd = kg - qg;
                        int dc = dd < -16 ? -16 : (dd > 16 ? 16 : dd);
                        float rb = __half2float(
                            *(hf*)(sm + ARB + (rr * 33 + dc + 16) * 2));
                        float p = exp2f(fmaf(acc[j][rh * 2 + v], C2A, rb));
                        p01[v] = p;
                        lsum[rh] += p;
                        if (dd >= 16) wsuf[rh] += p;
                        else if (dd > -16) sW[rr * 33 + dd + 16] = p;
                    }
                    *(uint32_t*)(sm + APH + (uint32_t)(rr * 144 + col * 2)) =
                        pk_h(p01[0], p01[1]);
                }
            }
        }
        if (t < 15) { CP_WAIT(1); } else { CP_WAIT(0); }
        __syncthreads();   // P visible + V[t] ready

        // ---- PV phase ----
#pragma unroll
        for (int ks = 0; ks < 4; ks++) {
            uint32_t ph[4];
            LDSM4(ph, sb + APH + (uint32_t)((wm * 16 + lr) * 144) + ks * 32 + hc);
            uint32_t vh[4][2];
#pragma unroll
            for (int c = 0; c < 2; c++) {
                int cg = wn * 2 + c;
                uint32_t vo = (uint32_t)((ks * 16 + lr) * 144) + (cg * 2 + (lane >> 4)) * 16;
                uint32_t r[4];
                LDSM4T(r, sb + AVH + vo);
                vh[2*c][0] = r[0]; vh[2*c][1] = r[1];
                vh[2*c+1][0] = r[2]; vh[2*c+1][1] = r[3];
            }
#pragma unroll
            for (int nf = 0; nf < 4; nf++) mma_f16(acc2[nf], ph, vh[nf]);
        }
        __syncthreads();
        if (t < 15) ldTile(AVH, Vh, t + 1);
    }

    // ---- deterministic l / w32 reduction ----
#pragma unroll
    for (int i = 0; i < 2; i++) {
        lsum[i] += __shfl_xor_sync(0xffffffffu, lsum[i], 1);
        lsum[i] += __shfl_xor_sync(0xffffffffu, lsum[i], 2);
        wsuf[i] += __shfl_xor_sync(0xffffffffu, wsuf[i], 1);
        wsuf[i] += __shfl_xor_sync(0xffffffffu, wsuf[i], 2);
    }
    if ((lane & 3) == 0) {
#pragma unroll
        for (int rh = 0; rh < 2; rh++) {
            int row = wm * 16 + rh * 8 + (lane >> 2);
            sLp[row * 2 + wn] = lsum[rh];
            sWp[row * 2 + wn] = wsuf[rh];
        }
    }
    __syncthreads();
    if (tid < 64) {
        int r = tid;
        float l = sLp[r * 2] + sLp[r * 2 + 1];
        float ws = sWp[r * 2] + sWp[r * 2 + 1];
        float mid = 0.f;
#pragma unroll
        for (int d = 1; d < 32; d++) mid += sW[r * 33 + d];
        sW[r * 33 + 0] = l - ws - mid;
        sW[r * 33 + 32] = ws;
        sL[r] = 1.f / l;
    }
    __syncthreads();

    // ---- rel_v bias + normalize + store O (fp16, [B,S,HID]) ----
#pragma unroll
    for (int nf = 0; nf < 4; nf++) {
        int row0 = wm * 16 + (lane >> 2), row1 = row0 + 8;
        int col = wn * 32 + nf * 8 + (lane & 3) * 2;
        float b00 = 0.f, b01 = 0.f, b10 = 0.f, b11 = 0.f;
#pragma unroll
        for (int d = 0; d < 33; d++) {
            float w0v = sW[row0 * 33 + d], w1v = sW[row1 * 33 + d];
            float r0 = sRV[d * 64 + col], r1 = sRV[d * 64 + col + 1];
            b00 += w0v * r0; b01 += w0v * r1;
            b10 += w1v * r0; b11 += w1v * r1;
        }
        float il0 = sL[row0], il1 = sL[row1];
        float o00 = (acc2[nf][0] + b00) * il0, o01 = (acc2[nf][1] + b01) * il0;
        float o10 = (acc2[nf][2] + b10) * il1, o11 = (acc2[nf][3] + b11) * il1;
        size_t g0 = ((size_t)(blockIdx.z * 1024 + q0 + row0)) * 1024 + blockIdx.y * 64 + col;
        size_t g1 = ((size_t)(blockIdx.z * 1024 + q0 + row1)) * 1024 + blockIdx.y * 64 + col;
        *(uint32_t*)&Oh[g0] = pk_h(o00, o01);
        *(uint32_t*)&Oh[g1] = pk_h(o10, o11);
    }
}

// =================================================================
extern "C" void kernel_launch(void* const* d_in, const int* in_sizes, int n_in,
                              void* d_out, int out_size)
{
    const float* query = (const float*)d_in[0];
    const float* key   = (const float*)d_in[1];
    const float* value = (const float*)d_in[2];
    const float* Wq    = (const float*)d_in[3];
    const float* bq    = (const float*)d_in[4];
    const float* Wk    = (const float*)d_in[5];
    const float* bk    = (const float*)d_in[6];
    const float* Wv    = (const float*)d_in[7];
    const float* bv    = (const float*)d_in[8];
    const float* relk  = (const float*)d_in[9];
    const float* relv  = (const float*)d_in[10];
    const float* fcW   = (const float*)d_in[11];
    const float* fcb   = (const float*)d_in[12];
    float* out = (float*)d_out;

    hf *Qh, *Kh, *Vh, *Oh, *Wh, *Wl, *Bh, *Bl;
    cudaGetSymbolAddress((void**)&Qh, g_Qh);
    cudaGetSymbolAddress((void**)&Kh, g_Kh);
    cudaGetSymbolAddress((void**)&Vh, g_Vh);
    cudaGetSymbolAddress((void**)&Oh, g_Oh);
    cudaGetSymbolAddress((void**)&Wh, g_Wh); cudaGetSymbolAddress((void**)&Wl, g_Wl);
    cudaGetSymbolAddress((void**)&Bh, g_Bh); cudaGetSymbolAddress((void**)&Bl, g_Bl);

    cudaFuncSetAttribute(gemm_proj, cudaFuncAttributeMaxDynamicSharedMemorySize, GH_SMEM);
    cudaFuncSetAttribute(gemm_fc, cudaFuncAttributeMaxDynamicSharedMemorySize, GH_SMEM);
    cudaFuncSetAttribute(attn_hmma, cudaFuncAttributeMaxDynamicSharedMemorySize, ATT_SMEM);

    splitW3<<<dim3(32, 32, 3), 256>>>(Wq, Wk, Wv, Wh, Wl);
    split_f32<<<1024, 256>>>(fcW, Bh, Bl, 1024 * 1024);

    gemm_proj<<<dim3(8, 32, 3), 256, GH_SMEM>>>(query, key, value, Wh, Wl,
                                                bq, bk, bv, Qh, Kh, Vh);

    attn_hmma<<<dim3(16, NH, NB), 256, ATT_SMEM>>>(Qh, Kh, Vh, relk, relv, Oh);

    gemm_fc<<<dim3(8, 32), 256, GH_SMEM>>>(Oh, Bh, Bl, fcb, out);
}

// round 13
// speedup vs baseline: 1.9649x; 1.3939x over previous
#include <cuda_runtime.h>
#include <cuda_fp16.h>
#include <cstdint>

#define NB 4
#define NS 1024
#define NH 16
#define NDH 64
#define C2A 0.18033688f   // ATT_SCALE * log2(e)
typedef __half hf;

// ---------------- scratch ----------------
__device__ hf g_Qh[NB * NH * NS * NDH];
__device__ hf g_Kh[NB * NH * NS * NDH];
__device__ hf g_Vh[NB * NH * NS * NDH];
__device__ hf g_Oh[4096 * 1024];
__device__ hf g_Wh[3 * 1024 * 1024];
__device__ hf g_Bh[1024 * 1024];

// ---------------- helpers ----------------
__device__ __forceinline__ uint32_t smem_u32(const void* p) {
    uint32_t a;
    asm("{ .reg .u64 t; cvta.to.shared.u64 t, %1; cvt.u32.u64 %0, t; }"
        : "=r"(a) : "l"(p));
    return a;
}
#define CP_ASYNC16(sp, gp) \
    asm volatile("cp.async.cg.shared.global [%0], [%1], 16;" :: "r"(sp), "l"(gp) : "memory")
#define CP_COMMIT() asm volatile("cp.async.commit_group;" ::: "memory")
#define CP_WAIT(n)  asm volatile("cp.async.wait_group %0;" :: "n"(n) : "memory")
#define LDSM4(r, a) \
    asm volatile("ldmatrix.sync.aligned.m8n8.x4.shared.b16 {%0,%1,%2,%3}, [%4];" \
                 : "=r"((r)[0]), "=r"((r)[1]), "=r"((r)[2]), "=r"((r)[3]) : "r"(a))
#define LDSM4T(r, a) \
    asm volatile("ldmatrix.sync.aligned.m8n8.x4.trans.shared.b16 {%0,%1,%2,%3}, [%4];" \
                 : "=r"((r)[0]), "=r"((r)[1]), "=r"((r)[2]), "=r"((r)[3]) : "r"(a))

__device__ __forceinline__ void mma_f16(float* d, const uint32_t* a, const uint32_t* b) {
    asm volatile(
        "mma.sync.aligned.m16n8k16.row.col.f32.f16.f16.f32 "
        "{%0,%1,%2,%3},{%4,%5,%6,%7},{%8,%9},{%0,%1,%2,%3};"
        : "+f"(d[0]), "+f"(d[1]), "+f"(d[2]), "+f"(d[3])
        : "r"(a[0]), "r"(a[1]), "r"(a[2]), "r"(a[3]), "r"(b[0]), "r"(b[1]));
}
__device__ __forceinline__ uint32_t pk_h(float a, float b) {
    __half2 t = __floats2half2_rn(a, b);
    return *(uint32_t*)&t;
}

// ---------------- prep kernels (fp16 hi only) ----------------
__global__ __launch_bounds__(256) void cvt_f32(
    const float* __restrict__ A, hf* __restrict__ H, int n)
{
    int i = (blockIdx.x * 256 + threadIdx.x) * 4;
    if (i >= n) return;
    float4 v = *(const float4*)&A[i];
    uint2 o = make_uint2(pk_h(v.x, v.y), pk_h(v.z, v.w));
    *(uint2*)&H[i] = o;
}

__global__ __launch_bounds__(256) void cvtW3(
    const float* __restrict__ Wq, const float* __restrict__ Wk,
    const float* __restrict__ Wv, hf* __restrict__ Ht)
{
    const float* W = blockIdx.z == 0 ? Wq : (blockIdx.z == 1 ? Wk : Wv);
    hf* H = Ht + (size_t)blockIdx.z * 1048576;
    __shared__ float t[32][33];
    const int k0 = blockIdx.x * 32, n0 = blockIdx.y * 32;
    const int h = n0 >> 6, e0 = n0 & 63;
    const int x = threadIdx.x & 31, y = threadIdx.x >> 5;
#pragma unroll
    for (int j = 0; j < 32; j += 8)
        t[y + j][x] = W[h * 65536 + (k0 + y + j) * 64 + e0 + x];
    __syncthreads();
#pragma unroll
    for (int j = 0; j < 32; j += 8)
        H[(size_t)(n0 + y + j) * 1024 + k0 + x] = __float2half_rn(t[x][y + j]);
}

// =================================================================
// HMMA GEMM body — fp16 single precision both sides, 1 MMA pass.
// smem slots per stage: 0=Ah, 1=Bh.
// MODE 0: fp32 C row-major.  MODE 1: fp16 at [B,H,S,DH].
// =================================================================
#define BK 32
#define TILE_B (128 * 80)
#define GH_SMEM (4 * TILE_B)

template <int ASPLIT, int MODE>
__device__ __forceinline__ void gemm_body(
    char* dynsm,
    const float* __restrict__ A32, const hf* __restrict__ Abh,
    const hf* __restrict__ Bh,
    const float* __restrict__ bias, float* __restrict__ C,
    hf* __restrict__ Ch)
{
    const uint32_t sb = smem_u32(dynsm);
    const int tid = threadIdx.x;
    const int m0 = blockIdx.y * 128, n0 = blockIdx.x * 128;
    const int lane = tid & 31, w = tid >> 5;
    const int wm = w >> 2, wn = w & 3;
    const int lr = lane & 15, lcb = (lane >> 4) * 16;

    float acc[4][4][4];
#pragma unroll
    for (int i = 0; i < 4; i++)
#pragma unroll
        for (int j = 0; j < 4; j++)
#pragma unroll
            for (int r = 0; r < 4; r++) acc[i][j][r] = 0.f;

    uint32_t aoff[4], boff[2];
#pragma unroll
    for (int i = 0; i < 4; i++)
        aoff[i] = (uint32_t)((wm * 64 + i * 16 + lr) * 80) + lcb;
#pragma unroll
    for (int hlf = 0; hlf < 2; hlf++)
        boff[hlf] = (uint32_t)((wn * 32 + hlf * 16 + lr) * 80) + lcb;

    const int a_row = tid >> 1, a_chb = (tid & 1) * 4;
    float4 areg[4];
    auto ldgA = [&](int s) {
#pragma unroll
        for (int i = 0; i < 4; i++)
            areg[i] = *(const float4*)&A32[(size_t)(m0 + a_row) * 1024 + s * BK + (a_chb + i) * 4];
    };
    auto cvtA = [&](int buf) {
        char* ph = dynsm + (size_t)(buf * 2 + 0) * TILE_B;
#pragma unroll
        for (int i = 0; i < 4; i++) {
            float4 v = areg[i];
            uint32_t off = (uint32_t)(a_row * 80 + (a_chb + i) * 8);
            *(uint2*)(ph + off) = make_uint2(pk_h(v.x, v.y), pk_h(v.z, v.w));
        }
    };
    auto cpStage = [&](int s) {
        const int buf = s & 1, k0 = s * BK;
        if (ASPLIT == 0) {
            uint32_t sbase = sb + (uint32_t)(buf * 2 + 0) * TILE_B;
#pragma unroll
            for (int i = 0; i < 2; i++) {
                int idx = tid + 256 * i, row = idx >> 2, ch = idx & 3;
                CP_ASYNC16(sbase + (uint32_t)(row * 80 + ch * 16),
                           Abh + (size_t)(m0 + row) * 1024 + k0 + ch * 8);
            }
        }
        {
            uint32_t sbase = sb + (uint32_t)(buf * 2 + 1) * TILE_B;
#pragma unroll
            for (int i = 0; i < 2; i++) {
                int idx = tid + 256 * i, row = idx >> 2, ch = idx & 3;
                CP_ASYNC16(sbase + (uint32_t)(row * 80 + ch * 16),
                           Bh + (size_t)(n0 + row) * 1024 + k0 + ch * 8);
            }
        }
        CP_COMMIT();
    };

    if (ASPLIT) ldgA(0);
    cpStage(0);
    if (ASPLIT) cvtA(0);

    for (int s = 0; s < 32; s++) {
        if (s < 31) {
            if (ASPLIT) ldgA(s + 1);
            cpStage(s + 1);
            CP_WAIT(1);
        } else CP_WAIT(0);
        __syncthreads();

        const uint32_t base = sb + (uint32_t)(s & 1) * 2 * TILE_B;
#pragma unroll
        for (int kk = 0; kk < 2; kk++) {
            const uint32_t kb = kk * 32;
            uint32_t ah[4][4];
#pragma unroll
            for (int i = 0; i < 4; i++)
                LDSM4(ah[i], base + aoff[i] + kb);
            uint32_t bh[4][2];
#pragma unroll
            for (int hlf = 0; hlf < 2; hlf++) {
                uint32_t r[4];
                LDSM4(r, base + TILE_B + boff[hlf] + kb);
                bh[2*hlf][0] = r[0]; bh[2*hlf+1][0] = r[1];
                bh[2*hlf][1] = r[2]; bh[2*hlf+1][1] = r[3];
            }
#pragma unroll
            for (int i = 0; i < 4; i++)
#pragma unroll
                for (int j = 0; j < 4; j++) mma_f16(acc[i][j], ah[i], bh[j]);
        }
        __syncthreads();
        if (ASPLIT && s < 31) cvtA((s + 1) & 1);
    }

#pragma unroll
    for (int i = 0; i < 4; i++)
#pragma unroll
        for (int j = 0; j < 4; j++) {
            int row = m0 + wm * 64 + i * 16 + (lane >> 2);
            int col = n0 + wn * 32 + j * 8 + (lane & 3) * 2;
            float b0 = bias[col], b1 = bias[col + 1];
            float v00 = acc[i][j][0] + b0, v01 = acc[i][j][1] + b1;
            float v10 = acc[i][j][2] + b0, v11 = acc[i][j][3] + b1;
            if (MODE == 0) {
                *(float2*)&C[(size_t)row * 1024 + col] = make_float2(v00, v01);
                *(float2*)&C[(size_t)(row + 8) * 1024 + col] = make_float2(v10, v11);
            } else {
                int h = col >> 6, e = col & 63;
                int b = row >> 10, sI = row & 1023;
                size_t o0 = (((size_t)(b * 16 + h) * 1024 + sI) << 6) + e;
                size_t o1 = o0 + (8 << 6);
                *(uint32_t*)&Ch[o0] = pk_h(v00, v01);
                *(uint32_t*)&Ch[o1] = pk_h(v10, v11);
            }
        }
}

__global__ __launch_bounds__(256) void gemm_proj(
    const float* q, const float* k, const float* v,
    const hf* Wh,
    const float* bq, const float* bk, const float* bv,
    hf* Qh, hf* Kh, hf* Vh)
{
    extern __shared__ __align__(128) char dynsm[];
    int z = blockIdx.z;
    const float* A = z == 0 ? q : (z == 1 ? k : v);
    const float* bias = z == 0 ? bq : (z == 1 ? bk : bv);
    hf* Ch = z == 0 ? Qh : (z == 1 ? Kh : Vh);
    gemm_body<1, 1>(dynsm, A, nullptr, Wh + (size_t)z * 1048576,
                    bias, nullptr, Ch);
}

__global__ __launch_bounds__(256) void gemm_fc(
    const hf* Abh, const hf* Bh, const float* bias, float* C)
{
    extern __shared__ __align__(128) char dynsm[];
    gemm_body<0, 0>(dynsm, nullptr, Abh, Bh, bias, C, nullptr);
}

// =================================================================
// HMMA fused attention — all-fp16-single (unchanged from R12).
// =================================================================
#define AQH 0
#define AKH 9216
#define AVH 18432
#define APH 27648
#define ARB 36864
#define AW  41088
#define ARK 49536
#define ARV 57984
#define ALP 66432
#define AWP 66944
#define AL_ 67456
#define ATT_SMEM 67712

__global__ __launch_bounds__(256, 2) void attn_hmma(
    const hf* __restrict__ Qh,
    const hf* __restrict__ Kh, const hf* __restrict__ Vh,
    const float* __restrict__ relk, const float* __restrict__ relv,
    hf* __restrict__ Oh)
{
    extern __shared__ __align__(128) char sm[];
    const uint32_t sb = smem_u32(sm);
    const int tid = threadIdx.x;
    const int lane = tid & 31, w = tid >> 5;
    const int q0 = blockIdx.x * 64;
    const size_t base = (size_t)(blockIdx.z * NH + blockIdx.y) * (NS * NDH);
    const int lr = lane & 15, hc = (lane >> 4) * 16;
    float* sW = (float*)(sm + AW);
    float* sRK = (float*)(sm + ARK);
    float* sRV = (float*)(sm + ARV);
    float* sLp = (float*)(sm + ALP);
    float* sWp = (float*)(sm + AWP);
    float* sL = (float*)(sm + AL_);

    auto ldTile = [&](uint32_t dst, const hf* g, int t) {
#pragma unroll
        for (int i = 0; i < 2; i++) {
            int idx = tid + 256 * i, row = idx >> 3, ch = idx & 7;
            size_t go = base + (size_t)(t * 64 + row) * 64 + ch * 8;
            CP_ASYNC16(sb + dst + (uint32_t)(row * 144 + ch * 16), g + go);
        }
        CP_COMMIT();
    };

    {
#pragma unroll
        for (int i = 0; i < 2; i++) {
            int idx = tid + 256 * i, row = idx >> 3, ch = idx & 7;
            size_t go = base + (size_t)(q0 + row) * 64 + ch * 8;
            CP_ASYNC16(sb + AQH + (uint32_t)(row * 144 + ch * 16), Qh + go);
        }
        CP_COMMIT();
    }
    ldTile(AKH, Kh, 0);
    ldTile(AVH, Vh, 0);

    for (int i = tid; i < 33 * 64; i += 256) { sRK[i] = relk[i]; sRV[i] = relv[i]; }
    for (int i = tid; i < 64 * 33; i += 256) sW[i] = 0.f;

    CP_WAIT(2);
    __syncthreads();

    // r[q][d] = (q . relk[d]) * C2A
    {
        int q = tid >> 2;
        int part = tid & 3;
        int d0 = part * 8, nd = (part == 3) ? 9 : 8;
        float qv[64];
#pragma unroll
        for (int e2 = 0; e2 < 32; e2++) {
            uint32_t hv = *(uint32_t*)(sm + AQH + q * 144 + e2 * 4);
            float2 fh = __half22float2(*(__half2*)&hv);
            qv[2 * e2] = fh.x;
            qv[2 * e2 + 1] = fh.y;
        }
        for (int d = d0; d < d0 + nd; d++) {
            float s = 0.f;
#pragma unroll
            for (int e = 0; e < 64; e++) s += qv[e] * sRK[d * 64 + e];
            *(hf*)(sm + ARB + (q * 33 + d) * 2) = __float2half_rn(s * C2A);
        }
    }
    __syncthreads();

    const int wm = w >> 1, wn = w & 1;
    float acc2[4][4];
#pragma unroll
    for (int j = 0; j < 4; j++)
#pragma unroll
        for (int r = 0; r < 4; r++) acc2[j][r] = 0.f;
    float lsum[2] = {0.f, 0.f};
    float wsuf[2] = {0.f, 0.f};

    for (int t = 0; t < 16; t++) {
        CP_WAIT(1);
        __syncthreads();

        // ---- QK phase ----
        float acc[4][4];
#pragma unroll
        for (int j = 0; j < 4; j++)
#pragma unroll
            for (int r = 0; r < 4; r++) acc[j][r] = 0.f;
#pragma unroll
        for (int es = 0; es < 4; es++) {
            uint32_t ah[4];
            LDSM4(ah, sb + AQH + (uint32_t)((wm * 16 + lr) * 144) + hc + es * 32);
            uint32_t bh[4][2];
#pragma unroll
            for (int c = 0; c < 2; c++) {
                uint32_t bo = (uint32_t)((wn * 32 + c * 16 + lr) * 144) + hc + es * 32;
                uint32_t r[4];
                LDSM4(r, sb + AKH + bo);
                bh[2*c][0] = r[0]; bh[2*c+1][0] = r[1];
                bh[2*c][1] = r[2]; bh[2*c+1][1] = r[3];
            }
#pragma unroll
            for (int j = 0; j < 4; j++) mma_f16(acc[j], ah, bh[j]);
        }
        __syncthreads();
        if (t < 15) ldTile(AKH, Kh, t + 1);

        // ---- softmax epilogue -> P (fp16) ----
        const int k0 = t * 64;
        const int X = blockIdx.x;
        const int cls = (t + 2 <= X) ? 0 : ((t >= X + 2) ? 2 : 1);
        if (cls != 1) {
            float rbv[2];
#pragma unroll
            for (int rh = 0; rh < 2; rh++) {
                int rr = wm * 16 + (lane >> 2) + rh * 8;
                rbv[rh] = __half2float(
                    *(hf*)(sm + ARB + (rr * 33 + (cls == 2 ? 32 : 0)) * 2));
            }
#pragma unroll
            for (int j = 0; j < 4; j++) {
                int col = wn * 32 + j * 8 + (lane & 3) * 2;
#pragma unroll
                for (int rh = 0; rh < 2; rh++) {
                    int rr = wm * 16 + (lane >> 2) + rh * 8;
                    float p0 = exp2f(fmaf(acc[j][rh * 2 + 0], C2A, rbv[rh]));
                    float p1 = exp2f(fmaf(acc[j][rh * 2 + 1], C2A, rbv[rh]));
                    lsum[rh] += p0 + p1;
                    if (cls == 2) wsuf[rh] += p0 + p1;
                    *(uint32_t*)(sm + APH + (uint32_t)(rr * 144 + col * 2)) = pk_h(p0, p1);
                }
            }
        } else {
#pragma unroll
            for (int j = 0; j < 4; j++) {
                int col = wn * 32 + j * 8 + (lane & 3) * 2;
#pragma unroll
                for (int rh = 0; rh < 2; rh++) {
                    int rr = wm * 16 + (lane >> 2) + rh * 8;
                    int qg = q0 + rr;
                    float p01[2];
#pragma unroll
                    for (int v = 0; v < 2; v++) {
                        int kg = k0 + col + v;
                        int dd = kg - qg;
                        int dc = dd < -16 ? -16 : (dd > 16 ? 16 : dd);
                        float rb = __half2float(
                            *(hf*)(sm + ARB + (rr * 33 + dc + 16) * 2));
                        float p = exp2f(fmaf(acc[j][rh * 2 + v], C2A, rb));
                        p01[v] = p;
                        lsum[rh] += p;
                        if (dd >= 16) wsuf[rh] += p;
                        else if (dd > -16) sW[rr * 33 + dd + 16] = p;
                    }
                    *(uint32_t*)(sm + APH + (uint32_t)(rr * 144 + col * 2)) =
                        pk_h(p01[0], p01[1]);
                }
            }
        }
        if (t < 15) { CP_WAIT(1); } else { CP_WAIT(0); }
        __syncthreads();

        // ---- PV phase ----
#pragma unroll
        for (int ks = 0; ks < 4; ks++) {
            uint32_t ph[4];
            LDSM4(ph, sb + APH + (uint32_t)((wm * 16 + lr) * 144) + ks * 32 + hc);
            uint32_t vh[4][2];
#pragma unroll
            for (int c = 0; c < 2; c++) {
                int cg = wn * 2 + c;
                uint32_t vo = (uint32_t)((ks * 16 + lr) * 144) + (cg * 2 + (lane >> 4)) * 16;
                uint32_t r[4];
                LDSM4T(r, sb + AVH + vo);
                vh[2*c][0] = r[0]; vh[2*c][1] = r[1];
                vh[2*c+1][0] = r[2]; vh[2*c+1][1] = r[3];
            }
#pragma unroll
            for (int nf = 0; nf < 4; nf++) mma_f16(acc2[nf], ph, vh[nf]);
        }
        __syncthreads();
        if (t < 15) ldTile(AVH, Vh, t + 1);
    }

    // ---- deterministic l / w32 reduction ----
#pragma unroll
    for (int i = 0; i < 2; i++) {
        lsum[i] += __shfl_xor_sync(0xffffffffu, lsum[i], 1);
        lsum[i] += __shfl_xor_sync(0xffffffffu, lsum[i], 2);
        wsuf[i] += __shfl_xor_sync(0xffffffffu, wsuf[i], 1);
        wsuf[i] += __shfl_xor_sync(0xffffffffu, wsuf[i], 2);
    }
    if ((lane & 3) == 0) {
#pragma unroll
        for (int rh = 0; rh < 2; rh++) {
            int row = wm * 16 + rh * 8 + (lane >> 2);
            sLp[row * 2 + wn] = lsum[rh];
            sWp[row * 2 + wn] = wsuf[rh];
        }
    }
    __syncthreads();
    if (tid < 64) {
        int r = tid;
        float l = sLp[r * 2] + sLp[r * 2 + 1];
        float ws = sWp[r * 2] + sWp[r * 2 + 1];
        float mid = 0.f;
#pragma unroll
        for (int d = 1; d < 32; d++) mid += sW[r * 33 + d];
        sW[r * 33 + 0] = l - ws - mid;
        sW[r * 33 + 32] = ws;
        sL[r] = 1.f / l;
    }
    __syncthreads();

    // ---- rel_v bias + normalize + store O ----
#pragma unroll
    for (int nf = 0; nf < 4; nf++) {
        int row0 = wm * 16 + (lane >> 2), row1 = row0 + 8;
        int col = wn * 32 + nf * 8 + (lane & 3) * 2;
        float b00 = 0.f, b01 = 0.f, b10 = 0.f, b11 = 0.f;
#pragma unroll
        for (int d = 0; d < 33; d++) {
            float w0v = sW[row0 * 33 + d], w1v = sW[row1 * 33 + d];
            float r0 = sRV[d * 64 + col], r1 = sRV[d * 64 + col + 1];
            b00 += w0v * r0; b01 += w0v * r1;
            b10 += w1v * r0; b11 += w1v * r1;
        }
        float il0 = sL[row0], il1 = sL[row1];
        float o00 = (acc2[nf][0] + b00) * il0, o01 = (acc2[nf][1] + b01) * il0;
        float o10 = (acc2[nf][2] + b10) * il1, o11 = (acc2[nf][3] + b11) * il1;
        size_t g0 = ((size_t)(blockIdx.z * 1024 + q0 + row0)) * 1024 + blockIdx.y * 64 + col;
        size_t g1 = ((size_t)(blockIdx.z * 1024 + q0 + row1)) * 1024 + blockIdx.y * 64 + col;
        *(uint32_t*)&Oh[g0] = pk_h(o00, o01);
        *(uint32_t*)&Oh[g1] = pk_h(o10, o11);
    }
}

// =================================================================
extern "C" void kernel_launch(void* const* d_in, const int* in_sizes, int n_in,
                              void* d_out, int out_size)
{
    const float* query = (const float*)d_in[0];
    const float* key   = (const float*)d_in[1];
    const float* value = (const float*)d_in[2];
    const float* Wq    = (const float*)d_in[3];
    const float* bq    = (const float*)d_in[4];
    const float* Wk    = (const float*)d_in[5];
    const float* bk    = (const float*)d_in[6];
    const float* Wv    = (const float*)d_in[7];
    const float* bv    = (const float*)d_in[8];
    const float* relk  = (const float*)d_in[9];
    const float* relv  = (const float*)d_in[10];
    const float* fcW   = (const float*)d_in[11];
    const float* fcb   = (const float*)d_in[12];
    float* out = (float*)d_out;

    hf *Qh, *Kh, *Vh, *Oh, *Wh, *Bh;
    cudaGetSymbolAddress((void**)&Qh, g_Qh);
    cudaGetSymbolAddress((void**)&Kh, g_Kh);
    cudaGetSymbolAddress((void**)&Vh, g_Vh);
    cudaGetSymbolAddress((void**)&Oh, g_Oh);
    cudaGetSymbolAddress((void**)&Wh, g_Wh);
    cudaGetSymbolAddress((void**)&Bh, g_Bh);

    cudaFuncSetAttribute(gemm_proj, cudaFuncAttributeMaxDynamicSharedMemorySize, GH_SMEM);
    cudaFuncSetAttribute(gemm_fc, cudaFuncAttributeMaxDynamicSharedMemorySize, GH_SMEM);
    cudaFuncSetAttribute(attn_hmma, cudaFuncAttributeMaxDynamicSharedMemorySize, ATT_SMEM);

    cvtW3<<<dim3(32, 32, 3), 256>>>(Wq, Wk, Wv, Wh);
    cvt_f32<<<1024, 256>>>(fcW, Bh, 1024 * 1024);

    gemm_proj<<<dim3(8, 32, 3), 256, GH_SMEM>>>(query, key, value, Wh,
                                                bq, bk, bv, Qh, Kh, Vh);

    attn_hmma<<<dim3(16, NH, NB), 256, ATT_SMEM>>>(Qh, Kh, Vh, relk, relv, Oh);

    gemm_fc<<<dim3(8, 32), 256, GH_SMEM>>>(Oh, Bh, fcb, out);
}

// round 14
// speedup vs baseline: 1.9870x; 1.0112x over previous
#include <cuda_runtime.h>
#include <cuda_fp16.h>
#include <cstdint>

#define NB 4
#define NS 1024
#define NH 16
#define NDH 64
#define C2A 0.18033688f   // ATT_SCALE * log2(e)
typedef __half hf;

// ---------------- scratch ----------------
__device__ hf g_Qh[NB * NH * NS * NDH];
__device__ hf g_Kh[NB * NH * NS * NDH];
__device__ hf g_Vh[NB * NH * NS * NDH];
__device__ hf g_Oh[4096 * 1024];
__device__ hf g_Wh[3 * 1024 * 1024];
__device__ hf g_Bh[1024 * 1024];

// ---------------- helpers ----------------
__device__ __forceinline__ uint32_t smem_u32(const void* p) {
    uint32_t a;
    asm("{ .reg .u64 t; cvta.to.shared.u64 t, %1; cvt.u32.u64 %0, t; }"
        : "=r"(a) : "l"(p));
    return a;
}
#define CP_ASYNC16(sp, gp) \
    asm volatile("cp.async.cg.shared.global [%0], [%1], 16;" :: "r"(sp), "l"(gp) : "memory")
#define CP_COMMIT() asm volatile("cp.async.commit_group;" ::: "memory")
#define CP_WAIT(n)  asm volatile("cp.async.wait_group %0;" :: "n"(n) : "memory")
#define LDSM4(r, a) \
    asm volatile("ldmatrix.sync.aligned.m8n8.x4.shared.b16 {%0,%1,%2,%3}, [%4];" \
                 : "=r"((r)[0]), "=r"((r)[1]), "=r"((r)[2]), "=r"((r)[3]) : "r"(a))
#define LDSM4T(r, a) \
    asm volatile("ldmatrix.sync.aligned.m8n8.x4.trans.shared.b16 {%0,%1,%2,%3}, [%4];" \
                 : "=r"((r)[0]), "=r"((r)[1]), "=r"((r)[2]), "=r"((r)[3]) : "r"(a))

__device__ __forceinline__ void mma_f16(float* d, const uint32_t* a, const uint32_t* b) {
    asm volatile(
        "mma.sync.aligned.m16n8k16.row.col.f32.f16.f16.f32 "
        "{%0,%1,%2,%3},{%4,%5,%6,%7},{%8,%9},{%0,%1,%2,%3};"
        : "+f"(d[0]), "+f"(d[1]), "+f"(d[2]), "+f"(d[3])
        : "r"(a[0]), "r"(a[1]), "r"(a[2]), "r"(a[3]), "r"(b[0]), "r"(b[1]));
}
__device__ __forceinline__ uint32_t pk_h(float a, float b) {
    __half2 t = __floats2half2_rn(a, b);
    return *(uint32_t*)&t;
}
__device__ __forceinline__ uint32_t ex2_f16x2(uint32_t x) {
    uint32_t r;
    asm("ex2.approx.f16x2 %0, %1;" : "=r"(r) : "r"(x));
    return r;
}

// ---------------- prep kernels (fp16) ----------------
__global__ __launch_bounds__(256) void cvt_f32(
    const float* __restrict__ A, hf* __restrict__ H, int n)
{
    int i = (blockIdx.x * 256 + threadIdx.x) * 4;
    if (i >= n) return;
    float4 v = *(const float4*)&A[i];
    uint2 o = make_uint2(pk_h(v.x, v.y), pk_h(v.z, v.w));
    *(uint2*)&H[i] = o;
}

__global__ __launch_bounds__(256) void cvtW3(
    const float* __restrict__ Wq, const float* __restrict__ Wk,
    const float* __restrict__ Wv, hf* __restrict__ Ht)
{
    const float* W = blockIdx.z == 0 ? Wq : (blockIdx.z == 1 ? Wk : Wv);
    hf* H = Ht + (size_t)blockIdx.z * 1048576;
    __shared__ float t[32][33];
    const int k0 = blockIdx.x * 32, n0 = blockIdx.y * 32;
    const int h = n0 >> 6, e0 = n0 & 63;
    const int x = threadIdx.x & 31, y = threadIdx.x >> 5;
#pragma unroll
    for (int j = 0; j < 32; j += 8)
        t[y + j][x] = W[h * 65536 + (k0 + y + j) * 64 + e0 + x];
    __syncthreads();
#pragma unroll
    for (int j = 0; j < 32; j += 8)
        H[(size_t)(n0 + y + j) * 1024 + k0 + x] = __float2half_rn(t[x][y + j]);
}

// =================================================================
// HMMA GEMM body — fp16 single precision, 1 MMA pass (unchanged R13)
// =================================================================
#define BK 32
#define TILE_B (128 * 80)
#define GH_SMEM (4 * TILE_B)

template <int ASPLIT, int MODE>
__device__ __forceinline__ void gemm_body(
    char* dynsm,
    const float* __restrict__ A32, const hf* __restrict__ Abh,
    const hf* __restrict__ Bh,
    const float* __restrict__ bias, float* __restrict__ C,
    hf* __restrict__ Ch)
{
    const uint32_t sb = smem_u32(dynsm);
    const int tid = threadIdx.x;
    const int m0 = blockIdx.y * 128, n0 = blockIdx.x * 128;
    const int lane = tid & 31, w = tid >> 5;
    const int wm = w >> 2, wn = w & 3;
    const int lr = lane & 15, lcb = (lane >> 4) * 16;

    float acc[4][4][4];
#pragma unroll
    for (int i = 0; i < 4; i++)
#pragma unroll
        for (int j = 0; j < 4; j++)
#pragma unroll
            for (int r = 0; r < 4; r++) acc[i][j][r] = 0.f;

    uint32_t aoff[4], boff[2];
#pragma unroll
    for (int i = 0; i < 4; i++)
        aoff[i] = (uint32_t)((wm * 64 + i * 16 + lr) * 80) + lcb;
#pragma unroll
    for (int hlf = 0; hlf < 2; hlf++)
        boff[hlf] = (uint32_t)((wn * 32 + hlf * 16 + lr) * 80) + lcb;

    const int a_row = tid >> 1, a_chb = (tid & 1) * 4;
    float4 areg[4];
    auto ldgA = [&](int s) {
#pragma unroll
        for (int i = 0; i < 4; i++)
            areg[i] = *(const float4*)&A32[(size_t)(m0 + a_row) * 1024 + s * BK + (a_chb + i) * 4];
    };
    auto cvtA = [&](int buf) {
        char* ph = dynsm + (size_t)(buf * 2 + 0) * TILE_B;
#pragma unroll
        for (int i = 0; i < 4; i++) {
            float4 v = areg[i];
            uint32_t off = (uint32_t)(a_row * 80 + (a_chb + i) * 8);
            *(uint2*)(ph + off) = make_uint2(pk_h(v.x, v.y), pk_h(v.z, v.w));
        }
    };
    auto cpStage = [&](int s) {
        const int buf = s & 1, k0 = s * BK;
        if (ASPLIT == 0) {
            uint32_t sbase = sb + (uint32_t)(buf * 2 + 0) * TILE_B;
#pragma unroll
            for (int i = 0; i < 2; i++) {
                int idx = tid + 256 * i, row = idx >> 2, ch = idx & 3;
                CP_ASYNC16(sbase + (uint32_t)(row * 80 + ch * 16),
                           Abh + (size_t)(m0 + row) * 1024 + k0 + ch * 8);
            }
        }
        {
            uint32_t sbase = sb + (uint32_t)(buf * 2 + 1) * TILE_B;
#pragma unroll
            for (int i = 0; i < 2; i++) {
                int idx = tid + 256 * i, row = idx >> 2, ch = idx & 3;
                CP_ASYNC16(sbase + (uint32_t)(row * 80 + ch * 16),
                           Bh + (size_t)(n0 + row) * 1024 + k0 + ch * 8);
            }
        }
        CP_COMMIT();
    };

    if (ASPLIT) ldgA(0);
    cpStage(0);
    if (ASPLIT) cvtA(0);

    for (int s = 0; s < 32; s++) {
        if (s < 31) {
            if (ASPLIT) ldgA(s + 1);
            cpStage(s + 1);
            CP_WAIT(1);
        } else CP_WAIT(0);
        __syncthreads();

        const uint32_t base = sb + (uint32_t)(s & 1) * 2 * TILE_B;
#pragma unroll
        for (int kk = 0; kk < 2; kk++) {
            const uint32_t kb = kk * 32;
            uint32_t ah[4][4];
#pragma unroll
            for (int i = 0; i < 4; i++)
                LDSM4(ah[i], base + aoff[i] + kb);
            uint32_t bh[4][2];
#pragma unroll
            for (int hlf = 0; hlf < 2; hlf++) {
                uint32_t r[4];
                LDSM4(r, base + TILE_B + boff[hlf] + kb);
                bh[2*hlf][0] = r[0]; bh[2*hlf+1][0] = r[1];
                bh[2*hlf][1] = r[2]; bh[2*hlf+1][1] = r[3];
            }
#pragma unroll
            for (int i = 0; i < 4; i++)
#pragma unroll
                for (int j = 0; j < 4; j++) mma_f16(acc[i][j], ah[i], bh[j]);
        }
        __syncthreads();
        if (ASPLIT && s < 31) cvtA((s + 1) & 1);
    }

#pragma unroll
    for (int i = 0; i < 4; i++)
#pragma unroll
        for (int j = 0; j < 4; j++) {
            int row = m0 + wm * 64 + i * 16 + (lane >> 2);
            int col = n0 + wn * 32 + j * 8 + (lane & 3) * 2;
            float b0 = bias[col], b1 = bias[col + 1];
            float v00 = acc[i][j][0] + b0, v01 = acc[i][j][1] + b1;
            float v10 = acc[i][j][2] + b0, v11 = acc[i][j][3] + b1;
            if (MODE == 0) {
                *(float2*)&C[(size_t)row * 1024 + col] = make_float2(v00, v01);
                *(float2*)&C[(size_t)(row + 8) * 1024 + col] = make_float2(v10, v11);
            } else {
                int h = col >> 6, e = col & 63;
                int b = row >> 10, sI = row & 1023;
                size_t o0 = (((size_t)(b * 16 + h) * 1024 + sI) << 6) + e;
                size_t o1 = o0 + (8 << 6);
                *(uint32_t*)&Ch[o0] = pk_h(v00, v01);
                *(uint32_t*)&Ch[o1] = pk_h(v10, v11);
            }
        }
}

__global__ __launch_bounds__(256) void gemm_proj(
    const float* q, const float* k, const float* v,
    const hf* Wh,
    const float* bq, const float* bk, const float* bv,
    hf* Qh, hf* Kh, hf* Vh)
{
    extern __shared__ __align__(128) char dynsm[];
    int z = blockIdx.z;
    const float* A = z == 0 ? q : (z == 1 ? k : v);
    const float* bias = z == 0 ? bq : (z == 1 ? bk : bv);
    hf* Ch = z == 0 ? Qh : (z == 1 ? Kh : Vh);
    gemm_body<1, 1>(dynsm, A, nullptr, Wh + (size_t)z * 1048576,
                    bias, nullptr, Ch);
}

__global__ __launch_bounds__(256) void gemm_fc(
    const hf* Abh, const hf* Bh, const float* bias, float* C)
{
    extern __shared__ __align__(128) char dynsm[];
    gemm_body<0, 0>(dynsm, nullptr, Abh, Bh, bias, C, nullptr);
}

// =================================================================
// HMMA fused attention — fp16 single; f16x2 exp in uniform tiles.
// =================================================================
#define AQH 0
#define AKH 9216
#define AVH 18432
#define APH 27648
#define ARB 36864
#define AW  41088
#define ARK 49536
#define ARV 57984
#define ALP 66432
#define AWP 66944
#define AL_ 67456
#define ATT_SMEM 67712

__global__ __launch_bounds__(256, 2) void attn_hmma(
    const hf* __restrict__ Qh,
    const hf* __restrict__ Kh, const hf* __restrict__ Vh,
    const float* __restrict__ relk, const float* __restrict__ relv,
    hf* __restrict__ Oh)
{
    extern __shared__ __align__(128) char sm[];
    const uint32_t sb = smem_u32(sm);
    const int tid = threadIdx.x;
    const int lane = tid & 31, w = tid >> 5;
    const int q0 = blockIdx.x * 64;
    const size_t base = (size_t)(blockIdx.z * NH + blockIdx.y) * (NS * NDH);
    const int lr = lane & 15, hc = (lane >> 4) * 16;
    float* sW = (float*)(sm + AW);
    float* sRK = (float*)(sm + ARK);
    float* sRV = (float*)(sm + ARV);
    float* sLp = (float*)(sm + ALP);
    float* sWp = (float*)(sm + AWP);
    float* sL = (float*)(sm + AL_);

    auto ldTile = [&](uint32_t dst, const hf* g, int t) {
#pragma unroll
        for (int i = 0; i < 2; i++) {
            int idx = tid + 256 * i, row = idx >> 3, ch = idx & 7;
            size_t go = base + (size_t)(t * 64 + row) * 64 + ch * 8;
            CP_ASYNC16(sb + dst + (uint32_t)(row * 144 + ch * 16), g + go);
        }
        CP_COMMIT();
    };

    {
#pragma unroll
        for (int i = 0; i < 2; i++) {
            int idx = tid + 256 * i, row = idx >> 3, ch = idx & 7;
            size_t go = base + (size_t)(q0 + row) * 64 + ch * 8;
            CP_ASYNC16(sb + AQH + (uint32_t)(row * 144 + ch * 16), Qh + go);
        }
        CP_COMMIT();
    }
    ldTile(AKH, Kh, 0);
    ldTile(AVH, Vh, 0);

    for (int i = tid; i < 33 * 64; i += 256) { sRK[i] = relk[i]; sRV[i] = relv[i]; }
    for (int i = tid; i < 64 * 33; i += 256) sW[i] = 0.f;

    CP_WAIT(2);
    __syncthreads();

    // r[q][d] = (q . relk[d]) * C2A
    {
        int q = tid >> 2;
        int part = tid & 3;
        int d0 = part * 8, nd = (part == 3) ? 9 : 8;
        float qv[64];
#pragma unroll
        for (int e2 = 0; e2 < 32; e2++) {
            uint32_t hv = *(uint32_t*)(sm + AQH + q * 144 + e2 * 4);
            float2 fh = __half22float2(*(__half2*)&hv);
            qv[2 * e2] = fh.x;
            qv[2 * e2 + 1] = fh.y;
        }
        for (int d = d0; d < d0 + nd; d++) {
            float s = 0.f;
#pragma unroll
            for (int e = 0; e < 64; e++) s += qv[e] * sRK[d * 64 + e];
            *(hf*)(sm + ARB + (q * 33 + d) * 2) = __float2half_rn(s * C2A);
        }
    }
    __syncthreads();

    const int wm = w >> 1, wn = w & 1;
    float acc2[4][4];
#pragma unroll
    for (int j = 0; j < 4; j++)
#pragma unroll
        for (int r = 0; r < 4; r++) acc2[j][r] = 0.f;
    float lsum[2] = {0.f, 0.f};
    float wsuf[2] = {0.f, 0.f};

    for (int t = 0; t < 16; t++) {
        CP_WAIT(1);
        __syncthreads();

        // ---- QK phase ----
        float acc[4][4];
#pragma unroll
        for (int j = 0; j < 4; j++)
#pragma unroll
            for (int r = 0; r < 4; r++) acc[j][r] = 0.f;
#pragma unroll
        for (int es = 0; es < 4; es++) {
            uint32_t ah[4];
            LDSM4(ah, sb + AQH + (uint32_t)((wm * 16 + lr) * 144) + hc + es * 32);
            uint32_t bh[4][2];
#pragma unroll
            for (int c = 0; c < 2; c++) {
                uint32_t bo = (uint32_t)((wn * 32 + c * 16 + lr) * 144) + hc + es * 32;
                uint32_t r[4];
                LDSM4(r, sb + AKH + bo);
                bh[2*c][0] = r[0]; bh[2*c+1][0] = r[1];
                bh[2*c][1] = r[2]; bh[2*c+1][1] = r[3];
            }
#pragma unroll
            for (int j = 0; j < 4; j++) mma_f16(acc[j], ah, bh[j]);
        }
        __syncthreads();
        if (t < 15) ldTile(AKH, Kh, t + 1);

        // ---- softmax epilogue -> P (fp16) ----
        const int k0 = t * 64;
        const int X = blockIdx.x;
        const int cls = (t + 2 <= X) ? 0 : ((t >= X + 2) ? 2 : 1);
        if (cls != 1) {
            float rbv[2];
#pragma unroll
            for (int rh = 0; rh < 2; rh++) {
                int rr = wm * 16 + (lane >> 2) + rh * 8;
                rbv[rh] = __half2float(
                    *(hf*)(sm + ARB + (rr * 33 + (cls == 2 ? 32 : 0)) * 2));
            }
            __half2 hs[2];
            hs[0] = __floats2half2_rn(0.f, 0.f);
            hs[1] = __floats2half2_rn(0.f, 0.f);
#pragma unroll
            for (int j = 0; j < 4; j++) {
                int col = wn * 32 + j * 8 + (lane & 3) * 2;
#pragma unroll
                for (int rh = 0; rh < 2; rh++) {
                    int rr = wm * 16 + (lane >> 2) + rh * 8;
                    float f0 = fmaf(acc[j][rh * 2 + 0], C2A, rbv[rh]);
                    float f1 = fmaf(acc[j][rh * 2 + 1], C2A, rbv[rh]);
                    uint32_t p01 = ex2_f16x2(pk_h(f0, f1));
                    *(uint32_t*)(sm + APH + (uint32_t)(rr * 144 + col * 2)) = p01;
                    hs[rh] = __hadd2(hs[rh], *(__half2*)&p01);
                }
            }
#pragma unroll
            for (int rh = 0; rh < 2; rh++) {
                float2 tf = __half22float2(hs[rh]);
                float ts = tf.x + tf.y;
                lsum[rh] += ts;
                if (cls == 2) wsuf[rh] += ts;
            }
        } else {
#pragma unroll
            for (int j = 0; j < 4; j++) {
                int col = wn * 32 + j * 8 + (lane & 3) * 2;
#pragma unroll
                for (int rh = 0; rh < 2; rh++) {
                    int rr = wm * 16 + (lane >> 2) + rh * 8;
                    int qg = q0 + rr;
                    float p01[2];
#pragma unroll
                    for (int v = 0; v < 2; v++) {
                        int kg = k0 + col + v;
                        int dd = kg - qg;
                        int dc = dd < -16 ? -16 : (dd > 16 ? 16 : dd);
                        float rb = __half2float(
                            *(hf*)(sm + ARB + (rr * 33 + dc + 16) * 2));
                        float p = exp2f(fmaf(acc[j][rh * 2 + v], C2A, rb));
                        p01[v] = p;
                        lsum[rh] += p;
                        if (dd >= 16) wsuf[rh] += p;
                        else if (dd > -16) sW[rr * 33 + dd + 16] = p;
                    }
                    *(uint32_t*)(sm + APH + (uint32_t)(rr * 144 + col * 2)) =
                        pk_h(p01[0], p01[1]);
                }
            }
        }
        if (t < 15) { CP_WAIT(1); } else { CP_WAIT(0); }
        __syncthreads();

        // ---- PV phase ----
#pragma unroll
        for (int ks = 0; ks < 4; ks++) {
            uint32_t ph[4];
            LDSM4(ph, sb + APH + (uint32_t)((wm * 16 + lr) * 144) + ks * 32 + hc);
            uint32_t vh[4][2];
#pragma unroll
            for (int c = 0; c < 2; c++) {
                int cg = wn * 2 + c;
                uint32_t vo = (uint32_t)((ks * 16 + lr) * 144) + (cg * 2 + (lane >> 4)) * 16;
                uint32_t r[4];
                LDSM4T(r, sb + AVH + vo);
                vh[2*c][0] = r[0]; vh[2*c][1] = r[1];
                vh[2*c+1][0] = r[2]; vh[2*c+1][1] = r[3];
            }
#pragma unroll
            for (int nf = 0; nf < 4; nf++) mma_f16(acc2[nf], ph, vh[nf]);
        }
        __syncthreads();
        if (t < 15) ldTile(AVH, Vh, t + 1);
    }

    // ---- deterministic l / w32 reduction ----
#pragma unroll
    for (int i = 0; i < 2; i++) {
        lsum[i] += __shfl_xor_sync(0xffffffffu, lsum[i], 1);
        lsum[i] += __shfl_xor_sync(0xffffffffu, lsum[i], 2);
        wsuf[i] += __shfl_xor_sync(0xffffffffu, wsuf[i], 1);
        wsuf[i] += __shfl_xor_sync(0xffffffffu, wsuf[i], 2);
    }
    if ((lane & 3) == 0) {
#pragma unroll
        for (int rh = 0; rh < 2; rh++) {
            int row = wm * 16 + rh * 8 + (lane >> 2);
            sLp[row * 2 + wn] = lsum[rh];
            sWp[row * 2 + wn] = wsuf[rh];
        }
    }
    __syncthreads();
    if (tid < 64) {
        int r = tid;
        float l = sLp[r * 2] + sLp[r * 2 + 1];
        float ws = sWp[r * 2] + sWp[r * 2 + 1];
        float mid = 0.f;
#pragma unroll
        for (int d = 1; d < 32; d++) mid += sW[r * 33 + d];
        sW[r * 33 + 0] = l - ws - mid;
        sW[r * 33 + 32] = ws;
        sL[r] = 1.f / l;
    }
    __syncthreads();

    // ---- rel_v bias + normalize + store O ----
#pragma unroll
    for (int nf = 0; nf < 4; nf++) {
        int row0 = wm * 16 + (lane >> 2), row1 = row0 + 8;
        int col = wn * 32 + nf * 8 + (lane & 3) * 2;
        float b00 = 0.f, b01 = 0.f, b10 = 0.f, b11 = 0.f;
#pragma unroll
        for (int d = 0; d < 33; d++) {
            float w0v = sW[row0 * 33 + d], w1v = sW[row1 * 33 + d];
            float r0 = sRV[d * 64 + col], r1 = sRV[d * 64 + col + 1];
            b00 += w0v * r0; b01 += w0v * r1;
            b10 += w1v * r0; b11 += w1v * r1;
        }
        float il0 = sL[row0], il1 = sL[row1];
        float o00 = (acc2[nf][0] + b00) * il0, o01 = (acc2[nf][1] + b01) * il0;
        float o10 = (acc2[nf][2] + b10) * il1, o11 = (acc2[nf][3] + b11) * il1;
        size_t g0 = ((size_t)(blockIdx.z * 1024 + q0 + row0)) * 1024 + blockIdx.y * 64 + col;
        size_t g1 = ((size_t)(blockIdx.z * 1024 + q0 + row1)) * 1024 + blockIdx.y * 64 + col;
        *(uint32_t*)&Oh[g0] = pk_h(o00, o01);
        *(uint32_t*)&Oh[g1] = pk_h(o10, o11);
    }
}

// =================================================================
extern "C" void kernel_launch(void* const* d_in, const int* in_sizes, int n_in,
                              void* d_out, int out_size)
{
    const float* query = (const float*)d_in[0];
    const float* key   = (const float*)d_in[1];
    const float* value = (const float*)d_in[2];
    const float* Wq    = (const float*)d_in[3];
    const float* bq    = (const float*)d_in[4];
    const float* Wk    = (const float*)d_in[5];
    const float* bk    = (const float*)d_in[6];
    const float* Wv    = (const float*)d_in[7];
    const float* bv    = (const float*)d_in[8];
    const float* relk  = (const float*)d_in[9];
    const float* relv  = (const float*)d_in[10];
    const float* fcW   = (const float*)d_in[11];
    const float* fcb   = (const float*)d_in[12];
    float* out = (float*)d_out;

    hf *Qh, *Kh, *Vh, *Oh, *Wh, *Bh;
    cudaGetSymbolAddress((void**)&Qh, g_Qh);
    cudaGetSymbolAddress((void**)&Kh, g_Kh);
    cudaGetSymbolAddress((void**)&Vh, g_Vh);
    cudaGetSymbolAddress((void**)&Oh, g_Oh);
    cudaGetSymbolAddress((void**)&Wh, g_Wh);
    cudaGetSymbolAddress((void**)&Bh, g_Bh);

    cudaFuncSetAttribute(gemm_proj, cudaFuncAttributeMaxDynamicSharedMemorySize, GH_SMEM);
    cudaFuncSetAttribute(gemm_fc, cudaFuncAttributeMaxDynamicSharedMemorySize, GH_SMEM);
    cudaFuncSetAttribute(attn_hmma, cudaFuncAttributeMaxDynamicSharedMemorySize, ATT_SMEM);

    cvtW3<<<dim3(32, 32, 3), 256>>>(Wq, Wk, Wv, Wh);
    cvt_f32<<<1024, 256>>>(fcW, Bh, 1024 * 1024);

    gemm_proj<<<dim3(8, 32, 3), 256, GH_SMEM>>>(query, key, value, Wh,
                                                bq, bk, bv, Qh, Kh, Vh);

    attn_hmma<<<dim3(16, NH, NB), 256, ATT_SMEM>>>(Qh, Kh, Vh, relk, relv, Oh);

    gemm_fc<<<dim3(8, 32), 256, GH_SMEM>>>(Oh, Bh, fcb, out);
}

// round 15
// speedup vs baseline: 2.0117x; 1.0125x over previous
#include <cuda_runtime.h>
#include <cuda_fp16.h>
#include <cstdint>

#define NB 4
#define NS 1024
#define NH 16
#define NDH 64
#define C2A 0.18033688f   // ATT_SCALE * log2(e)
typedef __half hf;

// ---------------- scratch ----------------
__device__ hf g_Qh[NB * NH * NS * NDH];
__device__ hf g_Kh[NB * NH * NS * NDH];
__device__ hf g_Vh[NB * NH * NS * NDH];
__device__ hf g_Oh[4096 * 1024];
__device__ hf g_Wh[3 * 1024 * 1024];
__device__ hf g_Bh[1024 * 1024];

// ---------------- helpers ----------------
__device__ __forceinline__ uint32_t smem_u32(const void* p) {
    uint32_t a;
    asm("{ .reg .u64 t; cvta.to.shared.u64 t, %1; cvt.u32.u64 %0, t; }"
        : "=r"(a) : "l"(p));
    return a;
}
#define CP_ASYNC16(sp, gp) \
    asm volatile("cp.async.cg.shared.global [%0], [%1], 16;" :: "r"(sp), "l"(gp) : "memory")
#define CP_COMMIT() asm volatile("cp.async.commit_group;" ::: "memory")
#define CP_WAIT(n)  asm volatile("cp.async.wait_group %0;" :: "n"(n) : "memory")
#define LDSM4(r, a) \
    asm volatile("ldmatrix.sync.aligned.m8n8.x4.shared.b16 {%0,%1,%2,%3}, [%4];" \
                 : "=r"((r)[0]), "=r"((r)[1]), "=r"((r)[2]), "=r"((r)[3]) : "r"(a))
#define LDSM4T(r, a) \
    asm volatile("ldmatrix.sync.aligned.m8n8.x4.trans.shared.b16 {%0,%1,%2,%3}, [%4];" \
                 : "=r"((r)[0]), "=r"((r)[1]), "=r"((r)[2]), "=r"((r)[3]) : "r"(a))

__device__ __forceinline__ void mma_f16(float* d, const uint32_t* a, const uint32_t* b) {
    asm volatile(
        "mma.sync.aligned.m16n8k16.row.col.f32.f16.f16.f32 "
        "{%0,%1,%2,%3},{%4,%5,%6,%7},{%8,%9},{%0,%1,%2,%3};"
        : "+f"(d[0]), "+f"(d[1]), "+f"(d[2]), "+f"(d[3])
        : "r"(a[0]), "r"(a[1]), "r"(a[2]), "r"(a[3]), "r"(b[0]), "r"(b[1]));
}
__device__ __forceinline__ uint32_t pk_h(float a, float b) {
    __half2 t = __floats2half2_rn(a, b);
    return *(uint32_t*)&t;
}
__device__ __forceinline__ uint32_t ex2_f16x2(uint32_t x) {
    uint32_t r;
    asm("ex2.approx.f16x2 %0, %1;" : "=r"(r) : "r"(x));
    return r;
}

// ---------------- prep: W transpose-convert (z<3) + fcW convert (z=3) ----
__global__ __launch_bounds__(256) void cvtW4(
    const float* __restrict__ Wq, const float* __restrict__ Wk,
    const float* __restrict__ Wv, const float* __restrict__ fcW,
    hf* __restrict__ Ht, hf* __restrict__ Bt)
{
    const int z = blockIdx.z;
    const int k0 = blockIdx.x * 32, n0 = blockIdx.y * 32;
    const int x = threadIdx.x & 31, y = threadIdx.x >> 5;
    if (z == 3) {
#pragma unroll
        for (int j = 0; j < 32; j += 8) {
            size_t o = (size_t)(n0 + y + j) * 1024 + k0 + x;
            Bt[o] = __float2half_rn(fcW[o]);
        }
        return;
    }
    const float* W = z == 0 ? Wq : (z == 1 ? Wk : Wv);
    hf* H = Ht + (size_t)z * 1048576;
    __shared__ float t[32][33];
    const int h = n0 >> 6, e0 = n0 & 63;
#pragma unroll
    for (int j = 0; j < 32; j += 8)
        t[y + j][x] = W[h * 65536 + (k0 + y + j) * 64 + e0 + x];
    __syncthreads();
#pragma unroll
    for (int j = 0; j < 32; j += 8)
        H[(size_t)(n0 + y + j) * 1024 + k0 + x] = __float2half_rn(t[x][y + j]);
}

// =================================================================
// HMMA GEMM body — fp16 single precision, 1 MMA pass (unchanged)
// =================================================================
#define BK 32
#define TILE_B (128 * 80)
#define GH_SMEM (4 * TILE_B)

template <int ASPLIT, int MODE>
__device__ __forceinline__ void gemm_body(
    char* dynsm,
    const float* __restrict__ A32, const hf* __restrict__ Abh,
    const hf* __restrict__ Bh,
    const float* __restrict__ bias, float* __restrict__ C,
    hf* __restrict__ Ch)
{
    const uint32_t sb = smem_u32(dynsm);
    const int tid = threadIdx.x;
    const int m0 = blockIdx.y * 128, n0 = blockIdx.x * 128;
    const int lane = tid & 31, w = tid >> 5;
    const int wm = w >> 2, wn = w & 3;
    const int lr = lane & 15, lcb = (lane >> 4) * 16;

    float acc[4][4][4];
#pragma unroll
    for (int i = 0; i < 4; i++)
#pragma unroll
        for (int j = 0; j < 4; j++)
#pragma unroll
            for (int r = 0; r < 4; r++) acc[i][j][r] = 0.f;

    uint32_t aoff[4], boff[2];
#pragma unroll
    for (int i = 0; i < 4; i++)
        aoff[i] = (uint32_t)((wm * 64 + i * 16 + lr) * 80) + lcb;
#pragma unroll
    for (int hlf = 0; hlf < 2; hlf++)
        boff[hlf] = (uint32_t)((wn * 32 + hlf * 16 + lr) * 80) + lcb;

    const int a_row = tid >> 1, a_chb = (tid & 1) * 4;
    float4 areg[4];
    auto ldgA = [&](int s) {
#pragma unroll
        for (int i = 0; i < 4; i++)
            areg[i] = *(const float4*)&A32[(size_t)(m0 + a_row) * 1024 + s * BK + (a_chb + i) * 4];
    };
    auto cvtA = [&](int buf) {
        char* ph = dynsm + (size_t)(buf * 2 + 0) * TILE_B;
#pragma unroll
        for (int i = 0; i < 4; i++) {
            float4 v = areg[i];
            uint32_t off = (uint32_t)(a_row * 80 + (a_chb + i) * 8);
            *(uint2*)(ph + off) = make_uint2(pk_h(v.x, v.y), pk_h(v.z, v.w));
        }
    };
    auto cpStage = [&](int s) {
        const int buf = s & 1, k0 = s * BK;
        if (ASPLIT == 0) {
            uint32_t sbase = sb + (uint32_t)(buf * 2 + 0) * TILE_B;
#pragma unroll
            for (int i = 0; i < 2; i++) {
                int idx = tid + 256 * i, row = idx >> 2, ch = idx & 3;
                CP_ASYNC16(sbase + (uint32_t)(row * 80 + ch * 16),
                           Abh + (size_t)(m0 + row) * 1024 + k0 + ch * 8);
            }
        }
        {
            uint32_t sbase = sb + (uint32_t)(buf * 2 + 1) * TILE_B;
#pragma unroll
            for (int i = 0; i < 2; i++) {
                int idx = tid + 256 * i, row = idx >> 2, ch = idx & 3;
                CP_ASYNC16(sbase + (uint32_t)(row * 80 + ch * 16),
                           Bh + (size_t)(n0 + row) * 1024 + k0 + ch * 8);
            }
        }
        CP_COMMIT();
    };

    if (ASPLIT) ldgA(0);
    cpStage(0);
    if (ASPLIT) cvtA(0);

    for (int s = 0; s < 32; s++) {
        if (s < 31) {
            if (ASPLIT) ldgA(s + 1);
            cpStage(s + 1);
            CP_WAIT(1);
        } else CP_WAIT(0);
        __syncthreads();

        const uint32_t base = sb + (uint32_t)(s & 1) * 2 * TILE_B;
#pragma unroll
        for (int kk = 0; kk < 2; kk++) {
            const uint32_t kb = kk * 32;
            uint32_t ah[4][4];
#pragma unroll
            for (int i = 0; i < 4; i++)
                LDSM4(ah[i], base + aoff[i] + kb);
            uint32_t bh[4][2];
#pragma unroll
            for (int hlf = 0; hlf < 2; hlf++) {
                uint32_t r[4];
                LDSM4(r, base + TILE_B + boff[hlf] + kb);
                bh[2*hlf][0] = r[0]; bh[2*hlf+1][0] = r[1];
                bh[2*hlf][1] = r[2]; bh[2*hlf+1][1] = r[3];
            }
#pragma unroll
            for (int i = 0; i < 4; i++)
#pragma unroll
                for (int j = 0; j < 4; j++) mma_f16(acc[i][j], ah[i], bh[j]);
        }
        __syncthreads();
        if (ASPLIT && s < 31) cvtA((s + 1) & 1);
    }

#pragma unroll
    for (int i = 0; i < 4; i++)
#pragma unroll
        for (int j = 0; j < 4; j++) {
            int row = m0 + wm * 64 + i * 16 + (lane >> 2);
            int col = n0 + wn * 32 + j * 8 + (lane & 3) * 2;
            float b0 = bias[col], b1 = bias[col + 1];
            float v00 = acc[i][j][0] + b0, v01 = acc[i][j][1] + b1;
            float v10 = acc[i][j][2] + b0, v11 = acc[i][j][3] + b1;
            if (MODE == 0) {
                *(float2*)&C[(size_t)row * 1024 + col] = make_float2(v00, v01);
                *(float2*)&C[(size_t)(row + 8) * 1024 + col] = make_float2(v10, v11);
            } else {
                int h = col >> 6, e = col & 63;
                int b = row >> 10, sI = row & 1023;
                size_t o0 = (((size_t)(b * 16 + h) * 1024 + sI) << 6) + e;
                size_t o1 = o0 + (8 << 6);
                *(uint32_t*)&Ch[o0] = pk_h(v00, v01);
                *(uint32_t*)&Ch[o1] = pk_h(v10, v11);
            }
        }
}

__global__ __launch_bounds__(256) void gemm_proj(
    const float* q, const float* k, const float* v,
    const hf* Wh,
    const float* bq, const float* bk, const float* bv,
    hf* Qh, hf* Kh, hf* Vh)
{
    extern __shared__ __align__(128) char dynsm[];
    int z = blockIdx.z;
    const float* A = z == 0 ? q : (z == 1 ? k : v);
    const float* bias = z == 0 ? bq : (z == 1 ? bk : bv);
    hf* Ch = z == 0 ? Qh : (z == 1 ? Kh : Vh);
    gemm_body<1, 1>(dynsm, A, nullptr, Wh + (size_t)z * 1048576,
                    bias, nullptr, Ch);
}

__global__ __launch_bounds__(256) void gemm_fc(
    const hf* Abh, const hf* Bh, const float* bias, float* C)
{
    extern __shared__ __align__(128) char dynsm[];
    gemm_body<0, 0>(dynsm, nullptr, Abh, Bh, bias, C, nullptr);
}

// =================================================================
// HMMA fused attention — fp16 single, double-buffered K/V,
// 2 syncs/tile, full-tile prefetch lead.  2 CTAs/SM.
// =================================================================
#define TILE9 9216
#define AQH 0
#define AKH 9216           // two 9216 buffers
#define AVH 27648          // two 9216 buffers
#define APH 46080
#define ARB 55296
#define AW  59520
#define ARK 67968
#define ARV 76416
#define ALP 84864
#define AWP 85376
#define AL_ 85888
#define ATT_SMEM 86144

__global__ __launch_bounds__(256, 2) void attn_hmma(
    const hf* __restrict__ Qh,
    const hf* __restrict__ Kh, const hf* __restrict__ Vh,
    const float* __restrict__ relk, const float* __restrict__ relv,
    hf* __restrict__ Oh)
{
    extern __shared__ __align__(128) char sm[];
    const uint32_t sb = smem_u32(sm);
    const int tid = threadIdx.x;
    const int lane = tid & 31, w = tid >> 5;
    const int q0 = blockIdx.x * 64;
    const size_t base = (size_t)(blockIdx.z * NH + blockIdx.y) * (NS * NDH);
    const int lr = lane & 15, hc = (lane >> 4) * 16;
    float* sW = (float*)(sm + AW);
    float* sRK = (float*)(sm + ARK);
    float* sRV = (float*)(sm + ARV);
    float* sLp = (float*)(sm + ALP);
    float* sWp = (float*)(sm + AWP);
    float* sL = (float*)(sm + AL_);

    // K+V tile prefetch for step t into buffer t&1 (one commit group each)
    auto ldKV = [&](int t) {
        uint32_t kb = AKH + (uint32_t)(t & 1) * TILE9;
        uint32_t vb = AVH + (uint32_t)(t & 1) * TILE9;
#pragma unroll
        for (int i = 0; i < 2; i++) {
            int idx = tid + 256 * i, row = idx >> 3, ch = idx & 7;
            size_t go = base + (size_t)(t * 64 + row) * 64 + ch * 8;
            uint32_t so = (uint32_t)(row * 144 + ch * 16);
            CP_ASYNC16(sb + kb + so, Kh + go);
            CP_ASYNC16(sb + vb + so, Vh + go);
        }
        CP_COMMIT();
    };

    {   // Q tile (own group)
#pragma unroll
        for (int i = 0; i < 2; i++) {
            int idx = tid + 256 * i, row = idx >> 3, ch = idx & 7;
            size_t go = base + (size_t)(q0 + row) * 64 + ch * 8;
            CP_ASYNC16(sb + AQH + (uint32_t)(row * 144 + ch * 16), Qh + go);
        }
        CP_COMMIT();
    }
    ldKV(0);

    for (int i = tid; i < 33 * 64; i += 256) { sRK[i] = relk[i]; sRV[i] = relv[i]; }
    for (int i = tid; i < 64 * 33; i += 256) sW[i] = 0.f;

    CP_WAIT(1);        // Q landed (KV0 may be pending)
    __syncthreads();

    // r[q][d] = (q . relk[d]) * C2A
    {
        int q = tid >> 2;
        int part = tid & 3;
        int d0 = part * 8, nd = (part == 3) ? 9 : 8;
        float qv[64];
#pragma unroll
        for (int e2 = 0; e2 < 32; e2++) {
            uint32_t hv = *(uint32_t*)(sm + AQH + q * 144 + e2 * 4);
            float2 fh = __half22float2(*(__half2*)&hv);
            qv[2 * e2] = fh.x;
            qv[2 * e2 + 1] = fh.y;
        }
        for (int d = d0; d < d0 + nd; d++) {
            float s = 0.f;
#pragma unroll
            for (int e = 0; e < 64; e++) s += qv[e] * sRK[d * 64 + e];
            *(hf*)(sm + ARB + (q * 33 + d) * 2) = __float2half_rn(s * C2A);
        }
    }

    const int wm = w >> 1, wn = w & 1;
    float acc2[4][4];
#pragma unroll
    for (int j = 0; j < 4; j++)
#pragma unroll
        for (int r = 0; r < 4; r++) acc2[j][r] = 0.f;
    float lsum[2] = {0.f, 0.f};
    float wsuf[2] = {0.f, 0.f};

    for (int t = 0; t < 16; t++) {
        CP_WAIT(0);          // K[t], V[t] landed (issued a full tile ago)
        __syncthreads();     // sync1: tiles visible; prev PV done; r-table ready (t=0)
        if (t < 15) ldKV(t + 1);   // alt buffers — free since PV(t-1) done

        const uint32_t kbuf = AKH + (uint32_t)(t & 1) * TILE9;
        const uint32_t vbuf = AVH + (uint32_t)(t & 1) * TILE9;

        // ---- QK phase ----
        float acc[4][4];
#pragma unroll
        for (int j = 0; j < 4; j++)
#pragma unroll
            for (int r = 0; r < 4; r++) acc[j][r] = 0.f;
#pragma unroll
        for (int es = 0; es < 4; es++) {
            uint32_t ah[4];
            LDSM4(ah, sb + AQH + (uint32_t)((wm * 16 + lr) * 144) + hc + es * 32);
            uint32_t bh[4][2];
#pragma unroll
            for (int c = 0; c < 2; c++) {
                uint32_t bo = (uint32_t)((wn * 32 + c * 16 + lr) * 144) + hc + es * 32;
                uint32_t r[4];
                LDSM4(r, sb + kbuf + bo);
                bh[2*c][0] = r[0]; bh[2*c+1][0] = r[1];
                bh[2*c][1] = r[2]; bh[2*c+1][1] = r[3];
            }
#pragma unroll
            for (int j = 0; j < 4; j++) mma_f16(acc[j], ah, bh[j]);
        }

        // ---- softmax epilogue -> P (fp16) ----
        const int k0 = t * 64;
        const int X = blockIdx.x;
        const int cls = (t + 2 <= X) ? 0 : ((t >= X + 2) ? 2 : 1);
        if (cls != 1) {
            float rbv[2];
#pragma unroll
            for (int rh = 0; rh < 2; rh++) {
                int rr = wm * 16 + (lane >> 2) + rh * 8;
                rbv[rh] = __half2float(
                    *(hf*)(sm + ARB + (rr * 33 + (cls == 2 ? 32 : 0)) * 2));
            }
            __half2 hs[2];
            hs[0] = __floats2half2_rn(0.f, 0.f);
            hs[1] = __floats2half2_rn(0.f, 0.f);
#pragma unroll
            for (int j = 0; j < 4; j++) {
                int col = wn * 32 + j * 8 + (lane & 3) * 2;
#pragma unroll
                for (int rh = 0; rh < 2; rh++) {
                    int rr = wm * 16 + (lane >> 2) + rh * 8;
                    float f0 = fmaf(acc[j][rh * 2 + 0], C2A, rbv[rh]);
                    float f1 = fmaf(acc[j][rh * 2 + 1], C2A, rbv[rh]);
                    uint32_t p01 = ex2_f16x2(pk_h(f0, f1));
                    *(uint32_t*)(sm + APH + (uint32_t)(rr * 144 + col * 2)) = p01;
                    hs[rh] = __hadd2(hs[rh], *(__half2*)&p01);
                }
            }
#pragma unroll
            for (int rh = 0; rh < 2; rh++) {
                float2 tf = __half22float2(hs[rh]);
                float ts = tf.x + tf.y;
                lsum[rh] += ts;
                if (cls == 2) wsuf[rh] += ts;
            }
        } else {
#pragma unroll
            for (int j = 0; j < 4; j++) {
                int col = wn * 32 + j * 8 + (lane & 3) * 2;
#pragma unroll
                for (int rh = 0; rh < 2; rh++) {
                    int rr = wm * 16 + (lane >> 2) + rh * 8;
                    int qg = q0 + rr;
                    float p01[2];
#pragma unroll
                    for (int v = 0; v < 2; v++) {
                        int kg = k0 + col + v;
                        int dd = kg - qg;
                        int dc = dd < -16 ? -16 : (dd > 16 ? 16 : dd);
                        float rb = __half2float(
                            *(hf*)(sm + ARB + (rr * 33 + dc + 16) * 2));
                        float p = exp2f(fmaf(acc[j][rh * 2 + v], C2A, rb));
                        p01[v] = p;
                        lsum[rh] += p;
                        if (dd >= 16) wsuf[rh] += p;
                        else if (dd > -16) sW[rr * 33 + dd + 16] = p;
                    }
                    *(uint32_t*)(sm + APH + (uint32_t)(rr * 144 + col * 2)) =
                        pk_h(p01[0], p01[1]);
                }
            }
        }
        __syncthreads();     // sync2: P visible (V[t] already ready via sync1)

        // ---- PV phase ----
#pragma unroll
        for (int ks = 0; ks < 4; ks++) {
            uint32_t ph[4];
            LDSM4(ph, sb + APH + (uint32_t)((wm * 16 + lr) * 144) + ks * 32 + hc);
            uint32_t vh[4][2];
#pragma unroll
            for (int c = 0; c < 2; c++) {
                int cg = wn * 2 + c;
                uint32_t vo = (uint32_t)((ks * 16 + lr) * 144) + (cg * 2 + (lane >> 4)) * 16;
                uint32_t r[4];
                LDSM4T(r, sb + vbuf + vo);
                vh[2*c][0] = r[0]; vh[2*c][1] = r[1];
                vh[2*c+1][0] = r[2]; vh[2*c+1][1] = r[3];
            }
#pragma unroll
            for (int nf = 0; nf < 4; nf++) mma_f16(acc2[nf], ph, vh[nf]);
        }
    }

    // ---- deterministic l / w32 reduction ----
#pragma unroll
    for (int i = 0; i < 2; i++) {
        lsum[i] += __shfl_xor_sync(0xffffffffu, lsum[i], 1);
        lsum[i] += __shfl_xor_sync(0xffffffffu, lsum[i], 2);
        wsuf[i] += __shfl_xor_sync(0xffffffffu, wsuf[i], 1);
        wsuf[i] += __shfl_xor_sync(0xffffffffu, wsuf[i], 2);
    }
    if ((lane & 3) == 0) {
#pragma unroll
        for (int rh = 0; rh < 2; rh++) {
            int row = wm * 16 + rh * 8 + (lane >> 2);
            sLp[row * 2 + wn] = lsum[rh];
            sWp[row * 2 + wn] = wsuf[rh];
        }
    }
    __syncthreads();
    if (tid < 64) {
        int r = tid;
        float l = sLp[r * 2] + sLp[r * 2 + 1];
        float ws = sWp[r * 2] + sWp[r * 2 + 1];
        float mid = 0.f;
#pragma unroll
        for (int d = 1; d < 32; d++) mid += sW[r * 33 + d];
        sW[r * 33 + 0] = l - ws - mid;
        sW[r * 33 + 32] = ws;
        sL[r] = 1.f / l;
    }
    __syncthreads();

    // ---- rel_v bias + normalize + store O ----
#pragma unroll
    for (int nf = 0; nf < 4; nf++) {
        int row0 = wm * 16 + (lane >> 2), row1 = row0 + 8;
        int col = wn * 32 + nf * 8 + (lane & 3) * 2;
        float b00 = 0.f, b01 = 0.f, b10 = 0.f, b11 = 0.f;
#pragma unroll
        for (int d = 0; d < 33; d++) {
            float w0v = sW[row0 * 33 + d], w1v = sW[row1 * 33 + d];
            float r0 = sRV[d * 64 + col], r1 = sRV[d * 64 + col + 1];
            b00 += w0v * r0; b01 += w0v * r1;
            b10 += w1v * r0; b11 += w1v * r1;
        }
        float il0 = sL[row0], il1 = sL[row1];
        float o00 = (acc2[nf][0] + b00) * il0, o01 = (acc2[nf][1] + b01) * il0;
        float o10 = (acc2[nf][2] + b10) * il1, o11 = (acc2[nf][3] + b11) * il1;
        size_t g0 = ((size_t)(blockIdx.z * 1024 + q0 + row0)) * 1024 + blockIdx.y * 64 + col;
        size_t g1 = ((size_t)(blockIdx.z * 1024 + q0 + row1)) * 1024 + blockIdx.y * 64 + col;
        *(uint32_t*)&Oh[g0] = pk_h(o00, o01);
        *(uint32_t*)&Oh[g1] = pk_h(o10, o11);
    }
}

// =================================================================
extern "C" void kernel_launch(void* const* d_in, const int* in_sizes, int n_in,
                              void* d_out, int out_size)
{
    const float* query = (const float*)d_in[0];
    const float* key   = (const float*)d_in[1];
    const float* value = (const float*)d_in[2];
    const float* Wq    = (const float*)d_in[3];
    const float* bq    = (const float*)d_in[4];
    const float* Wk    = (const float*)d_in[5];
    const float* bk    = (const float*)d_in[6];
    const float* Wv    = (const float*)d_in[7];
    const float* bv    = (const float*)d_in[8];
    const float* relk  = (const float*)d_in[9];
    const float* relv  = (const float*)d_in[10];
    const float* fcW   = (const float*)d_in[11];
    const float* fcb   = (const float*)d_in[12];
    float* out = (float*)d_out;

    hf *Qh, *Kh, *Vh, *Oh, *Wh, *Bh;
    cudaGetSymbolAddress((void**)&Qh, g_Qh);
    cudaGetSymbolAddress((void**)&Kh, g_Kh);
    cudaGetSymbolAddress((void**)&Vh, g_Vh);
    cudaGetSymbolAddress((void**)&Oh, g_Oh);
    cudaGetSymbolAddress((void**)&Wh, g_Wh);
    cudaGetSymbolAddress((void**)&Bh, g_Bh);

    cudaFuncSetAttribute(gemm_proj, cudaFuncAttributeMaxDynamicSharedMemorySize, GH_SMEM);
    cudaFuncSetAttribute(gemm_fc, cudaFuncAttributeMaxDynamicSharedMemorySize, GH_SMEM);
    cudaFuncSetAttribute(attn_hmma, cudaFuncAttributeMaxDynamicSharedMemorySize, ATT_SMEM);

    cvtW4<<<dim3(32, 32, 4), 256>>>(Wq, Wk, Wv, fcW, Wh, Bh);

    gemm_proj<<<dim3(8, 32, 3), 256, GH_SMEM>>>(query, key, value, Wh,
                                                bq, bk, bv, Qh, Kh, Vh);

    attn_hmma<<<dim3(16, NH, NB), 256, ATT_SMEM>>>(Qh, Kh, Vh, relk, relv, Oh);

    gemm_fc<<<dim3(8, 32), 256, GH_SMEM>>>(Oh, Bh, fcb, out);
}

// round 16
// speedup vs baseline: 2.0479x; 1.0180x over previous
#include <cuda_runtime.h>
#include <cuda_fp16.h>
#include <cstdint>

#define NB 4
#define NS 1024
#define NH 16
#define NDH 64
#define C2A 0.18033688f   // ATT_SCALE * log2(e)
typedef __half hf;

// ---------------- scratch ----------------
__device__ hf g_Qh[NB * NH * NS * NDH];
__device__ hf g_Kh[NB * NH * NS * NDH];
__device__ hf g_Vh[NB * NH * NS * NDH];
__device__ hf g_Oh[4096 * 1024];
__device__ hf g_Wh[3 * 1024 * 1024];
__device__ hf g_Bh[1024 * 1024];

// ---------------- helpers ----------------
__device__ __forceinline__ uint32_t smem_u32(const void* p) {
    uint32_t a;
    asm("{ .reg .u64 t; cvta.to.shared.u64 t, %1; cvt.u32.u64 %0, t; }"
        : "=r"(a) : "l"(p));
    return a;
}
#define CP_ASYNC16(sp, gp) \
    asm volatile("cp.async.cg.shared.global [%0], [%1], 16;" :: "r"(sp), "l"(gp) : "memory")
#define CP_COMMIT() asm volatile("cp.async.commit_group;" ::: "memory")
#define CP_WAIT(n)  asm volatile("cp.async.wait_group %0;" :: "n"(n) : "memory")
#define LDSM4(r, a) \
    asm volatile("ldmatrix.sync.aligned.m8n8.x4.shared.b16 {%0,%1,%2,%3}, [%4];" \
                 : "=r"((r)[0]), "=r"((r)[1]), "=r"((r)[2]), "=r"((r)[3]) : "r"(a))
#define LDSM4T(r, a) \
    asm volatile("ldmatrix.sync.aligned.m8n8.x4.trans.shared.b16 {%0,%1,%2,%3}, [%4];" \
                 : "=r"((r)[0]), "=r"((r)[1]), "=r"((r)[2]), "=r"((r)[3]) : "r"(a))

__device__ __forceinline__ void mma_f16(float* d, const uint32_t* a, const uint32_t* b) {
    asm volatile(
        "mma.sync.aligned.m16n8k16.row.col.f32.f16.f16.f32 "
        "{%0,%1,%2,%3},{%4,%5,%6,%7},{%8,%9},{%0,%1,%2,%3};"
        : "+f"(d[0]), "+f"(d[1]), "+f"(d[2]), "+f"(d[3])
        : "r"(a[0]), "r"(a[1]), "r"(a[2]), "r"(a[3]), "r"(b[0]), "r"(b[1]));
}
__device__ __forceinline__ uint32_t pk_h(float a, float b) {
    __half2 t = __floats2half2_rn(a, b);
    return *(uint32_t*)&t;
}
__device__ __forceinline__ uint32_t ex2_f16x2(uint32_t x) {
    uint32_t r;
    asm("ex2.approx.f16x2 %0, %1;" : "=r"(r) : "r"(x));
    return r;
}

// ---------------- prep: W transpose-convert (z<3) + fcW convert (z=3) ----
__global__ __launch_bounds__(256) void cvtW4(
    const float* __restrict__ Wq, const float* __restrict__ Wk,
    const float* __restrict__ Wv, const float* __restrict__ fcW,
    hf* __restrict__ Ht, hf* __restrict__ Bt)
{
    const int z = blockIdx.z;
    const int k0 = blockIdx.x * 32, n0 = blockIdx.y * 32;
    const int x = threadIdx.x & 31, y = threadIdx.x >> 5;
    if (z == 3) {
#pragma unroll
        for (int j = 0; j < 32; j += 8) {
            size_t o = (size_t)(n0 + y + j) * 1024 + k0 + x;
            Bt[o] = __float2half_rn(fcW[o]);
        }
        return;
    }
    const float* W = z == 0 ? Wq : (z == 1 ? Wk : Wv);
    hf* H = Ht + (size_t)z * 1048576;
    __shared__ float t[32][33];
    const int h = n0 >> 6, e0 = n0 & 63;
#pragma unroll
    for (int j = 0; j < 32; j += 8)
        t[y + j][x] = W[h * 65536 + (k0 + y + j) * 64 + e0 + x];
    __syncthreads();
#pragma unroll
    for (int j = 0; j < 32; j += 8)
        H[(size_t)(n0 + y + j) * 1024 + k0 + x] = __float2half_rn(t[x][y + j]);
}

// =================================================================
// HMMA GEMM body — fp16 single precision, 1 MMA pass (unchanged)
// =================================================================
#define BK 32
#define TILE_B (128 * 80)
#define GH_SMEM (4 * TILE_B)

template <int ASPLIT, int MODE>
__device__ __forceinline__ void gemm_body(
    char* dynsm,
    const float* __restrict__ A32, const hf* __restrict__ Abh,
    const hf* __restrict__ Bh,
    const float* __restrict__ bias, float* __restrict__ C,
    hf* __restrict__ Ch)
{
    const uint32_t sb = smem_u32(dynsm);
    const int tid = threadIdx.x;
    const int m0 = blockIdx.y * 128, n0 = blockIdx.x * 128;
    const int lane = tid & 31, w = tid >> 5;
    const int wm = w >> 2, wn = w & 3;
    const int lr = lane & 15, lcb = (lane >> 4) * 16;

    float acc[4][4][4];
#pragma unroll
    for (int i = 0; i < 4; i++)
#pragma unroll
        for (int j = 0; j < 4; j++)
#pragma unroll
            for (int r = 0; r < 4; r++) acc[i][j][r] = 0.f;

    uint32_t aoff[4], boff[2];
#pragma unroll
    for (int i = 0; i < 4; i++)
        aoff[i] = (uint32_t)((wm * 64 + i * 16 + lr) * 80) + lcb;
#pragma unroll
    for (int hlf = 0; hlf < 2; hlf++)
        boff[hlf] = (uint32_t)((wn * 32 + hlf * 16 + lr) * 80) + lcb;

    const int a_row = tid >> 1, a_chb = (tid & 1) * 4;
    float4 areg[4];
    auto ldgA = [&](int s) {
#pragma unroll
        for (int i = 0; i < 4; i++)
            areg[i] = *(const float4*)&A32[(size_t)(m0 + a_row) * 1024 + s * BK + (a_chb + i) * 4];
    };
    auto cvtA = [&](int buf) {
        char* ph = dynsm + (size_t)(buf * 2 + 0) * TILE_B;
#pragma unroll
        for (int i = 0; i < 4; i++) {
            float4 v = areg[i];
            uint32_t off = (uint32_t)(a_row * 80 + (a_chb + i) * 8);
            *(uint2*)(ph + off) = make_uint2(pk_h(v.x, v.y), pk_h(v.z, v.w));
        }
    };
    auto cpStage = [&](int s) {
        const int buf = s & 1, k0 = s * BK;
        if (ASPLIT == 0) {
            uint32_t sbase = sb + (uint32_t)(buf * 2 + 0) * TILE_B;
#pragma unroll
            for (int i = 0; i < 2; i++) {
                int idx = tid + 256 * i, row = idx >> 2, ch = idx & 3;
                CP_ASYNC16(sbase + (uint32_t)(row * 80 + ch * 16),
                           Abh + (size_t)(m0 + row) * 1024 + k0 + ch * 8);
            }
        }
        {
            uint32_t sbase = sb + (uint32_t)(buf * 2 + 1) * TILE_B;
#pragma unroll
            for (int i = 0; i < 2; i++) {
                int idx = tid + 256 * i, row = idx >> 2, ch = idx & 3;
                CP_ASYNC16(sbase + (uint32_t)(row * 80 + ch * 16),
                           Bh + (size_t)(n0 + row) * 1024 + k0 + ch * 8);
            }
        }
        CP_COMMIT();
    };

    if (ASPLIT) ldgA(0);
    cpStage(0);
    if (ASPLIT) cvtA(0);

    for (int s = 0; s < 32; s++) {
        if (s < 31) {
            if (ASPLIT) ldgA(s + 1);
            cpStage(s + 1);
            CP_WAIT(1);
        } else CP_WAIT(0);
        __syncthreads();

        const uint32_t base = sb + (uint32_t)(s & 1) * 2 * TILE_B;
#pragma unroll
        for (int kk = 0; kk < 2; kk++) {
            const uint32_t kb = kk * 32;
            uint32_t ah[4][4];
#pragma unroll
            for (int i = 0; i < 4; i++)
                LDSM4(ah[i], base + aoff[i] + kb);
            uint32_t bh[4][2];
#pragma unroll
            for (int hlf = 0; hlf < 2; hlf++) {
                uint32_t r[4];
                LDSM4(r, base + TILE_B + boff[hlf] + kb);
                bh[2*hlf][0] = r[0]; bh[2*hlf+1][0] = r[1];
                bh[2*hlf][1] = r[2]; bh[2*hlf+1][1] = r[3];
            }
#pragma unroll
            for (int i = 0; i < 4; i++)
#pragma unroll
                for (int j = 0; j < 4; j++) mma_f16(acc[i][j], ah[i], bh[j]);
        }
        __syncthreads();
        if (ASPLIT && s < 31) cvtA((s + 1) & 1);
    }

#pragma unroll
    for (int i = 0; i < 4; i++)
#pragma unroll
        for (int j = 0; j < 4; j++) {
            int row = m0 + wm * 64 + i * 16 + (lane >> 2);
            int col = n0 + wn * 32 + j * 8 + (lane & 3) * 2;
            float b0 = bias[col], b1 = bias[col + 1];
            float v00 = acc[i][j][0] + b0, v01 = acc[i][j][1] + b1;
            float v10 = acc[i][j][2] + b0, v11 = acc[i][j][3] + b1;
            if (MODE == 0) {
                *(float2*)&C[(size_t)row * 1024 + col] = make_float2(v00, v01);
                *(float2*)&C[(size_t)(row + 8) * 1024 + col] = make_float2(v10, v11);
            } else {
                int h = col >> 6, e = col & 63;
                int b = row >> 10, sI = row & 1023;
                size_t o0 = (((size_t)(b * 16 + h) * 1024 + sI) << 6) + e;
                size_t o1 = o0 + (8 << 6);
                *(uint32_t*)&Ch[o0] = pk_h(v00, v01);
                *(uint32_t*)&Ch[o1] = pk_h(v10, v11);
            }
        }
}

__global__ __launch_bounds__(256) void gemm_proj(
    const float* q, const float* k, const float* v,
    const hf* Wh,
    const float* bq, const float* bk, const float* bv,
    hf* Qh, hf* Kh, hf* Vh)
{
    extern __shared__ __align__(128) char dynsm[];
    int z = blockIdx.z;
    const float* A = z == 0 ? q : (z == 1 ? k : v);
    const float* bias = z == 0 ? bq : (z == 1 ? bk : bv);
    hf* Ch = z == 0 ? Qh : (z == 1 ? Kh : Vh);
    gemm_body<1, 1>(dynsm, A, nullptr, Wh + (size_t)z * 1048576,
                    bias, nullptr, Ch);
}

__global__ __launch_bounds__(256) void gemm_fc(
    const hf* Abh, const hf* Bh, const float* bias, float* C)
{
    extern __shared__ __align__(128) char dynsm[];
    gemm_body<0, 0>(dynsm, nullptr, Abh, Bh, bias, C, nullptr);
}

// =================================================================
// HMMA fused attention — fp16 single, double-buffered K/V,
// Q fragments register-resident across the k loop.  2 CTAs/SM.
// =================================================================
#define TILE9 9216
#define AQH 0
#define AKH 9216           // two 9216 buffers
#define AVH 27648          // two 9216 buffers
#define APH 46080
#define ARB 55296
#define AW  59520
#define ARK 67968
#define ARV 76416
#define ALP 84864
#define AWP 85376
#define AL_ 85888
#define ATT_SMEM 86144

__global__ __launch_bounds__(256, 2) void attn_hmma(
    const hf* __restrict__ Qh,
    const hf* __restrict__ Kh, const hf* __restrict__ Vh,
    const float* __restrict__ relk, const float* __restrict__ relv,
    hf* __restrict__ Oh)
{
    extern __shared__ __align__(128) char sm[];
    const uint32_t sb = smem_u32(sm);
    const int tid = threadIdx.x;
    const int lane = tid & 31, w = tid >> 5;
    const int q0 = blockIdx.x * 64;
    const size_t base = (size_t)(blockIdx.z * NH + blockIdx.y) * (NS * NDH);
    const int lr = lane & 15, hc = (lane >> 4) * 16;
    float* sW = (float*)(sm + AW);
    float* sRK = (float*)(sm + ARK);
    float* sRV = (float*)(sm + ARV);
    float* sLp = (float*)(sm + ALP);
    float* sWp = (float*)(sm + AWP);
    float* sL = (float*)(sm + AL_);

    auto ldKV = [&](int t) {
        uint32_t kb = AKH + (uint32_t)(t & 1) * TILE9;
        uint32_t vb = AVH + (uint32_t)(t & 1) * TILE9;
#pragma unroll
        for (int i = 0; i < 2; i++) {
            int idx = tid + 256 * i, row = idx >> 3, ch = idx & 7;
            size_t go = base + (size_t)(t * 64 + row) * 64 + ch * 8;
            uint32_t so = (uint32_t)(row * 144 + ch * 16);
            CP_ASYNC16(sb + kb + so, Kh + go);
            CP_ASYNC16(sb + vb + so, Vh + go);
        }
        CP_COMMIT();
    };

    {   // Q tile (own group)
#pragma unroll
        for (int i = 0; i < 2; i++) {
            int idx = tid + 256 * i, row = idx >> 3, ch = idx & 7;
            size_t go = base + (size_t)(q0 + row) * 64 + ch * 8;
            CP_ASYNC16(sb + AQH + (uint32_t)(row * 144 + ch * 16), Qh + go);
        }
        CP_COMMIT();
    }
    ldKV(0);

    for (int i = tid; i < 33 * 64; i += 256) { sRK[i] = relk[i]; sRV[i] = relv[i]; }
    for (int i = tid; i < 64 * 33; i += 256) sW[i] = 0.f;

    CP_WAIT(1);        // Q landed
    __syncthreads();

    // r[q][d] = (q . relk[d]) * C2A
    {
        int q = tid >> 2;
        int part = tid & 3;
        int d0 = part * 8, nd = (part == 3) ? 9 : 8;
        float qv[64];
#pragma unroll
        for (int e2 = 0; e2 < 32; e2++) {
            uint32_t hv = *(uint32_t*)(sm + AQH + q * 144 + e2 * 4);
            float2 fh = __half22float2(*(__half2*)&hv);
            qv[2 * e2] = fh.x;
            qv[2 * e2 + 1] = fh.y;
        }
        for (int d = d0; d < d0 + nd; d++) {
            float s = 0.f;
#pragma unroll
            for (int e = 0; e < 64; e++) s += qv[e] * sRK[d * 64 + e];
            *(hf*)(sm + ARB + (q * 33 + d) * 2) = __float2half_rn(s * C2A);
        }
    }

    const int wm = w >> 1, wn = w & 1;

    // ---- hoist Q fragments (constant across all 16 k-tiles) ----
    uint32_t aq[4][4];
#pragma unroll
    for (int es = 0; es < 4; es++)
        LDSM4(aq[es], sb + AQH + (uint32_t)((wm * 16 + lr) * 144) + hc + es * 32);

    float acc2[4][4];
#pragma unroll
    for (int j = 0; j < 4; j++)
#pragma unroll
        for (int r = 0; r < 4; r++) acc2[j][r] = 0.f;
    float lsum[2] = {0.f, 0.f};
    float wsuf[2] = {0.f, 0.f};

    for (int t = 0; t < 16; t++) {
        CP_WAIT(0);
        __syncthreads();     // sync1: K/V[t] visible; prev PV done; r-table ready (t=0)
        if (t < 15) ldKV(t + 1);

        const uint32_t kbuf = AKH + (uint32_t)(t & 1) * TILE9;
        const uint32_t vbuf = AVH + (uint32_t)(t & 1) * TILE9;

        // ---- QK phase (Q from registers) ----
        float acc[4][4];
#pragma unroll
        for (int j = 0; j < 4; j++)
#pragma unroll
            for (int r = 0; r < 4; r++) acc[j][r] = 0.f;
#pragma unroll
        for (int es = 0; es < 4; es++) {
            uint32_t bh[4][2];
#pragma unroll
            for (int c = 0; c < 2; c++) {
                uint32_t bo = (uint32_t)((wn * 32 + c * 16 + lr) * 144) + hc + es * 32;
                uint32_t r[4];
                LDSM4(r, sb + kbuf + bo);
                bh[2*c][0] = r[0]; bh[2*c+1][0] = r[1];
                bh[2*c][1] = r[2]; bh[2*c+1][1] = r[3];
            }
#pragma unroll
            for (int j = 0; j < 4; j++) mma_f16(acc[j], aq[es], bh[j]);
        }

        // ---- softmax epilogue -> P (fp16) ----
        const int k0 = t * 64;
        const int X = blockIdx.x;
        const int cls = (t + 2 <= X) ? 0 : ((t >= X + 2) ? 2 : 1);
        if (cls != 1) {
            float rbv[2];
#pragma unroll
            for (int rh = 0; rh < 2; rh++) {
                int rr = wm * 16 + (lane >> 2) + rh * 8;
                rbv[rh] = __half2float(
                    *(hf*)(sm + ARB + (rr * 33 + (cls == 2 ? 32 : 0)) * 2));
            }
            __half2 hs[2];
            hs[0] = __floats2half2_rn(0.f, 0.f);
            hs[1] = __floats2half2_rn(0.f, 0.f);
#pragma unroll
            for (int j = 0; j < 4; j++) {
                int col = wn * 32 + j * 8 + (lane & 3) * 2;
#pragma unroll
                for (int rh = 0; rh < 2; rh++) {
                    int rr = wm * 16 + (lane >> 2) + rh * 8;
                    float f0 = fmaf(acc[j][rh * 2 + 0], C2A, rbv[rh]);
                    float f1 = fmaf(acc[j][rh * 2 + 1], C2A, rbv[rh]);
                    uint32_t p01 = ex2_f16x2(pk_h(f0, f1));
                    *(uint32_t*)(sm + APH + (uint32_t)(rr * 144 + col * 2)) = p01;
                    hs[rh] = __hadd2(hs[rh], *(__half2*)&p01);
                }
            }
#pragma unroll
            for (int rh = 0; rh < 2; rh++) {
                float2 tf = __half22float2(hs[rh]);
                float ts = tf.x + tf.y;
                lsum[rh] += ts;
                if (cls == 2) wsuf[rh] += ts;
            }
        } else {
#pragma unroll
            for (int j = 0; j < 4; j++) {
                int col = wn * 32 + j * 8 + (lane & 3) * 2;
#pragma unroll
                for (int rh = 0; rh < 2; rh++) {
                    int rr = wm * 16 + (lane >> 2) + rh * 8;
                    int qg = q0 + rr;
                    float p01[2];
#pragma unroll
                    for (int v = 0; v < 2; v++) {
                        int kg = k0 + col + v;
                        int dd = kg - qg;
                        int dc = dd < -16 ? -16 : (dd > 16 ? 16 : dd);
                        float rb = __half2float(
                            *(hf*)(sm + ARB + (rr * 33 + dc + 16) * 2));
                        float p = exp2f(fmaf(acc[j][rh * 2 + v], C2A, rb));
                        p01[v] = p;
                        lsum[rh] += p;
                        if (dd >= 16) wsuf[rh] += p;
                        else if (dd > -16) sW[rr * 33 + dd + 16] = p;
                    }
                    *(uint32_t*)(sm + APH + (uint32_t)(rr * 144 + col * 2)) =
                        pk_h(p01[0], p01[1]);
                }
            }
        }
        __syncthreads();     // sync2: P visible

        // ---- PV phase ----
#pragma unroll
        for (int ks = 0; ks < 4; ks++) {
            uint32_t ph[4];
            LDSM4(ph, sb + APH + (uint32_t)((wm * 16 + lr) * 144) + ks * 32 + hc);
            uint32_t vh[4][2];
#pragma unroll
            for (int c = 0; c < 2; c++) {
                int cg = wn * 2 + c;
                uint32_t vo = (uint32_t)((ks * 16 + lr) * 144) + (cg * 2 + (lane >> 4)) * 16;
                uint32_t r[4];
                LDSM4T(r, sb + vbuf + vo);
                vh[2*c][0] = r[0]; vh[2*c][1] = r[1];
                vh[2*c+1][0] = r[2]; vh[2*c+1][1] = r[3];
            }
#pragma unroll
            for (int nf = 0; nf < 4; nf++) mma_f16(acc2[nf], ph, vh[nf]);
        }
    }

    // ---- deterministic l / w32 reduction ----
#pragma unroll
    for (int i = 0; i < 2; i++) {
        lsum[i] += __shfl_xor_sync(0xffffffffu, lsum[i], 1);
        lsum[i] += __shfl_xor_sync(0xffffffffu, lsum[i], 2);
        wsuf[i] += __shfl_xor_sync(0xffffffffu, wsuf[i], 1);
        wsuf[i] += __shfl_xor_sync(0xffffffffu, wsuf[i], 2);
    }
    if ((lane & 3) == 0) {
#pragma unroll
        for (int rh = 0; rh < 2; rh++) {
            int row = wm * 16 + rh * 8 + (lane >> 2);
            sLp[row * 2 + wn] = lsum[rh];
            sWp[row * 2 + wn] = wsuf[rh];
        }
    }
    __syncthreads();
    if (tid < 64) {
        int r = tid;
        float l = sLp[r * 2] + sLp[r * 2 + 1];
        float ws = sWp[r * 2] + sWp[r * 2 + 1];
        float mid = 0.f;
#pragma unroll
        for (int d = 1; d < 32; d++) mid += sW[r * 33 + d];
        sW[r * 33 + 0] = l - ws - mid;
        sW[r * 33 + 32] = ws;
        sL[r] = 1.f / l;
    }
    __syncthreads();

    // ---- rel_v bias + normalize + store O ----
#pragma unroll
    for (int nf = 0; nf < 4; nf++) {
        int row0 = wm * 16 + (lane >> 2), row1 = row0 + 8;
        int col = wn * 32 + nf * 8 + (lane & 3) * 2;
        float b00 = 0.f, b01 = 0.f, b10 = 0.f, b11 = 0.f;
#pragma unroll
        for (int d = 0; d < 33; d++) {
            float w0v = sW[row0 * 33 + d], w1v = sW[row1 * 33 + d];
            float r0 = sRV[d * 64 + col], r1 = sRV[d * 64 + col + 1];
            b00 += w0v * r0; b01 += w0v * r1;
            b10 += w1v * r0; b11 += w1v * r1;
        }
        float il0 = sL[row0], il1 = sL[row1];
        float o00 = (acc2[nf][0] + b00) * il0, o01 = (acc2[nf][1] + b01) * il0;
        float o10 = (acc2[nf][2] + b10) * il1, o11 = (acc2[nf][3] + b11) * il1;
        size_t g0 = ((size_t)(blockIdx.z * 1024 + q0 + row0)) * 1024 + blockIdx.y * 64 + col;
        size_t g1 = ((size_t)(blockIdx.z * 1024 + q0 + row1)) * 1024 + blockIdx.y * 64 + col;
        *(uint32_t*)&Oh[g0] = pk_h(o00, o01);
        *(uint32_t*)&Oh[g1] = pk_h(o10, o11);
    }
}

// =================================================================
extern "C" void kernel_launch(void* const* d_in, const int* in_sizes, int n_in,
                              void* d_out, int out_size)
{
    const float* query = (const float*)d_in[0];
    const float* key   = (const float*)d_in[1];
    const float* value = (const float*)d_in[2];
    const float* Wq    = (const float*)d_in[3];
    const float* bq    = (const float*)d_in[4];
    const float* Wk    = (const float*)d_in[5];
    const float* bk    = (const float*)d_in[6];
    const float* Wv    = (const float*)d_in[7];
    const float* bv    = (const float*)d_in[8];
    const float* relk  = (const float*)d_in[9];
    const float* relv  = (const float*)d_in[10];
    const float* fcW   = (const float*)d_in[11];
    const float* fcb   = (const float*)d_in[12];
    float* out = (float*)d_out;

    hf *Qh, *Kh, *Vh, *Oh, *Wh, *Bh;
    cudaGetSymbolAddress((void**)&Qh, g_Qh);
    cudaGetSymbolAddress((void**)&Kh, g_Kh);
    cudaGetSymbolAddress((void**)&Vh, g_Vh);
    cudaGetSymbolAddress((void**)&Oh, g_Oh);
    cudaGetSymbolAddress((void**)&Wh, g_Wh);
    cudaGetSymbolAddress((void**)&Bh, g_Bh);

    cudaFuncSetAttribute(gemm_proj, cudaFuncAttributeMaxDynamicSharedMemorySize, GH_SMEM);
    cudaFuncSetAttribute(gemm_fc, cudaFuncAttributeMaxDynamicSharedMemorySize, GH_SMEM);
    cudaFuncSetAttribute(attn_hmma, cudaFuncAttributeMaxDynamicSharedMemorySize, ATT_SMEM);

    cvtW4<<<dim3(32, 32, 4), 256>>>(Wq, Wk, Wv, fcW, Wh, Bh);

    gemm_proj<<<dim3(8, 32, 3), 256, GH_SMEM>>>(query, key, value, Wh,
                                                bq, bk, bv, Qh, Kh, Vh);

    attn_hmma<<<dim3(16, NH, NB), 256, ATT_SMEM>>>(Qh, Kh, Vh, relk, relv, Oh);

    gemm_fc<<<dim3(8, 32), 256, GH_SMEM>>>(Oh, Bh, fcb, out);
}

// round 17
// speedup vs baseline: 2.0820x; 1.0166x over previous
#include <cuda_runtime.h>
#include <cuda_fp16.h>
#include <cstdint>

#define NB 4
#define NS 1024
#define NH 16
#define NDH 64
#define C2A 0.18033688f   // ATT_SCALE * log2(e)
typedef __half hf;

// ---------------- scratch ----------------
__device__ hf g_Qh[NB * NH * NS * NDH];
__device__ hf g_Kh[NB * NH * NS * NDH];
__device__ hf g_Vh[NB * NH * NS * NDH];
__device__ hf g_Oh[4096 * 1024];
__device__ hf g_Wh[3 * 1024 * 1024];
__device__ hf g_Bh[1024 * 1024];

// ---------------- helpers ----------------
__device__ __forceinline__ uint32_t smem_u32(const void* p) {
    uint32_t a;
    asm("{ .reg .u64 t; cvta.to.shared.u64 t, %1; cvt.u32.u64 %0, t; }"
        : "=r"(a) : "l"(p));
    return a;
}
#define CP_ASYNC16(sp, gp) \
    asm volatile("cp.async.cg.shared.global [%0], [%1], 16;" :: "r"(sp), "l"(gp) : "memory")
#define CP_COMMIT() asm volatile("cp.async.commit_group;" ::: "memory")
#define CP_WAIT(n)  asm volatile("cp.async.wait_group %0;" :: "n"(n) : "memory")
#define LDSM4(r, a) \
    asm volatile("ldmatrix.sync.aligned.m8n8.x4.shared.b16 {%0,%1,%2,%3}, [%4];" \
                 : "=r"((r)[0]), "=r"((r)[1]), "=r"((r)[2]), "=r"((r)[3]) : "r"(a))
#define LDSM4T(r, a) \
    asm volatile("ldmatrix.sync.aligned.m8n8.x4.trans.shared.b16 {%0,%1,%2,%3}, [%4];" \
                 : "=r"((r)[0]), "=r"((r)[1]), "=r"((r)[2]), "=r"((r)[3]) : "r"(a))

__device__ __forceinline__ void mma_f16(float* d, const uint32_t* a, const uint32_t* b) {
    asm volatile(
        "mma.sync.aligned.m16n8k16.row.col.f32.f16.f16.f32 "
        "{%0,%1,%2,%3},{%4,%5,%6,%7},{%8,%9},{%0,%1,%2,%3};"
        : "+f"(d[0]), "+f"(d[1]), "+f"(d[2]), "+f"(d[3])
        : "r"(a[0]), "r"(a[1]), "r"(a[2]), "r"(a[3]), "r"(b[0]), "r"(b[1]));
}
__device__ __forceinline__ uint32_t pk_h(float a, float b) {
    __half2 t = __floats2half2_rn(a, b);
    return *(uint32_t*)&t;
}
__device__ __forceinline__ uint32_t ex2_f16x2(uint32_t x) {
    uint32_t r;
    asm("ex2.approx.f16x2 %0, %1;" : "=r"(r) : "r"(x));
    return r;
}

// ---------------- prep: W transpose-convert (z<3) + fcW convert (z=3) ----
__global__ __launch_bounds__(256) void cvtW4(
    const float* __restrict__ Wq, const float* __restrict__ Wk,
    const float* __restrict__ Wv, const float* __restrict__ fcW,
    hf* __restrict__ Ht, hf* __restrict__ Bt)
{
    const int z = blockIdx.z;
    const int k0 = blockIdx.x * 32, n0 = blockIdx.y * 32;
    const int x = threadIdx.x & 31, y = threadIdx.x >> 5;
    if (z == 3) {
#pragma unroll
        for (int j = 0; j < 32; j += 8) {
            size_t o = (size_t)(n0 + y + j) * 1024 + k0 + x;
            Bt[o] = __float2half_rn(fcW[o]);
        }
        return;
    }
    const float* W = z == 0 ? Wq : (z == 1 ? Wk : Wv);
    hf* H = Ht + (size_t)z * 1048576;
    __shared__ float t[32][33];
    const int h = n0 >> 6, e0 = n0 & 63;
#pragma unroll
    for (int j = 0; j < 32; j += 8)
        t[y + j][x] = W[h * 65536 + (k0 + y + j) * 64 + e0 + x];
    __syncthreads();
#pragma unroll
    for (int j = 0; j < 32; j += 8)
        H[(size_t)(n0 + y + j) * 1024 + k0 + x] = __float2half_rn(t[x][y + j]);
}

// =================================================================
// HMMA GEMM body — fp16 single precision, 1 MMA pass (unchanged)
// =================================================================
#define BK 32
#define TILE_B (128 * 80)
#define GH_SMEM (4 * TILE_B)

template <int ASPLIT, int MODE>
__device__ __forceinline__ void gemm_body(
    char* dynsm,
    const float* __restrict__ A32, const hf* __restrict__ Abh,
    const hf* __restrict__ Bh,
    const float* __restrict__ bias, float* __restrict__ C,
    hf* __restrict__ Ch)
{
    const uint32_t sb = smem_u32(dynsm);
    const int tid = threadIdx.x;
    const int m0 = blockIdx.y * 128, n0 = blockIdx.x * 128;
    const int lane = tid & 31, w = tid >> 5;
    const int wm = w >> 2, wn = w & 3;
    const int lr = lane & 15, lcb = (lane >> 4) * 16;

    float acc[4][4][4];
#pragma unroll
    for (int i = 0; i < 4; i++)
#pragma unroll
        for (int j = 0; j < 4; j++)
#pragma unroll
            for (int r = 0; r < 4; r++) acc[i][j][r] = 0.f;

    uint32_t aoff[4], boff[2];
#pragma unroll
    for (int i = 0; i < 4; i++)
        aoff[i] = (uint32_t)((wm * 64 + i * 16 + lr) * 80) + lcb;
#pragma unroll
    for (int hlf = 0; hlf < 2; hlf++)
        boff[hlf] = (uint32_t)((wn * 32 + hlf * 16 + lr) * 80) + lcb;

    const int a_row = tid >> 1, a_chb = (tid & 1) * 4;
    float4 areg[4];
    auto ldgA = [&](int s) {
#pragma unroll
        for (int i = 0; i < 4; i++)
            areg[i] = *(const float4*)&A32[(size_t)(m0 + a_row) * 1024 + s * BK + (a_chb + i) * 4];
    };
    auto cvtA = [&](int buf) {
        char* ph = dynsm + (size_t)(buf * 2 + 0) * TILE_B;
#pragma unroll
        for (int i = 0; i < 4; i++) {
            float4 v = areg[i];
            uint32_t off = (uint32_t)(a_row * 80 + (a_chb + i) * 8);
            *(uint2*)(ph + off) = make_uint2(pk_h(v.x, v.y), pk_h(v.z, v.w));
        }
    };
    auto cpStage = [&](int s) {
        const int buf = s & 1, k0 = s * BK;
        if (ASPLIT == 0) {
            uint32_t sbase = sb + (uint32_t)(buf * 2 + 0) * TILE_B;
#pragma unroll
            for (int i = 0; i < 2; i++) {
                int idx = tid + 256 * i, row = idx >> 2, ch = idx & 3;
                CP_ASYNC16(sbase + (uint32_t)(row * 80 + ch * 16),
                           Abh + (size_t)(m0 + row) * 1024 + k0 + ch * 8);
            }
        }
        {
            uint32_t sbase = sb + (uint32_t)(buf * 2 + 1) * TILE_B;
#pragma unroll
            for (int i = 0; i < 2; i++) {
                int idx = tid + 256 * i, row = idx >> 2, ch = idx & 3;
                CP_ASYNC16(sbase + (uint32_t)(row * 80 + ch * 16),
                           Bh + (size_t)(n0 + row) * 1024 + k0 + ch * 8);
            }
        }
        CP_COMMIT();
    };

    if (ASPLIT) ldgA(0);
    cpStage(0);
    if (ASPLIT) cvtA(0);

    for (int s = 0; s < 32; s++) {
        if (s < 31) {
            if (ASPLIT) ldgA(s + 1);
            cpStage(s + 1);
            CP_WAIT(1);
        } else CP_WAIT(0);
        __syncthreads();

        const uint32_t base = sb + (uint32_t)(s & 1) * 2 * TILE_B;
#pragma unroll
        for (int kk = 0; kk < 2; kk++) {
            const uint32_t kb = kk * 32;
            uint32_t ah[4][4];
#pragma unroll
            for (int i = 0; i < 4; i++)
                LDSM4(ah[i], base + aoff[i] + kb);
            uint32_t bh[4][2];
#pragma unroll
            for (int hlf = 0; hlf < 2; hlf++) {
                uint32_t r[4];
                LDSM4(r, base + TILE_B + boff[hlf] + kb);
                bh[2*hlf][0] = r[0]; bh[2*hlf+1][0] = r[1];
                bh[2*hlf][1] = r[2]; bh[2*hlf+1][1] = r[3];
            }
#pragma unroll
            for (int i = 0; i < 4; i++)
#pragma unroll
                for (int j = 0; j < 4; j++) mma_f16(acc[i][j], ah[i], bh[j]);
        }
        __syncthreads();
        if (ASPLIT && s < 31) cvtA((s + 1) & 1);
    }

#pragma unroll
    for (int i = 0; i < 4; i++)
#pragma unroll
        for (int j = 0; j < 4; j++) {
            int row = m0 + wm * 64 + i * 16 + (lane >> 2);
            int col = n0 + wn * 32 + j * 8 + (lane & 3) * 2;
            float b0 = bias[col], b1 = bias[col + 1];
            float v00 = acc[i][j][0] + b0, v01 = acc[i][j][1] + b1;
            float v10 = acc[i][j][2] + b0, v11 = acc[i][j][3] + b1;
            if (MODE == 0) {
                *(float2*)&C[(size_t)row * 1024 + col] = make_float2(v00, v01);
                *(float2*)&C[(size_t)(row + 8) * 1024 + col] = make_float2(v10, v11);
            } else {
                int h = col >> 6, e = col & 63;
                int b = row >> 10, sI = row & 1023;
                size_t o0 = (((size_t)(b * 16 + h) * 1024 + sI) << 6) + e;
                size_t o1 = o0 + (8 << 6);
                *(uint32_t*)&Ch[o0] = pk_h(v00, v01);
                *(uint32_t*)&Ch[o1] = pk_h(v10, v11);
            }
        }
}

__global__ __launch_bounds__(256) void gemm_proj(
    const float* q, const float* k, const float* v,
    const hf* Wh,
    const float* bq, const float* bk, const float* bv,
    hf* Qh, hf* Kh, hf* Vh)
{
    extern __shared__ __align__(128) char dynsm[];
    int z = blockIdx.z;
    const float* A = z == 0 ? q : (z == 1 ? k : v);
    const float* bias = z == 0 ? bq : (z == 1 ? bk : bv);
    hf* Ch = z == 0 ? Qh : (z == 1 ? Kh : Vh);
    gemm_body<1, 1>(dynsm, A, nullptr, Wh + (size_t)z * 1048576,
                    bias, nullptr, Ch);
}

__global__ __launch_bounds__(256) void gemm_fc(
    const hf* Abh, const hf* Bh, const float* bias, float* C)
{
    extern __shared__ __align__(128) char dynsm[];
    gemm_body<0, 0>(dynsm, nullptr, Abh, Bh, bias, C, nullptr);
}

// =================================================================
// HMMA fused attention — register-resident P, per-warp k-half PV,
// 1 sync/tile, double-buffered K/V.  2 CTAs/SM.
// =================================================================
#define TILE9 9216
#define AQH 0
#define AKH 9216           // two 9216 buffers (staging reuse at end)
#define AVH 27648          // two 9216 buffers
#define ARB 46080
#define AW  50304
#define ARK 58752
#define ARV 67200
#define ALP 75648
#define AWP 76160
#define AL_ 76672
#define ATT_SMEM 76928

__global__ __launch_bounds__(256, 2) void attn_hmma(
    const hf* __restrict__ Qh,
    const hf* __restrict__ Kh, const hf* __restrict__ Vh,
    const float* __restrict__ relk, const float* __restrict__ relv,
    hf* __restrict__ Oh)
{
    extern __shared__ __align__(128) char sm[];
    const uint32_t sb = smem_u32(sm);
    const int tid = threadIdx.x;
    const int lane = tid & 31, w = tid >> 5;
    const int q0 = blockIdx.x * 64;
    const size_t base = (size_t)(blockIdx.z * NH + blockIdx.y) * (NS * NDH);
    const int lr = lane & 15, hc = (lane >> 4) * 16;
    float* sW = (float*)(sm + AW);
    float* sRK = (float*)(sm + ARK);
    float* sRV = (float*)(sm + ARV);
    float* sLp = (float*)(sm + ALP);
    float* sWp = (float*)(sm + AWP);
    float* sL = (float*)(sm + AL_);

    auto ldKV = [&](int t) {
        uint32_t kb = AKH + (uint32_t)(t & 1) * TILE9;
        uint32_t vb = AVH + (uint32_t)(t & 1) * TILE9;
#pragma unroll
        for (int i = 0; i < 2; i++) {
            int idx = tid + 256 * i, row = idx >> 3, ch = idx & 7;
            size_t go = base + (size_t)(t * 64 + row) * 64 + ch * 8;
            uint32_t so = (uint32_t)(row * 144 + ch * 16);
            CP_ASYNC16(sb + kb + so, Kh + go);
            CP_ASYNC16(sb + vb + so, Vh + go);
        }
        CP_COMMIT();
    };

    {   // Q tile (own group)
#pragma unroll
        for (int i = 0; i < 2; i++) {
            int idx = tid + 256 * i, row = idx >> 3, ch = idx & 7;
            size_t go = base + (size_t)(q0 + row) * 64 + ch * 8;
            CP_ASYNC16(sb + AQH + (uint32_t)(row * 144 + ch * 16), Qh + go);
        }
        CP_COMMIT();
    }
    ldKV(0);

    for (int i = tid; i < 33 * 64; i += 256) { sRK[i] = relk[i]; sRV[i] = relv[i]; }
    for (int i = tid; i < 64 * 33; i += 256) sW[i] = 0.f;

    CP_WAIT(1);        // Q landed
    __syncthreads();

    // r[q][d] = (q . relk[d]) * C2A
    {
        int q = tid >> 2;
        int part = tid & 3;
        int d0 = part * 8, nd = (part == 3) ? 9 : 8;
        float qv[64];
#pragma unroll
        for (int e2 = 0; e2 < 32; e2++) {
            uint32_t hv = *(uint32_t*)(sm + AQH + q * 144 + e2 * 4);
            float2 fh = __half22float2(*(__half2*)&hv);
            qv[2 * e2] = fh.x;
            qv[2 * e2 + 1] = fh.y;
        }
        for (int d = d0; d < d0 + nd; d++) {
            float s = 0.f;
#pragma unroll
            for (int e = 0; e < 64; e++) s += qv[e] * sRK[d * 64 + e];
            *(hf*)(sm + ARB + (q * 33 + d) * 2) = __float2half_rn(s * C2A);
        }
    }

    const int wm = w >> 1, wn = w & 1;

    // ---- hoist Q fragments ----
    uint32_t aq[4][4];
#pragma unroll
    for (int es = 0; es < 4; es++)
        LDSM4(aq[es], sb + AQH + (uint32_t)((wm * 16 + lr) * 144) + hc + es * 32);

    float acc2[8][4];   // partial O: 16 rows x 64 cols over this warp's k-half
#pragma unroll
    for (int j = 0; j < 8; j++)
#pragma unroll
        for (int r = 0; r < 4; r++) acc2[j][r] = 0.f;
    float lsum[2] = {0.f, 0.f};
    float wsuf[2] = {0.f, 0.f};

    for (int t = 0; t < 16; t++) {
        CP_WAIT(0);
        __syncthreads();     // only sync per tile
        if (t < 15) ldKV(t + 1);

        const uint32_t kbuf = AKH + (uint32_t)(t & 1) * TILE9;
        const uint32_t vbuf = AVH + (uint32_t)(t & 1) * TILE9;

        // ---- QK phase (Q from registers) ----
        float acc[4][4];
#pragma unroll
        for (int j = 0; j < 4; j++)
#pragma unroll
            for (int r = 0; r < 4; r++) acc[j][r] = 0.f;
#pragma unroll
        for (int es = 0; es < 4; es++) {
            uint32_t bh[4][2];
#pragma unroll
            for (int c = 0; c < 2; c++) {
                uint32_t bo = (uint32_t)((wn * 32 + c * 16 + lr) * 144) + hc + es * 32;
                uint32_t r[4];
                LDSM4(r, sb + kbuf + bo);
                bh[2*c][0] = r[0]; bh[2*c+1][0] = r[1];
                bh[2*c][1] = r[2]; bh[2*c+1][1] = r[3];
            }
#pragma unroll
            for (int j = 0; j < 4; j++) mma_f16(acc[j], aq[es], bh[j]);
        }

        // ---- softmax -> P in registers (A-frag layout) ----
        const int k0 = t * 64;
        const int X = blockIdx.x;
        const int cls = (t + 2 <= X) ? 0 : ((t >= X + 2) ? 2 : 1);
        uint32_t ph[2][4];   // ph[kc][(j&1)*2+rh]
        if (cls != 1) {
            float rbv[2];
#pragma unroll
            for (int rh = 0; rh < 2; rh++) {
                int rr = wm * 16 + (lane >> 2) + rh * 8;
                rbv[rh] = __half2float(
                    *(hf*)(sm + ARB + (rr * 33 + (cls == 2 ? 32 : 0)) * 2));
            }
            __half2 hs[2];
            hs[0] = __floats2half2_rn(0.f, 0.f);
            hs[1] = __floats2half2_rn(0.f, 0.f);
#pragma unroll
            for (int j = 0; j < 4; j++)
#pragma unroll
                for (int rh = 0; rh < 2; rh++) {
                    float f0 = fmaf(acc[j][rh * 2 + 0], C2A, rbv[rh]);
                    float f1 = fmaf(acc[j][rh * 2 + 1], C2A, rbv[rh]);
                    uint32_t p01 = ex2_f16x2(pk_h(f0, f1));
                    ph[j >> 1][(j & 1) * 2 + rh] = p01;
                    hs[rh] = __hadd2(hs[rh], *(__half2*)&p01);
                }
#pragma unroll
            for (int rh = 0; rh < 2; rh++) {
                float2 tf = __half22float2(hs[rh]);
                float ts = tf.x + tf.y;
                lsum[rh] += ts;
                if (cls == 2) wsuf[rh] += ts;
            }
        } else {
#pragma unroll
            for (int j = 0; j < 4; j++) {
                int col = wn * 32 + j * 8 + (lane & 3) * 2;
#pragma unroll
                for (int rh = 0; rh < 2; rh++) {
                    int rr = wm * 16 + (lane >> 2) + rh * 8;
                    int qg = q0 + rr;
                    float p01[2];
#pragma unroll
                    for (int v = 0; v < 2; v++) {
                        int kg = k0 + col + v;
                        int dd = kg - qg;
                        int dc = dd < -16 ? -16 : (dd > 16 ? 16 : dd);
                        float rb = __half2float(
                            *(hf*)(sm + ARB + (rr * 33 + dc + 16) * 2));
                        float p = exp2f(fmaf(acc[j][rh * 2 + v], C2A, rb));
                        p01[v] = p;
                        lsum[rh] += p;
                        if (dd >= 16) wsuf[rh] += p;
                        else if (dd > -16) sW[rr * 33 + dd + 16] = p;
                    }
                    ph[j >> 1][(j & 1) * 2 + rh] = pk_h(p01[0], p01[1]);
                }
            }
        }

        // ---- PV phase: P from registers, warp's own 32-k slice, 64 cols ----
#pragma unroll
        for (int kc = 0; kc < 2; kc++) {
            uint32_t vh[8][2];
#pragma unroll
            for (int cg = 0; cg < 4; cg++) {
                uint32_t vo = (uint32_t)((wn * 32 + kc * 16 + lr) * 144)
                              + (cg * 2 + (lane >> 4)) * 16;
                uint32_t r[4];
                LDSM4T(r, sb + vbuf + vo);
                vh[2*cg][0] = r[0]; vh[2*cg][1] = r[1];
                vh[2*cg+1][0] = r[2]; vh[2*cg+1][1] = r[3];
            }
#pragma unroll
            for (int nf = 0; nf < 8; nf++) mma_f16(acc2[nf], ph[kc], vh[nf]);
        }
    }

    // ---- deterministic l / w32 reduction + O-partial staging ----
#pragma unroll
    for (int i = 0; i < 2; i++) {
        lsum[i] += __shfl_xor_sync(0xffffffffu, lsum[i], 1);
        lsum[i] += __shfl_xor_sync(0xffffffffu, lsum[i], 2);
        wsuf[i] += __shfl_xor_sync(0xffffffffu, wsuf[i], 1);
        wsuf[i] += __shfl_xor_sync(0xffffffffu, wsuf[i], 2);
    }
    if ((lane & 3) == 0) {
#pragma unroll
        for (int rh = 0; rh < 2; rh++) {
            int row = wm * 16 + rh * 8 + (lane >> 2);
            sLp[row * 2 + wn] = lsum[rh];
            sWp[row * 2 + wn] = wsuf[rh];
        }
    }
    // wn=1 warps stage their k-half O partial (64 x 66 fp32 in old K region)
    float* sOst = (float*)(sm + AKH);
    if (wn == 1) {
#pragma unroll
        for (int nf = 0; nf < 8; nf++) {
            int row0 = wm * 16 + (lane >> 2);
            int col = nf * 8 + (lane & 3) * 2;
            *(float2*)&sOst[row0 * 66 + col] = make_float2(acc2[nf][0], acc2[nf][1]);
            *(float2*)&sOst[(row0 + 8) * 66 + col] = make_float2(acc2[nf][2], acc2[nf][3]);
        }
    }
    __syncthreads();
    if (tid < 64) {
        int r = tid;
        float l = sLp[r * 2] + sLp[r * 2 + 1];
        float ws = sWp[r * 2] + sWp[r * 2 + 1];
        float mid = 0.f;
#pragma unroll
        for (int d = 1; d < 32; d++) mid += sW[r * 33 + d];
        sW[r * 33 + 0] = l - ws - mid;
        sW[r * 33 + 32] = ws;
        sL[r] = 1.f / l;
    }
    __syncthreads();

    // ---- wn=0 warps: combine halves, rel_v bias, normalize, store ----
    if (wn == 0) {
#pragma unroll
        for (int nf = 0; nf < 8; nf++) {
            int row0 = wm * 16 + (lane >> 2), row1 = row0 + 8;
            int col = nf * 8 + (lane & 3) * 2;
            float2 s0 = *(float2*)&sOst[row0 * 66 + col];
            float2 s1 = *(float2*)&sOst[row1 * 66 + col];
            float o00 = acc2[nf][0] + s0.x, o01 = acc2[nf][1] + s0.y;
            float o10 = acc2[nf][2] + s1.x, o11 = acc2[nf][3] + s1.y;
            float b00 = 0.f, b01 = 0.f, b10 = 0.f, b11 = 0.f;
#pragma unroll
            for (int d = 0; d < 33; d++) {
                float w0v = sW[row0 * 33 + d], w1v = sW[row1 * 33 + d];
                float r0 = sRV[d * 64 + col], r1 = sRV[d * 64 + col + 1];
                b00 += w0v * r0; b01 += w0v * r1;
                b10 += w1v * r0; b11 += w1v * r1;
            }
            float il0 = sL[row0], il1 = sL[row1];
            o00 = (o00 + b00) * il0; o01 = (o01 + b01) * il0;
            o10 = (o10 + b10) * il1; o11 = (o11 + b11) * il1;
            size_t g0 = ((size_t)(blockIdx.z * 1024 + q0 + row0)) * 1024
                        + blockIdx.y * 64 + col;
            size_t g1 = ((size_t)(blockIdx.z * 1024 + q0 + row1)) * 1024
                        + blockIdx.y * 64 + col;
            *(uint32_t*)&Oh[g0] = pk_h(o00, o01);
            *(uint32_t*)&Oh[g1] = pk_h(o10, o11);
        }
    }
}

// =================================================================
extern "C" void kernel_launch(void* const* d_in, const int* in_sizes, int n_in,
                              void* d_out, int out_size)
{
    const float* query = (const float*)d_in[0];
    const float* key   = (const float*)d_in[1];
    const float* value = (const float*)d_in[2];
    const float* Wq    = (const float*)d_in[3];
    const float* bq    = (const float*)d_in[4];
    const float* Wk    = (const float*)d_in[5];
    const float* bk    = (const float*)d_in[6];
    const float* Wv    = (const float*)d_in[7];
    const float* bv    = (const float*)d_in[8];
    const float* relk  = (const float*)d_in[9];
    const float* relv  = (const float*)d_in[10];
    const float* fcW   = (const float*)d_in[11];
    const float* fcb   = (const float*)d_in[12];
    float* out = (float*)d_out;

    hf *Qh, *Kh, *Vh, *Oh, *Wh, *Bh;
    cudaGetSymbolAddress((void**)&Qh, g_Qh);
    cudaGetSymbolAddress((void**)&Kh, g_Kh);
    cudaGetSymbolAddress((void**)&Vh, g_Vh);
    cudaGetSymbolAddress((void**)&Oh, g_Oh);
    cudaGetSymbolAddress((void**)&Wh, g_Wh);
    cudaGetSymbolAddress((void**)&Bh, g_Bh);

    cudaFuncSetAttribute(gemm_proj, cudaFuncAttributeMaxDynamicSharedMemorySize, GH_SMEM);
    cudaFuncSetAttribute(gemm_fc, cudaFuncAttributeMaxDynamicSharedMemorySize, GH_SMEM);
    cudaFuncSetAttribute(attn_hmma, cudaFuncAttributeMaxDynamicSharedMemorySize, ATT_SMEM);

    cvtW4<<<dim3(32, 32, 4), 256>>>(Wq, Wk, Wv, fcW, Wh, Bh);

    gemm_proj<<<dim3(8, 32, 3), 256, GH_SMEM>>>(query, key, value, Wh,
                                                bq, bk, bv, Qh, Kh, Vh);

    attn_hmma<<<dim3(16, NH, NB), 256, ATT_SMEM>>>(Qh, Kh, Vh, relk, relv, Oh);

    gemm_fc<<<dim3(8, 32), 256, GH_SMEM>>>(Oh, Bh, fcb, out);
}